// round 4
// baseline (speedup 1.0000x reference)
#include <cuda_runtime.h>
#include <cstdint>
#include <cstddef>

#define Bsz 4096
#define Tsz 60
#define Dsz 200
#define Hsz 64
#define G4  256
#define BT  (Bsz*Tsz)       // 245760
#define M2  (2*BT)          // 491520
#define FCK (2*Tsz*Hsz)     // 7680
#define KSPLIT 4
#define KCHUNK (FCK/KSPLIT) // 1920

// ---------------- scratch (device globals: allocation-free) ----------------
__device__ float g_XG[(size_t)M2 * G4];                  // layer-0 gate pre-activations
__device__ float g_FEAT[(size_t)Bsz * FCK];              // relu(concat) layout
__device__ float g_FC1P[(size_t)KSPLIT * Bsz * 128];     // split-K partials
__device__ float g_FC1R[(size_t)Bsz * 128];
__device__ float g_PART[240];
__device__ float g_INV[1];

// ---------------- packed f32x2 helpers ----------------
#define PK2(d, s)      asm("mov.b64 %0, {%1, %1};" : "=l"(d) : "f"(s))
#define UNPK2(lo, hi, s) asm("mov.b64 {%0, %1}, %2;" : "=f"(lo), "=f"(hi) : "l"(s))
#define FMA2(acc, a, b) asm("fma.rn.f32x2 %0, %1, %2, %0;" : "+l"(acc) : "l"(a), "l"(b))

// ---------------- activations: single-MUFU tanh ----------------
__device__ __forceinline__ float tanh_fast(float x) {
    float y;
    asm("tanh.approx.f32 %0, %1;" : "=f"(y) : "f"(x));
    return y;
}
__device__ __forceinline__ float sig_fast(float x) {
    return fmaf(tanh_fast(0.5f * x), 0.5f, 0.5f);
}

// ---------------- fp32 GEMM (FFMA2): C[M,N] = A[M,K] * W[N,K]^T (+bias) ----------
// BM=64, 256 threads, acc pairs along M (4x TN u64 accs). A read from smem as
// natural u64 pairs; B stored to smem PRE-DUPLICATED {v,v} so the inner loop
// has no pack movs. Double-buffered, 2 CTAs/SM.
template<int BN, int TN, int NB, bool RELU>
__global__ void __launch_bounds__(256, 2) gemm_nt(
    const float* __restrict__ A, int lda, int Kloop,
    const float* __restrict__ W, int ldw,
    const float* __restrict__ b0, const float* __restrict__ b1,
    float* __restrict__ C, int ldc, size_t csplit)
{
    constexpr int BM = 64, BK = 8, TM = 8;
    constexpr int BL = (BN * BK) / 256;         // 8 (BN=256) or 4 (BN=128)
    __shared__ float As[2][BK][BM];
    __shared__ unsigned long long Bs[2][BK][BN];   // duplicated pairs

    const int tid  = threadIdx.x;
    const int lane = tid & 31;
    const int warp = tid >> 5;
    const int tx   = (warp & 3) * 8 + (lane & 7);   // 0..31
    const int ty   = (warp >> 2) * 4 + (lane >> 3); // 0..7
    const int row0 = blockIdx.x * BM;
    const int col0 = blockIdx.y * BN;
    const int koff = blockIdx.z * Kloop;

    const float* Ab = A + (size_t)row0 * lda + koff;
    const float* Wb = W + (size_t)col0 * ldw + koff;
    float* Cb = C + (size_t)blockIdx.z * csplit;

    const int ar = (2 * tid) >> 3;              // 0..63
    const int ak = (2 * tid) & 7;               // even
    const int bn = tid % BN;
    const int bk0 = (tid / BN) * BL;

    unsigned long long acc2[TM / 2][TN];        // pairs of rows
#pragma unroll
    for (int i = 0; i < TM / 2; i++)
#pragma unroll
        for (int j = 0; j < TN; j++) acc2[i][j] = 0ULL;

    float2 av = *reinterpret_cast<const float2*>(Ab + (size_t)ar * lda + ak);
    float bt[BL];
#pragma unroll
    for (int i = 0; i < BL; i += 4) {
        float4 v = *reinterpret_cast<const float4*>(Wb + (size_t)bn * ldw + bk0 + i);
        bt[i] = v.x; bt[i + 1] = v.y; bt[i + 2] = v.z; bt[i + 3] = v.w;
    }
    As[0][ak][ar] = av.x;
    As[0][ak + 1][ar] = av.y;
#pragma unroll
    for (int i = 0; i < BL; i++) {
        unsigned long long p; PK2(p, bt[i]);
        Bs[0][bk0 + i][bn] = p;
    }
    __syncthreads();

    int buf = 0;
    for (int k0 = 0;; k0 += BK) {
        const bool more = (k0 + BK) < Kloop;
        if (more) {
            av = *reinterpret_cast<const float2*>(Ab + (size_t)ar * lda + k0 + BK + ak);
#pragma unroll
            for (int i = 0; i < BL; i += 4) {
                float4 v = *reinterpret_cast<const float4*>(
                    Wb + (size_t)bn * ldw + k0 + BK + bk0 + i);
                bt[i] = v.x; bt[i + 1] = v.y; bt[i + 2] = v.z; bt[i + 3] = v.w;
            }
        }

#pragma unroll
        for (int kk = 0; kk < BK; kk++) {
            ulonglong2 aA = *reinterpret_cast<const ulonglong2*>(&As[buf][kk][ty * TM]);
            ulonglong2 aB = *reinterpret_cast<const ulonglong2*>(&As[buf][kk][ty * TM + 4]);
            unsigned long long a2[4];
            a2[0] = aA.x; a2[1] = aA.y; a2[2] = aB.x; a2[3] = aB.y;
            unsigned long long b2[TN];
#pragma unroll
            for (int j = 0; j < TN; j += 2) {
                ulonglong2 bb = *reinterpret_cast<const ulonglong2*>(
                    &Bs[buf][kk][tx * TN + j]);
                b2[j] = bb.x; b2[j + 1] = bb.y;
            }
#pragma unroll
            for (int i = 0; i < TM / 2; i++)
#pragma unroll
                for (int j = 0; j < TN; j++)
                    FMA2(acc2[i][j], a2[i], b2[j]);
        }

        if (!more) break;
        As[buf ^ 1][ak][ar] = av.x;
        As[buf ^ 1][ak + 1][ar] = av.y;
#pragma unroll
        for (int i = 0; i < BL; i++) {
            unsigned long long p; PK2(p, bt[i]);
            Bs[buf ^ 1][bk0 + i][bn] = p;
        }
        __syncthreads();
        buf ^= 1;
    }

    float bv[TN];
#pragma unroll
    for (int j = 0; j < TN; j++) {
        bv[j] = 0.f;
        if (NB >= 1) bv[j] += b0[col0 + tx * TN + j];
        if (NB >= 2) bv[j] += b1[col0 + tx * TN + j];
    }
#pragma unroll
    for (int i = 0; i < TM / 2; i++) {
        float lo[TN], hi[TN];
#pragma unroll
        for (int j = 0; j < TN; j++) UNPK2(lo[j], hi[j], acc2[i][j]);
        float* Cr0 = Cb + (size_t)(row0 + ty * TM + 2 * i)     * ldc + col0 + tx * TN;
        float* Cr1 = Cb + (size_t)(row0 + ty * TM + 2 * i + 1) * ldc + col0 + tx * TN;
#pragma unroll
        for (int j = 0; j < TN; j += 4) {
            float4 v0, v1;
            v0.x = lo[j] + bv[j];     v0.y = lo[j+1] + bv[j+1];
            v0.z = lo[j+2] + bv[j+2]; v0.w = lo[j+3] + bv[j+3];
            v1.x = hi[j] + bv[j];     v1.y = hi[j+1] + bv[j+1];
            v1.z = hi[j+2] + bv[j+2]; v1.w = hi[j+3] + bv[j+3];
            if (RELU) {
                v0.x = fmaxf(v0.x, 0.f); v0.y = fmaxf(v0.y, 0.f);
                v0.z = fmaxf(v0.z, 0.f); v0.w = fmaxf(v0.w, 0.f);
                v1.x = fmaxf(v1.x, 0.f); v1.y = fmaxf(v1.y, 0.f);
                v1.z = fmaxf(v1.z, 0.f); v1.w = fmaxf(v1.w, 0.f);
            }
            *reinterpret_cast<float4*>(Cr0 + j) = v0;
            *reinterpret_cast<float4*>(Cr1 + j) = v1;
        }
    }
}

// ---------------- fused 2-layer LSTM recurrence (768 thr, 3 groups) ----------
// 4 batch rows/CTA. Group 0 (thr 0-255): layer-0 gates, Whh0[g][:] in 64 regs,
// also owns xg prefetch + layer-0 activations (c0). Group 1: layer-1 h0-part
// (Wih1) + layer-1 activations (c1) + FEAT store. Group 2: layer-1 h1-part
// (Whh1). One-step skew; dot products in packed f32x2.
__global__ void __launch_bounds__(768, 1) lstm_fused(
    const float* __restrict__ XG,     // [8192*T, 256] layer-0 preacts (biases folded)
    const float* __restrict__ Whh0,   // [256, 64]
    const float* __restrict__ Wih1,   // [256, 64]
    const float* __restrict__ Whh1,   // [256, 64]
    const float* __restrict__ bih1, const float* __restrict__ bhh1,
    float* __restrict__ FEAT)
{
    __shared__ float sh_h0[4][64];
    __shared__ float sh_h1[4][64];
    __shared__ float sg0[4][G4];
    __shared__ float sg1a[4][G4];
    __shared__ float sg1b[4][G4];

    const int tid = threadIdx.x;
    const int grp = tid >> 8;              // 0,1,2
    const int g   = tid & 255;

    const float* Wsel = (grp == 0) ? Whh0 : (grp == 1) ? Wih1 : Whh1;
    unsigned long long w2[32];             // 64 weights as 32 u64 pairs
    {
        const ulonglong2* wp = reinterpret_cast<const ulonglong2*>(Wsel + (size_t)g * Hsz);
#pragma unroll
        for (int i = 0; i < 16; i++) {
            ulonglong2 v = wp[i];
            w2[2 * i] = v.x; w2[2 * i + 1] = v.y;
        }
    }
    const float bgate = (grp == 1) ? (bih1[g] + bhh1[g]) : 0.f;

    const int row0 = blockIdx.x * 4;
    const float* xgb = XG + (size_t)row0 * Tsz * G4 + g;

    const int ar = g >> 6;                 // 0..3
    const int aj = g & 63;
    float c = 0.f;

    if (grp == 0) reinterpret_cast<float*>(sh_h0)[g] = 0.f;
    else if (grp == 1) reinterpret_cast<float*>(sh_h1)[g] = 0.f;
    __syncthreads();

    float xc[4];
    if (grp == 0) {
#pragma unroll
        for (int rr = 0; rr < 4; rr++) xc[rr] = xgb[(size_t)rr * Tsz * G4];
    }

    for (int m = 0; m <= Tsz; m++) {
        // ---- phase A: gate dot products ----
        if (grp == 0) {
            if (m < Tsz) {
#pragma unroll
                for (int rr = 0; rr < 4; rr++) {
                    unsigned long long acc = 0ULL;
                    const ulonglong2* hp = reinterpret_cast<const ulonglong2*>(sh_h0[rr]);
#pragma unroll
                    for (int k = 0; k < 16; k++) {
                        ulonglong2 h = hp[k];
                        FMA2(acc, h.x, w2[2 * k]);
                        FMA2(acc, h.y, w2[2 * k + 1]);
                    }
                    float lo, hi; UNPK2(lo, hi, acc);
                    sg0[rr][g] = lo + hi + xc[rr];
                }
                if (m + 1 < Tsz) {   // prefetch next step's xg (consumed next iter)
#pragma unroll
                    for (int rr = 0; rr < 4; rr++)
                        xc[rr] = xgb[(size_t)rr * Tsz * G4 + (size_t)(m + 1) * G4];
                }
            }
        } else if (grp == 1) {
            if (m >= 1) {
#pragma unroll
                for (int rr = 0; rr < 4; rr++) {
                    unsigned long long acc = 0ULL;
                    const ulonglong2* hp = reinterpret_cast<const ulonglong2*>(sh_h0[rr]);
#pragma unroll
                    for (int k = 0; k < 16; k++) {
                        ulonglong2 h = hp[k];
                        FMA2(acc, h.x, w2[2 * k]);
                        FMA2(acc, h.y, w2[2 * k + 1]);
                    }
                    float lo, hi; UNPK2(lo, hi, acc);
                    sg1a[rr][g] = lo + hi + bgate;
                }
            }
        } else {
            if (m >= 1) {
#pragma unroll
                for (int rr = 0; rr < 4; rr++) {
                    unsigned long long acc = 0ULL;
                    const ulonglong2* hp = reinterpret_cast<const ulonglong2*>(sh_h1[rr]);
#pragma unroll
                    for (int k = 0; k < 16; k++) {
                        ulonglong2 h = hp[k];
                        FMA2(acc, h.x, w2[2 * k]);
                        FMA2(acc, h.y, w2[2 * k + 1]);
                    }
                    float lo, hi; UNPK2(lo, hi, acc);
                    sg1b[rr][g] = lo + hi;
                }
            }
        }
        __syncthreads();

        // ---- phase B: activations ----
        if (grp == 0) {
            if (m < Tsz) {
                float iv = sg0[ar][aj],       fv = sg0[ar][aj + 64];
                float gv = sg0[ar][aj + 128], ov = sg0[ar][aj + 192];
                c = sig_fast(fv) * c + sig_fast(iv) * tanh_fast(gv);
                sh_h0[ar][aj] = sig_fast(ov) * tanh_fast(c);
            }
        } else if (grp == 1) {
            if (m >= 1) {
                float iv = sg1a[ar][aj]       + sg1b[ar][aj];
                float fv = sg1a[ar][aj + 64]  + sg1b[ar][aj + 64];
                float gv = sg1a[ar][aj + 128] + sg1b[ar][aj + 128];
                float ov = sg1a[ar][aj + 192] + sg1b[ar][aj + 192];
                c = sig_fast(fv) * c + sig_fast(iv) * tanh_fast(gv);
                float h = sig_fast(ov) * tanh_fast(c);
                sh_h1[ar][aj] = h;
                int row = row0 + ar;
                int inp = row >> 12, b = row & (Bsz - 1);
                FEAT[(size_t)b * FCK + (size_t)inp * (Tsz * Hsz)
                     + (size_t)(m - 1) * Hsz + aj] = fmaxf(h, 0.f);
            }
        }
        __syncthreads();
    }
}

// ---------------- FC1 split-K reduction (+bias, +relu) ----------------
__global__ void __launch_bounds__(256) fc1_reduce(
    const float* __restrict__ part, const float* __restrict__ bias,
    float* __restrict__ outp)
{
    const size_t S = (size_t)Bsz * 128;
    size_t i = (size_t)blockIdx.x * 256 + threadIdx.x;
    int n = (int)(i & 127);
    float s = bias[n] + part[i] + part[i + S] + part[i + 2 * S] + part[i + 3 * S];
    outp[i] = fmaxf(s, 0.f);
}

// ---------------- FC2 + partial sum-of-squares ----------------
__global__ void __launch_bounds__(256) fc2_norm(
    const float* __restrict__ fc1, const float* __restrict__ w,
    const float* __restrict__ bias, float* __restrict__ out,
    float* __restrict__ partial)
{
    __shared__ float sw[15 * 132];
    __shared__ float red[256];
    const int tid = threadIdx.x;
    for (int i = tid; i < 15 * 128; i += 256) {
        int n = i >> 7, k = i & 127;
        sw[n * 132 + k] = w[i];
    }
    __syncthreads();

    int idx = blockIdx.x * 256 + tid;
    int b = idx / 15, n = idx - b * 15;
    const float4* fr = reinterpret_cast<const float4*>(fc1 + (size_t)b * 128);
    const float4* wn = reinterpret_cast<const float4*>(sw + n * 132);
    float acc = bias[n];
#pragma unroll
    for (int k = 0; k < 32; k++) {
        float4 f4 = fr[k];
        float4 w4 = wn[k];
        acc = fmaf(f4.x, w4.x, acc);
        acc = fmaf(f4.y, w4.y, acc);
        acc = fmaf(f4.z, w4.z, acc);
        acc = fmaf(f4.w, w4.w, acc);
    }
    out[idx] = acc;
    red[tid] = acc * acc;
    __syncthreads();
#pragma unroll
    for (int s = 128; s > 0; s >>= 1) {
        if (tid < s) red[tid] += red[tid + s];
        __syncthreads();
    }
    if (tid == 0) partial[blockIdx.x] = red[0];
}

__global__ void reduce_norm(const float* __restrict__ partial, float* __restrict__ inv)
{
    __shared__ float red[256];
    float s = 0.f;
    for (int i = threadIdx.x; i < 240; i += 256) s += partial[i];
    red[threadIdx.x] = s;
    __syncthreads();
#pragma unroll
    for (int st = 128; st > 0; st >>= 1) {
        if (threadIdx.x < st) red[threadIdx.x] += red[threadIdx.x + st];
        __syncthreads();
    }
    if (threadIdx.x == 0) inv[0] = 1.0f / sqrtf(red[0]);
}

__global__ void scale_out(float* __restrict__ out, const float* __restrict__ inv)
{
    int i = blockIdx.x * 256 + threadIdx.x;
    out[i] *= inv[0];
}

// ---------------- launch ----------------
extern "C" void kernel_launch(void* const* d_in, const int* in_sizes, int n_in,
                              void* d_out, int out_size)
{
    const float* x1      = (const float*)d_in[0];
    const float* x2      = (const float*)d_in[1];
    const float* W_ih_l0 = (const float*)d_in[2];
    const float* W_hh_l0 = (const float*)d_in[3];
    const float* b_ih_l0 = (const float*)d_in[4];
    const float* b_hh_l0 = (const float*)d_in[5];
    const float* W_ih_l1 = (const float*)d_in[6];
    const float* W_hh_l1 = (const float*)d_in[7];
    const float* b_ih_l1 = (const float*)d_in[8];
    const float* b_hh_l1 = (const float*)d_in[9];
    const float* fc1_w   = (const float*)d_in[10];
    const float* fc1_b   = (const float*)d_in[11];
    const float* fc2_w   = (const float*)d_in[12];
    const float* fc2_b   = (const float*)d_in[13];
    float* out = (float*)d_out;

    float *XG, *FEAT, *FC1P, *FC1R, *PART, *INV;
    cudaGetSymbolAddress((void**)&XG,   g_XG);
    cudaGetSymbolAddress((void**)&FEAT, g_FEAT);
    cudaGetSymbolAddress((void**)&FC1P, g_FC1P);
    cudaGetSymbolAddress((void**)&FC1R, g_FC1R);
    cudaGetSymbolAddress((void**)&PART, g_PART);
    cudaGetSymbolAddress((void**)&INV,  g_INV);

    // layer-0 input projection (both sequences), biases folded in
    gemm_nt<256, 8, 2, false><<<dim3(BT / 64, 1, 1), 256>>>(
        x1, Dsz, Dsz, W_ih_l0, Dsz, b_ih_l0, b_hh_l0, XG, G4, 0);
    gemm_nt<256, 8, 2, false><<<dim3(BT / 64, 1, 1), 256>>>(
        x2, Dsz, Dsz, W_ih_l0, Dsz, b_ih_l0, b_hh_l0, XG + (size_t)BT * G4, G4, 0);

    // fused 2-layer recurrence -> relu(FEAT) in concat layout
    lstm_fused<<<2048, 768>>>(XG, W_hh_l0, W_ih_l1, W_hh_l1, b_ih_l1, b_hh_l1, FEAT);

    // FC1: split-K x4, deterministic partial buffers, then reduce+bias+relu
    gemm_nt<128, 4, 0, false><<<dim3(Bsz / 64, 1, KSPLIT), 256>>>(
        FEAT, FCK, KCHUNK, fc1_w, FCK, nullptr, nullptr,
        FC1P, 128, (size_t)Bsz * 128);
    fc1_reduce<<<(Bsz * 128) / 256, 256>>>(FC1P, fc1_b, FC1R);

    // FC2 + deterministic norm + scale
    fc2_norm<<<240, 256>>>(FC1R, fc2_w, fc2_b, out, PART);
    reduce_norm<<<1, 256>>>(PART, INV);
    scale_out<<<240, 256>>>(out, INV);
}

// round 6
// speedup vs baseline: 2.9457x; 2.9457x over previous
#include <cuda_runtime.h>
#include <cuda_bf16.h>
#include <cstdint>
#include <cstddef>

#define Bsz 4096
#define Tsz 60
#define Dsz 200
#define K0P 208             // Dsz padded to multiple of 16
#define Hsz 64
#define G4  256
#define BT  (Bsz*Tsz)       // 245760
#define M2  (2*BT)          // 491520
#define FCK (2*Tsz*Hsz)     // 7680
#define FSPLIT 8
#define FSTEPS (FCK/FSPLIT/16)  // 60 k-steps per split

// ---------------- scratch (device globals: allocation-free) ----------------
__device__ float g_XG[(size_t)M2 * G4];
__device__ float g_H1[(size_t)M2 * Hsz];
__device__ float g_FEAT[(size_t)Bsz * FCK];
__device__ float g_FC1P[(size_t)FSPLIT * Bsz * 128];
__device__ float g_FC1R[(size_t)Bsz * 128];
__device__ float g_PART[240];
__device__ float g_INV[1];
__device__ __nv_bfloat16 g_W0hi[256 * K0P];
__device__ __nv_bfloat16 g_W0lo[256 * K0P];
__device__ __nv_bfloat16 g_W1hi[256 * 64];
__device__ __nv_bfloat16 g_W1lo[256 * 64];
__device__ __nv_bfloat16 g_FWhi[(size_t)128 * FCK];
__device__ __nv_bfloat16 g_FWlo[(size_t)128 * FCK];
__device__ float g_B0[256];
__device__ float g_B1[256];

// ---------------- activations ----------------
__device__ __forceinline__ float tanh_fast(float x) {
    float y;
    asm("tanh.approx.f32 %0, %1;" : "=f"(y) : "f"(x));
    return y;
}
__device__ __forceinline__ float sig_fast(float x) {
    return fmaf(tanh_fast(0.5f * x), 0.5f, 0.5f);
}

// ---------------- mma/ldmatrix helpers (baseline PTX, no sm_103a features) --
__device__ __forceinline__ uint32_t smem_u32(const void* p) {
    uint32_t a;
    asm("{ .reg .u64 t; cvta.to.shared.u64 t, %1; cvt.u32.u64 %0, t; }" : "=r"(a) : "l"(p));
    return a;
}
#define LDSM_X4(r, addr) \
    asm volatile("ldmatrix.sync.aligned.m8n8.x4.shared.b16 {%0,%1,%2,%3}, [%4];" \
        : "=r"((r)[0]), "=r"((r)[1]), "=r"((r)[2]), "=r"((r)[3]) : "r"(addr))
#define LDSM_X2(r, addr) \
    asm volatile("ldmatrix.sync.aligned.m8n8.x2.shared.b16 {%0,%1}, [%2];" \
        : "=r"((r)[0]), "=r"((r)[1]) : "r"(addr))

__device__ __forceinline__ void mma_bf16(float* c, const uint32_t* a, const uint32_t* b) {
    asm volatile(
        "mma.sync.aligned.m16n8k16.row.col.f32.bf16.bf16.f32 "
        "{%0,%1,%2,%3}, {%4,%5,%6,%7}, {%8,%9}, {%0,%1,%2,%3};"
        : "+f"(c[0]), "+f"(c[1]), "+f"(c[2]), "+f"(c[3])
        : "r"(a[0]), "r"(a[1]), "r"(a[2]), "r"(a[3]), "r"(b[0]), "r"(b[1]));
}

__device__ __forceinline__ uint32_t pack_hi(float v0, float v1, float& l0, float& l1) {
    __nv_bfloat16 h0 = __float2bfloat16(v0);
    __nv_bfloat16 h1 = __float2bfloat16(v1);
    l0 = v0 - __bfloat162float(h0);
    l1 = v1 - __bfloat162float(h1);
    return (uint32_t)__bfloat16_as_ushort(h0) | ((uint32_t)__bfloat16_as_ushort(h1) << 16);
}
__device__ __forceinline__ uint32_t pack_lo(float l0, float l1) {
    return (uint32_t)__bfloat16_as_ushort(__float2bfloat16(l0))
         | ((uint32_t)__bfloat16_as_ushort(__float2bfloat16(l1)) << 16);
}

// ---------------- W pre-conversion (fp32 -> bf16 hi/lo, zero-padded) --------
__global__ void convert_w(const float* __restrict__ W, int K, int ldwp, int total,
                          __nv_bfloat16* __restrict__ hi, __nv_bfloat16* __restrict__ lo)
{
    int idx = blockIdx.x * 256 + threadIdx.x;
    if (idx >= total) return;
    int n = idx / ldwp, k = idx - n * ldwp;
    float v = (k < K) ? W[n * K + k] : 0.f;
    __nv_bfloat16 h = __float2bfloat16(v);
    hi[idx] = h;
    lo[idx] = __float2bfloat16(v - __bfloat162float(h));
}
__global__ void combine_bias(const float* a, const float* b, float* o) {
    int i = threadIdx.x;
    o[i] = a[i] + b[i];
}

// ---------------- tensor-core GEMM (mma.sync bf16 hi/lo) --------------------
// C[M,N-slice] = A[M,K] * W[N,K]^T (+bias). CTA tile 128x128, 8 warps (2x4),
// warp tile 64x32 (4x4 m16n8k16). Smem rows padded to 48B (conflict-free
// ldmatrix). Double-buffered, 1 sync/iter. blockIdx.z = K-split.
// Smem layout (bytes): A hi: buf*12288; A lo: +6144; W: +24576 same structure.
__global__ void __launch_bounds__(256) gemm_mma(
    const float* __restrict__ A0, const float* __restrict__ A1, int rowsplit,
    int lda, int nch,
    const __nv_bfloat16* __restrict__ Whi, const __nv_bfloat16* __restrict__ Wlo,
    int ldw, const float* __restrict__ bias,
    float* __restrict__ C, int ldc, size_t csplit)
{
    __shared__ __align__(16) uint32_t sm[12288];   // 48 KB
    const uint32_t sb = smem_u32(sm);

    const int tid  = threadIdx.x;
    const int lane = tid & 31;
    const int wid  = tid >> 5;
    const int warpM = wid >> 2;          // 0..1
    const int warpN = wid & 3;           // 0..3
    const int row0 = blockIdx.x * 128;
    const int col0 = blockIdx.y * 128;

    const float* Ab = (row0 < rowsplit)
        ? A0 + (size_t)row0 * lda
        : A1 + (size_t)(row0 - rowsplit) * lda;

    // staging coords: idx = tid + 256*i -> r = idx>>3 (4 strides of 32), cp = tid&7
    const int sr = tid >> 3;             // 0..31
    const int scp = tid & 7;             // 0..7 (k-pair)

    // lane offsets for ldmatrix
    const uint32_t laneA = (uint32_t)((((lane >> 3) & 1) * 8 + (lane & 7)) * 48
                                      + ((lane >> 4) * 8) * 2);
    const uint32_t laneB = (uint32_t)((lane & 7) * 48 + (((lane >> 3) & 1) * 8) * 2);
    const uint32_t aBase = sb + (uint32_t)(warpM * 64) * 48 + laneA;
    const uint32_t bBase = sb + 24576u + (uint32_t)(warpN * 32) * 48 + laneB;

    float acc[4][4][4];
#pragma unroll
    for (int mt = 0; mt < 4; mt++)
#pragma unroll
        for (int nt = 0; nt < 4; nt++)
#pragma unroll
            for (int e = 0; e < 4; e++) acc[mt][nt][e] = 0.f;

    // ---- register-staged loads for one k-step ----
    float2 av[4];
    uint32_t wh[4], wl[4];
    auto ldg_step = [&](int k0) {
#pragma unroll
        for (int i = 0; i < 4; i++) {
            int r = sr + 32 * i;
            int k = k0 + 2 * scp;
            if (k + 2 <= lda)
                av[i] = *reinterpret_cast<const float2*>(Ab + (size_t)r * lda + k);
            else
                av[i] = make_float2(0.f, 0.f);
            size_t go = (size_t)r * ldw + k0 + 2 * scp;
            wh[i] = *reinterpret_cast<const uint32_t*>(Whi + (col0 + r) * (size_t)ldw
                                                        + k0 + 2 * scp - go + go);
            wh[i] = *reinterpret_cast<const uint32_t*>(Whi + (size_t)(col0 + r) * ldw + k0 + 2 * scp);
            wl[i] = *reinterpret_cast<const uint32_t*>(Wlo + (size_t)(col0 + r) * ldw + k0 + 2 * scp);
        }
    };
    auto sts_step = [&](int buf) {
        char* base = reinterpret_cast<char*>(sm) + buf * 12288;
#pragma unroll
        for (int i = 0; i < 4; i++) {
            int r = sr + 32 * i;
            float l0, l1;
            uint32_t hp = pack_hi(av[i].x, av[i].y, l0, l1);
            uint32_t lp = pack_lo(l0, l1);
            *reinterpret_cast<uint32_t*>(base + r * 48 + scp * 4) = hp;
            *reinterpret_cast<uint32_t*>(base + 6144 + r * 48 + scp * 4) = lp;
            *reinterpret_cast<uint32_t*>(base + 24576 + r * 48 + scp * 4) = wh[i];
            *reinterpret_cast<uint32_t*>(base + 24576 + 6144 + r * 48 + scp * 4) = wl[i];
        }
    };

    ldg_step(blockIdx.z * nch * 16);
    sts_step(0);
    __syncthreads();

    int buf = 0;
    for (int s = 0;; s++) {
        const bool more = (s + 1) < nch;
        if (more) ldg_step((blockIdx.z * nch + s + 1) * 16);

        // ---- compute from buf ----
        uint32_t ah[4][4], al[4][4], bh[4][2], bl[4][2];
        uint32_t aOff = aBase + buf * 12288u;
        uint32_t bOff = bBase + buf * 12288u;
#pragma unroll
        for (int mt = 0; mt < 4; mt++) {
            LDSM_X4(ah[mt], aOff + mt * 768u);
            LDSM_X4(al[mt], aOff + mt * 768u + 6144u);
        }
#pragma unroll
        for (int nt = 0; nt < 4; nt++) {
            LDSM_X2(bh[nt], bOff + nt * 384u);
            LDSM_X2(bl[nt], bOff + nt * 384u + 6144u);
        }
#pragma unroll
        for (int mt = 0; mt < 4; mt++)
#pragma unroll
            for (int nt = 0; nt < 4; nt++) {
                mma_bf16(acc[mt][nt], ah[mt], bh[nt]);
                mma_bf16(acc[mt][nt], ah[mt], bl[nt]);
                mma_bf16(acc[mt][nt], al[mt], bh[nt]);
            }

        if (!more) break;
        sts_step(buf ^ 1);
        __syncthreads();
        buf ^= 1;
    }

    // ---- epilogue: direct STG (+bias) ----
    float* Cb = C + (size_t)blockIdx.z * csplit;
    const int gid = lane >> 2;           // 0..7
    const int tig = lane & 3;            // 0..3
#pragma unroll
    for (int mt = 0; mt < 4; mt++) {
        int r = row0 + warpM * 64 + mt * 16 + gid;
#pragma unroll
        for (int nt = 0; nt < 4; nt++) {
            int cc = col0 + warpN * 32 + nt * 8 + 2 * tig;
            float b0 = bias ? bias[cc] : 0.f;
            float b1 = bias ? bias[cc + 1] : 0.f;
            float2 v0 = make_float2(acc[mt][nt][0] + b0, acc[mt][nt][1] + b1);
            float2 v1 = make_float2(acc[mt][nt][2] + b0, acc[mt][nt][3] + b1);
            *reinterpret_cast<float2*>(Cb + (size_t)r * ldc + cc) = v0;
            *reinterpret_cast<float2*>(Cb + (size_t)(r + 8) * ldc + cc) = v1;
        }
    }
}

// ---------------- LSTM recurrence (R2 known-good, 2 CTAs/SM) ----------------
__global__ void __launch_bounds__(256, 2) lstm_rec(
    const float* __restrict__ XG,   // [rows*T, 256]
    const float* __restrict__ Whh,  // [256, 64]
    float* __restrict__ out, int mode)
{
    __shared__ float4 sh_h4[4][16];
    __shared__ float  sgate[4][G4];
    float* sh_h = reinterpret_cast<float*>(sh_h4);

    const int tid = threadIdx.x;
    const int g   = tid;

    float w[64];
    {
        const float4* wp = reinterpret_cast<const float4*>(Whh + (size_t)g * Hsz);
#pragma unroll
        for (int i = 0; i < 16; i++) {
            float4 v = wp[i];
            w[4 * i] = v.x; w[4 * i + 1] = v.y; w[4 * i + 2] = v.z; w[4 * i + 3] = v.w;
        }
    }

    const int row0 = blockIdx.x * 4;
    const float* xgb = XG + (size_t)row0 * Tsz * G4 + g;

    const int ar = tid >> 6;
    const int aj = tid & 63;
    float c = 0.f;

    sh_h[tid] = 0.f;
    __syncthreads();

    float xc[4];
#pragma unroll
    for (int rr = 0; rr < 4; rr++)
        xc[rr] = xgb[(size_t)rr * Tsz * G4];

    for (int t = 0; t < Tsz; t++) {
        float xn[4];
        const bool more = (t + 1 < Tsz);
        if (more) {
#pragma unroll
            for (int rr = 0; rr < 4; rr++)
                xn[rr] = xgb[(size_t)rr * Tsz * G4 + (size_t)(t + 1) * G4];
        }

#pragma unroll
        for (int rr = 0; rr < 4; rr++) {
            float a = xc[rr];
            const float4* hp = sh_h4[rr];
#pragma unroll
            for (int k = 0; k < 16; k++) {
                float4 hv = hp[k];
                a = fmaf(hv.x, w[4 * k + 0], a);
                a = fmaf(hv.y, w[4 * k + 1], a);
                a = fmaf(hv.z, w[4 * k + 2], a);
                a = fmaf(hv.w, w[4 * k + 3], a);
            }
            sgate[rr][g] = a;
        }
        __syncthreads();

        {
            float iv = sgate[ar][aj],       fv = sgate[ar][aj + 64];
            float gv = sgate[ar][aj + 128], ov = sgate[ar][aj + 192];
            c = sig_fast(fv) * c + sig_fast(iv) * tanh_fast(gv);
            float h = sig_fast(ov) * tanh_fast(c);
            sh_h[ar * 64 + aj] = h;
            int row = row0 + ar;
            if (mode == 0) {
                out[((size_t)row * Tsz + t) * Hsz + aj] = h;
            } else {
                int inp = row >> 12, b = row & (Bsz - 1);
                out[(size_t)b * FCK + (size_t)inp * (Tsz * Hsz)
                    + (size_t)t * Hsz + aj] = fmaxf(h, 0.f);
            }
        }
        __syncthreads();

#pragma unroll
        for (int rr = 0; rr < 4; rr++) xc[rr] = xn[rr];
    }
}

// ---------------- FC1 split-K reduction (+bias, +relu) ----------------
__global__ void __launch_bounds__(256) fc1_reduce(
    const float* __restrict__ part, const float* __restrict__ bias,
    float* __restrict__ outp)
{
    const size_t S = (size_t)Bsz * 128;
    size_t i = (size_t)blockIdx.x * 256 + threadIdx.x;
    int n = (int)(i & 127);
    float s = bias[n];
#pragma unroll
    for (int z = 0; z < FSPLIT; z++) s += part[i + z * S];
    outp[i] = fmaxf(s, 0.f);
}

// ---------------- FC2 + partial sum-of-squares ----------------
__global__ void __launch_bounds__(256) fc2_norm(
    const float* __restrict__ fc1, const float* __restrict__ w,
    const float* __restrict__ bias, float* __restrict__ out,
    float* __restrict__ partial)
{
    __shared__ float sw[15 * 132];
    __shared__ float red[256];
    const int tid = threadIdx.x;
    for (int i = tid; i < 15 * 128; i += 256) {
        int n = i >> 7, k = i & 127;
        sw[n * 132 + k] = w[i];
    }
    __syncthreads();

    int idx = blockIdx.x * 256 + tid;
    int b = idx / 15, n = idx - b * 15;
    const float4* fr = reinterpret_cast<const float4*>(fc1 + (size_t)b * 128);
    const float4* wn = reinterpret_cast<const float4*>(sw + n * 132);
    float acc = bias[n];
#pragma unroll
    for (int k = 0; k < 32; k++) {
        float4 f4 = fr[k];
        float4 w4 = wn[k];
        acc = fmaf(f4.x, w4.x, acc);
        acc = fmaf(f4.y, w4.y, acc);
        acc = fmaf(f4.z, w4.z, acc);
        acc = fmaf(f4.w, w4.w, acc);
    }
    out[idx] = acc;
    red[tid] = acc * acc;
    __syncthreads();
#pragma unroll
    for (int s = 128; s > 0; s >>= 1) {
        if (tid < s) red[tid] += red[tid + s];
        __syncthreads();
    }
    if (tid == 0) partial[blockIdx.x] = red[0];
}

__global__ void reduce_norm(const float* __restrict__ partial, float* __restrict__ inv)
{
    __shared__ float red[256];
    float s = 0.f;
    for (int i = threadIdx.x; i < 240; i += 256) s += partial[i];
    red[threadIdx.x] = s;
    __syncthreads();
#pragma unroll
    for (int st = 128; st > 0; st >>= 1) {
        if (threadIdx.x < st) red[threadIdx.x] += red[threadIdx.x + st];
        __syncthreads();
    }
    if (threadIdx.x == 0) inv[0] = 1.0f / sqrtf(red[0]);
}

__global__ void scale_out(float* __restrict__ out, const float* __restrict__ inv)
{
    int i = blockIdx.x * 256 + threadIdx.x;
    out[i] *= inv[0];
}

// ---------------- launch ----------------
extern "C" void kernel_launch(void* const* d_in, const int* in_sizes, int n_in,
                              void* d_out, int out_size)
{
    const float* x1      = (const float*)d_in[0];
    const float* x2      = (const float*)d_in[1];
    const float* W_ih_l0 = (const float*)d_in[2];
    const float* W_hh_l0 = (const float*)d_in[3];
    const float* b_ih_l0 = (const float*)d_in[4];
    const float* b_hh_l0 = (const float*)d_in[5];
    const float* W_ih_l1 = (const float*)d_in[6];
    const float* W_hh_l1 = (const float*)d_in[7];
    const float* b_ih_l1 = (const float*)d_in[8];
    const float* b_hh_l1 = (const float*)d_in[9];
    const float* fc1_w   = (const float*)d_in[10];
    const float* fc1_b   = (const float*)d_in[11];
    const float* fc2_w   = (const float*)d_in[12];
    const float* fc2_b   = (const float*)d_in[13];
    float* out = (float*)d_out;

    float *XG, *H1, *FEAT, *FC1P, *FC1R, *PART, *INV, *B0, *B1;
    __nv_bfloat16 *W0hi, *W0lo, *W1hi, *W1lo, *FWhi, *FWlo;
    cudaGetSymbolAddress((void**)&XG,   g_XG);
    cudaGetSymbolAddress((void**)&H1,   g_H1);
    cudaGetSymbolAddress((void**)&FEAT, g_FEAT);
    cudaGetSymbolAddress((void**)&FC1P, g_FC1P);
    cudaGetSymbolAddress((void**)&FC1R, g_FC1R);
    cudaGetSymbolAddress((void**)&PART, g_PART);
    cudaGetSymbolAddress((void**)&INV,  g_INV);
    cudaGetSymbolAddress((void**)&B0,   g_B0);
    cudaGetSymbolAddress((void**)&B1,   g_B1);
    cudaGetSymbolAddress((void**)&W0hi, g_W0hi);
    cudaGetSymbolAddress((void**)&W0lo, g_W0lo);
    cudaGetSymbolAddress((void**)&W1hi, g_W1hi);
    cudaGetSymbolAddress((void**)&W1lo, g_W1lo);
    cudaGetSymbolAddress((void**)&FWhi, g_FWhi);
    cudaGetSymbolAddress((void**)&FWlo, g_FWlo);

    // weight conversions + bias combines (deterministic, every call)
    convert_w<<<(256 * K0P + 255) / 256, 256>>>(W_ih_l0, Dsz, K0P, 256 * K0P, W0hi, W0lo);
    convert_w<<<(256 * 64 + 255) / 256, 256>>>(W_ih_l1, Hsz, 64, 256 * 64, W1hi, W1lo);
    convert_w<<<(128 * FCK + 255) / 256, 256>>>(fc1_w, FCK, FCK, 128 * FCK, FWhi, FWlo);
    combine_bias<<<1, 256>>>(b_ih_l0, b_hh_l0, B0);
    combine_bias<<<1, 256>>>(b_ih_l1, b_hh_l1, B1);

    // layer-0 input projection: XG = [x1;x2] @ W_ih0^T + B0   (K=200 pad 208)
    gemm_mma<<<dim3(M2 / 128, 2, 1), 256>>>(
        x1, x2, BT, Dsz, K0P / 16, W0hi, W0lo, K0P, B0, XG, 256, 0);

    // layer-0 recurrence -> H1
    lstm_rec<<<2048, 256>>>(XG, W_hh_l0, H1, 0);

    // layer-1 input projection: XG = H1 @ W_ih1^T + B1   (K=64)
    gemm_mma<<<dim3(M2 / 128, 2, 1), 256>>>(
        H1, H1, 1 << 30, Hsz, 4, W1hi, W1lo, 64, B1, XG, 256, 0);

    // layer-1 recurrence -> relu(FEAT)
    lstm_rec<<<2048, 256>>>(XG, W_hh_l1, FEAT, 1);

    // FC1: split-K x8 (chunks of 960), then reduce(+bias,+relu)
    gemm_mma<<<dim3(Bsz / 128, 1, FSPLIT), 256>>>(
        FEAT, FEAT, 1 << 30, FCK, FSTEPS, FWhi, FWlo, FCK, nullptr,
        FC1P, 128, (size_t)Bsz * 128);
    fc1_reduce<<<(Bsz * 128) / 256, 256>>>(FC1P, fc1_b, FC1R);

    // FC2 + deterministic norm + scale
    fc2_norm<<<240, 256>>>(FC1R, fc2_w, fc2_b, out, PART);
    reduce_norm<<<1, 256>>>(PART, INV);
    scale_out<<<240, 256>>>(out, INV);
}

// round 7
// speedup vs baseline: 4.0556x; 1.3768x over previous
#include <cuda_runtime.h>
#include <cuda_bf16.h>
#include <cstdint>
#include <cstddef>

#define Bsz 4096
#define Tsz 60
#define Dsz 200
#define K0P 208             // Dsz padded to multiple of 16
#define Hsz 64
#define G4  256
#define BT  (Bsz*Tsz)       // 245760
#define M2  (2*BT)          // 491520
#define FCK (2*Tsz*Hsz)     // 7680
#define FSPLIT 8
#define FSTEPS (FCK/FSPLIT/16)  // 60 k-steps per split

// lstm_tc smem layout (bytes)
#define OFF_WH 0            // Whh hi  256 x 144
#define OFF_WL 36864        // Whh lo
#define OFF_AH 73728        // h hi    64 x 144
#define OFF_AL 82944        // h lo
#define OFF_GT 92160        // gates   64 x 258 floats
#define OFF_XG 158208       // xg      64 x 256 floats
#define LSTM_SMEM 223744

// ---------------- scratch (device globals: allocation-free) ----------------
__device__ float g_XG[(size_t)M2 * G4];
__device__ float g_H1[(size_t)M2 * Hsz];
__device__ float g_FEAT[(size_t)Bsz * FCK];
__device__ float g_FC1P[(size_t)FSPLIT * Bsz * 128];
__device__ float g_FC1R[(size_t)Bsz * 128];
__device__ float g_PART[240];
__device__ float g_INV[1];
__device__ __nv_bfloat16 g_W0hi[256 * K0P];
__device__ __nv_bfloat16 g_W0lo[256 * K0P];
__device__ __nv_bfloat16 g_W1hi[256 * 64];
__device__ __nv_bfloat16 g_W1lo[256 * 64];
__device__ __nv_bfloat16 g_WH0hi[256 * 64];
__device__ __nv_bfloat16 g_WH0lo[256 * 64];
__device__ __nv_bfloat16 g_WH1hi[256 * 64];
__device__ __nv_bfloat16 g_WH1lo[256 * 64];
__device__ __nv_bfloat16 g_FWhi[(size_t)128 * FCK];
__device__ __nv_bfloat16 g_FWlo[(size_t)128 * FCK];
__device__ float g_B0[256];
__device__ float g_B1[256];

// ---------------- activations ----------------
__device__ __forceinline__ float tanh_fast(float x) {
    float y;
    asm("tanh.approx.f32 %0, %1;" : "=f"(y) : "f"(x));
    return y;
}
__device__ __forceinline__ float sig_fast(float x) {
    return fmaf(tanh_fast(0.5f * x), 0.5f, 0.5f);
}

// ---------------- mma/ldmatrix helpers (baseline PTX) ----------------
__device__ __forceinline__ uint32_t smem_u32(const void* p) {
    uint32_t a;
    asm("{ .reg .u64 t; cvta.to.shared.u64 t, %1; cvt.u32.u64 %0, t; }" : "=r"(a) : "l"(p));
    return a;
}
#define LDSM_X4(r, addr) \
    asm volatile("ldmatrix.sync.aligned.m8n8.x4.shared.b16 {%0,%1,%2,%3}, [%4];" \
        : "=r"((r)[0]), "=r"((r)[1]), "=r"((r)[2]), "=r"((r)[3]) : "r"(addr))
#define LDSM_X2(r, addr) \
    asm volatile("ldmatrix.sync.aligned.m8n8.x2.shared.b16 {%0,%1}, [%2];" \
        : "=r"((r)[0]), "=r"((r)[1]) : "r"(addr))

__device__ __forceinline__ void mma_bf16(float* c, const uint32_t* a, const uint32_t* b) {
    asm volatile(
        "mma.sync.aligned.m16n8k16.row.col.f32.bf16.bf16.f32 "
        "{%0,%1,%2,%3}, {%4,%5,%6,%7}, {%8,%9}, {%0,%1,%2,%3};"
        : "+f"(c[0]), "+f"(c[1]), "+f"(c[2]), "+f"(c[3])
        : "r"(a[0]), "r"(a[1]), "r"(a[2]), "r"(a[3]), "r"(b[0]), "r"(b[1]));
}

__device__ __forceinline__ void cp16(uint32_t dst, const void* src) {
    asm volatile("cp.async.cg.shared.global [%0], [%1], 16;" :: "r"(dst), "l"(src));
}
#define CP_COMMIT() asm volatile("cp.async.commit_group;" ::: "memory")
#define CP_WAIT0()  asm volatile("cp.async.wait_group 0;" ::: "memory")

__device__ __forceinline__ uint32_t pack_hi(float v0, float v1, float& l0, float& l1) {
    __nv_bfloat16 h0 = __float2bfloat16(v0);
    __nv_bfloat16 h1 = __float2bfloat16(v1);
    l0 = v0 - __bfloat162float(h0);
    l1 = v1 - __bfloat162float(h1);
    return (uint32_t)__bfloat16_as_ushort(h0) | ((uint32_t)__bfloat16_as_ushort(h1) << 16);
}
__device__ __forceinline__ uint32_t pack_lo(float l0, float l1) {
    return (uint32_t)__bfloat16_as_ushort(__float2bfloat16(l0))
         | ((uint32_t)__bfloat16_as_ushort(__float2bfloat16(l1)) << 16);
}

// ---------------- W pre-conversion (fp32 -> bf16 hi/lo, zero-padded) --------
__global__ void convert_w(const float* __restrict__ W, int K, int ldwp, int total,
                          __nv_bfloat16* __restrict__ hi, __nv_bfloat16* __restrict__ lo)
{
    int idx = blockIdx.x * 256 + threadIdx.x;
    if (idx >= total) return;
    int n = idx / ldwp, k = idx - n * ldwp;
    float v = (k < K) ? W[n * K + k] : 0.f;
    __nv_bfloat16 h = __float2bfloat16(v);
    hi[idx] = h;
    lo[idx] = __float2bfloat16(v - __bfloat162float(h));
}
__global__ void combine_bias(const float* a, const float* b, float* o) {
    int i = threadIdx.x;
    o[i] = a[i] + b[i];
}

// ---------------- tensor-core GEMM (mma.sync bf16 hi/lo) — R6 proven --------
__global__ void __launch_bounds__(256) gemm_mma(
    const float* __restrict__ A0, const float* __restrict__ A1, int rowsplit,
    int lda, int nch,
    const __nv_bfloat16* __restrict__ Whi, const __nv_bfloat16* __restrict__ Wlo,
    int ldw, const float* __restrict__ bias,
    float* __restrict__ C, int ldc, size_t csplit)
{
    __shared__ __align__(16) uint32_t sm[12288];   // 48 KB
    const uint32_t sb = smem_u32(sm);

    const int tid  = threadIdx.x;
    const int lane = tid & 31;
    const int wid  = tid >> 5;
    const int warpM = wid >> 2;
    const int warpN = wid & 3;
    const int row0 = blockIdx.x * 128;
    const int col0 = blockIdx.y * 128;

    const float* Ab = (row0 < rowsplit)
        ? A0 + (size_t)row0 * lda
        : A1 + (size_t)(row0 - rowsplit) * lda;

    const int sr = tid >> 3;
    const int scp = tid & 7;

    const uint32_t laneA = (uint32_t)((((lane >> 3) & 1) * 8 + (lane & 7)) * 48
                                      + ((lane >> 4) * 8) * 2);
    const uint32_t laneB = (uint32_t)((lane & 7) * 48 + (((lane >> 3) & 1) * 8) * 2);
    const uint32_t aBase = sb + (uint32_t)(warpM * 64) * 48 + laneA;
    const uint32_t bBase = sb + 24576u + (uint32_t)(warpN * 32) * 48 + laneB;

    float acc[4][4][4];
#pragma unroll
    for (int mt = 0; mt < 4; mt++)
#pragma unroll
        for (int nt = 0; nt < 4; nt++)
#pragma unroll
            for (int e = 0; e < 4; e++) acc[mt][nt][e] = 0.f;

    float2 av[4];
    uint32_t wh[4], wl[4];
    auto ldg_step = [&](int k0) {
#pragma unroll
        for (int i = 0; i < 4; i++) {
            int r = sr + 32 * i;
            int k = k0 + 2 * scp;
            if (k + 2 <= lda)
                av[i] = *reinterpret_cast<const float2*>(Ab + (size_t)r * lda + k);
            else
                av[i] = make_float2(0.f, 0.f);
            wh[i] = *reinterpret_cast<const uint32_t*>(Whi + (size_t)(col0 + r) * ldw + k0 + 2 * scp);
            wl[i] = *reinterpret_cast<const uint32_t*>(Wlo + (size_t)(col0 + r) * ldw + k0 + 2 * scp);
        }
    };
    auto sts_step = [&](int buf) {
        char* base = reinterpret_cast<char*>(sm) + buf * 12288;
#pragma unroll
        for (int i = 0; i < 4; i++) {
            int r = sr + 32 * i;
            float l0, l1;
            uint32_t hp = pack_hi(av[i].x, av[i].y, l0, l1);
            uint32_t lp = pack_lo(l0, l1);
            *reinterpret_cast<uint32_t*>(base + r * 48 + scp * 4) = hp;
            *reinterpret_cast<uint32_t*>(base + 6144 + r * 48 + scp * 4) = lp;
            *reinterpret_cast<uint32_t*>(base + 24576 + r * 48 + scp * 4) = wh[i];
            *reinterpret_cast<uint32_t*>(base + 24576 + 6144 + r * 48 + scp * 4) = wl[i];
        }
    };

    ldg_step(blockIdx.z * nch * 16);
    sts_step(0);
    __syncthreads();

    int buf = 0;
    for (int s = 0;; s++) {
        const bool more = (s + 1) < nch;
        if (more) ldg_step((blockIdx.z * nch + s + 1) * 16);

        uint32_t ah[4][4], al[4][4], bh[4][2], bl[4][2];
        uint32_t aOff = aBase + buf * 12288u;
        uint32_t bOff = bBase + buf * 12288u;
#pragma unroll
        for (int mt = 0; mt < 4; mt++) {
            LDSM_X4(ah[mt], aOff + mt * 768u);
            LDSM_X4(al[mt], aOff + mt * 768u + 6144u);
        }
#pragma unroll
        for (int nt = 0; nt < 4; nt++) {
            LDSM_X2(bh[nt], bOff + nt * 384u);
            LDSM_X2(bl[nt], bOff + nt * 384u + 6144u);
        }
#pragma unroll
        for (int mt = 0; mt < 4; mt++)
#pragma unroll
            for (int nt = 0; nt < 4; nt++) {
                mma_bf16(acc[mt][nt], ah[mt], bh[nt]);
                mma_bf16(acc[mt][nt], ah[mt], bl[nt]);
                mma_bf16(acc[mt][nt], al[mt], bh[nt]);
            }

        if (!more) break;
        sts_step(buf ^ 1);
        __syncthreads();
        buf ^= 1;
    }

    float* Cb = C + (size_t)blockIdx.z * csplit;
    const int gid = lane >> 2;
    const int tig = lane & 3;
#pragma unroll
    for (int mt = 0; mt < 4; mt++) {
        int r = row0 + warpM * 64 + mt * 16 + gid;
#pragma unroll
        for (int nt = 0; nt < 4; nt++) {
            int cc = col0 + warpN * 32 + nt * 8 + 2 * tig;
            float b0 = bias ? bias[cc] : 0.f;
            float b1 = bias ? bias[cc + 1] : 0.f;
            float2 v0 = make_float2(acc[mt][nt][0] + b0, acc[mt][nt][1] + b1);
            float2 v1 = make_float2(acc[mt][nt][2] + b0, acc[mt][nt][3] + b1);
            *reinterpret_cast<float2*>(Cb + (size_t)r * ldc + cc) = v0;
            *reinterpret_cast<float2*>(Cb + (size_t)(r + 8) * ldc + cc) = v1;
        }
    }
}

// ---------------- tensor-core LSTM recurrence ----------------
// 64 batch rows/CTA, 512 threads (warps 0-7 do mma, all do activations).
// gates[64,256] = h[64,64] @ Whh^T via bf16 hi/lo mma; xg via cp.async;
// h repacked to bf16 hi/lo each step; c in registers.
__global__ void __launch_bounds__(512, 1) lstm_tc(
    const float* __restrict__ XG,
    const __nv_bfloat16* __restrict__ Whi,   // [256][64]
    const __nv_bfloat16* __restrict__ Wlo,
    float* __restrict__ out, int mode)
{
    extern __shared__ char smem[];
    const uint32_t sb = smem_u32(smem);
    const int tid = threadIdx.x;
    const int lane = tid & 31;
    const int wid = tid >> 5;
    const int row0 = blockIdx.x * 64;

    // load Whh hi/lo into padded smem (144B rows), zero h staging
    {
        const uint32_t* wh = reinterpret_cast<const uint32_t*>(Whi);
        const uint32_t* wl = reinterpret_cast<const uint32_t*>(Wlo);
#pragma unroll
        for (int i = 0; i < 16; i++) {
            int idx = tid + 512 * i;        // 8192 u32
            int r = idx >> 5, cc = idx & 31;
            *reinterpret_cast<uint32_t*>(smem + OFF_WH + r * 144 + cc * 4) = wh[idx];
            *reinterpret_cast<uint32_t*>(smem + OFF_WL + r * 144 + cc * 4) = wl[idx];
        }
#pragma unroll
        for (int i = 0; i < 5; i++) {
            int idx = tid + 512 * i;
            if (idx < 2304) {
                *reinterpret_cast<uint32_t*>(smem + OFF_AH + idx * 4) = 0;
                *reinterpret_cast<uint32_t*>(smem + OFF_AL + idx * 4) = 0;
            }
        }
    }

    const int warpM = wid & 3;
    const int warpN = wid >> 2;              // valid for wid<8
    const uint32_t aoff = sb + OFF_AH
        + (uint32_t)((warpM * 16 + (lane & 7) + ((lane >> 3) & 1) * 8) * 144
                     + (lane >> 4) * 16);
    const uint32_t boff = sb + OFF_WH
        + (uint32_t)((warpN * 128 + (lane & 7) + (lane >> 4) * 8) * 144
                     + ((lane >> 3) & 1) * 16);

    float cst[8];
#pragma unroll
    for (int i = 0; i < 8; i++) cst[i] = 0.f;

    // prefetch xg(0)
#pragma unroll
    for (int i = 0; i < 8; i++) {
        int idx = tid + 512 * i;
        int r = idx >> 6, ch = idx & 63;
        cp16(sb + OFF_XG + r * 1024 + ch * 16,
             XG + ((size_t)(row0 + r) * Tsz + 0) * 256 + ch * 4);
    }
    CP_COMMIT();
    __syncthreads();

    const int tg = tid >> 6;
    const int j = tid & 63;
    float* gates = reinterpret_cast<float*>(smem + OFF_GT);
    const float* xgs = reinterpret_cast<const float*>(smem + OFF_XG);

    for (int t = 0; t < Tsz; t++) {
        float acc[16][4];
        if (wid < 8) {
#pragma unroll
            for (int nt = 0; nt < 16; nt++)
#pragma unroll
                for (int e = 0; e < 4; e++) acc[nt][e] = 0.f;
#pragma unroll
            for (int ks = 0; ks < 4; ks++) {
                uint32_t ahi[4], alo[4];
                LDSM_X4(ahi, aoff + ks * 32);
                LDSM_X4(alo, aoff + ks * 32 + (OFF_AL - OFF_AH));
#pragma unroll
                for (int np = 0; np < 8; np++) {
                    uint32_t bhi[4], blo[4];
                    LDSM_X4(bhi, boff + np * 2304 + ks * 32);
                    LDSM_X4(blo, boff + np * 2304 + ks * 32 + (OFF_WL - OFF_WH));
                    mma_bf16(acc[2 * np],     ahi, bhi);
                    mma_bf16(acc[2 * np],     ahi, blo);
                    mma_bf16(acc[2 * np],     alo, bhi);
                    mma_bf16(acc[2 * np + 1], ahi, bhi + 2);
                    mma_bf16(acc[2 * np + 1], ahi, blo + 2);
                    mma_bf16(acc[2 * np + 1], alo, bhi + 2);
                }
            }
        }
        CP_WAIT0();
        __syncthreads();

        if (wid < 8) {
            const int gr = warpM * 16 + (lane >> 2);
            const int gc = warpN * 128 + 2 * (lane & 3);
#pragma unroll
            for (int nt = 0; nt < 16; nt++) {
                *reinterpret_cast<float2*>(gates + gr * 258 + gc + nt * 8)
                    = make_float2(acc[nt][0], acc[nt][1]);
                *reinterpret_cast<float2*>(gates + (gr + 8) * 258 + gc + nt * 8)
                    = make_float2(acc[nt][2], acc[nt][3]);
            }
        }
        __syncthreads();

        // activations: each thread 8 (row, j) pairs
#pragma unroll
        for (int ii = 0; ii < 8; ii++) {
            int r = tg * 8 + ii;
            float gi = gates[r * 258 + j]       + xgs[r * 256 + j];
            float gf = gates[r * 258 + 64 + j]  + xgs[r * 256 + 64 + j];
            float gg = gates[r * 258 + 128 + j] + xgs[r * 256 + 128 + j];
            float go = gates[r * 258 + 192 + j] + xgs[r * 256 + 192 + j];
            cst[ii] = sig_fast(gf) * cst[ii] + sig_fast(gi) * tanh_fast(gg);
            float h = sig_fast(go) * tanh_fast(cst[ii]);
            int row = row0 + r;
            if (mode == 0) {
                out[((size_t)row * Tsz + t) * Hsz + j] = h;
            } else {
                int inp = row >> 12, b = row & (Bsz - 1);
                out[(size_t)b * FCK + (size_t)inp * (Tsz * Hsz)
                    + (size_t)t * Hsz + j] = fmaxf(h, 0.f);
            }
            float hp = __shfl_xor_sync(0xFFFFFFFFu, h, 1);
            if ((j & 1) == 0) {
                float l0, l1;
                uint32_t hw = pack_hi(h, hp, l0, l1);
                uint32_t lw = pack_lo(l0, l1);
                *reinterpret_cast<uint32_t*>(smem + OFF_AH + r * 144 + j * 2) = hw;
                *reinterpret_cast<uint32_t*>(smem + OFF_AL + r * 144 + j * 2) = lw;
            }
        }
        __syncthreads();

        if (t + 1 < Tsz) {
#pragma unroll
            for (int i = 0; i < 8; i++) {
                int idx = tid + 512 * i;
                int r = idx >> 6, ch = idx & 63;
                cp16(sb + OFF_XG + r * 1024 + ch * 16,
                     XG + ((size_t)(row0 + r) * Tsz + t + 1) * 256 + ch * 4);
            }
            CP_COMMIT();
        }
    }
}

// ---------------- FC1 split-K reduction (+bias, +relu) ----------------
__global__ void __launch_bounds__(256) fc1_reduce(
    const float* __restrict__ part, const float* __restrict__ bias,
    float* __restrict__ outp)
{
    const size_t S = (size_t)Bsz * 128;
    size_t i = (size_t)blockIdx.x * 256 + threadIdx.x;
    int n = (int)(i & 127);
    float s = bias[n];
#pragma unroll
    for (int z = 0; z < FSPLIT; z++) s += part[i + z * S];
    outp[i] = fmaxf(s, 0.f);
}

// ---------------- FC2 + partial sum-of-squares ----------------
__global__ void __launch_bounds__(256) fc2_norm(
    const float* __restrict__ fc1, const float* __restrict__ w,
    const float* __restrict__ bias, float* __restrict__ out,
    float* __restrict__ partial)
{
    __shared__ float sw[15 * 132];
    __shared__ float red[256];
    const int tid = threadIdx.x;
    for (int i = tid; i < 15 * 128; i += 256) {
        int n = i >> 7, k = i & 127;
        sw[n * 132 + k] = w[i];
    }
    __syncthreads();

    int idx = blockIdx.x * 256 + tid;
    int b = idx / 15, n = idx - b * 15;
    const float4* fr = reinterpret_cast<const float4*>(fc1 + (size_t)b * 128);
    const float4* wn = reinterpret_cast<const float4*>(sw + n * 132);
    float acc = bias[n];
#pragma unroll
    for (int k = 0; k < 32; k++) {
        float4 f4 = fr[k];
        float4 w4 = wn[k];
        acc = fmaf(f4.x, w4.x, acc);
        acc = fmaf(f4.y, w4.y, acc);
        acc = fmaf(f4.z, w4.z, acc);
        acc = fmaf(f4.w, w4.w, acc);
    }
    out[idx] = acc;
    red[tid] = acc * acc;
    __syncthreads();
#pragma unroll
    for (int s = 128; s > 0; s >>= 1) {
        if (tid < s) red[tid] += red[tid + s];
        __syncthreads();
    }
    if (tid == 0) partial[blockIdx.x] = red[0];
}

__global__ void reduce_norm(const float* __restrict__ partial, float* __restrict__ inv)
{
    __shared__ float red[256];
    float s = 0.f;
    for (int i = threadIdx.x; i < 240; i += 256) s += partial[i];
    red[threadIdx.x] = s;
    __syncthreads();
#pragma unroll
    for (int st = 128; st > 0; st >>= 1) {
        if (threadIdx.x < st) red[threadIdx.x] += red[threadIdx.x + st];
        __syncthreads();
    }
    if (threadIdx.x == 0) inv[0] = 1.0f / sqrtf(red[0]);
}

__global__ void scale_out(float* __restrict__ out, const float* __restrict__ inv)
{
    int i = blockIdx.x * 256 + threadIdx.x;
    out[i] *= inv[0];
}

// ---------------- launch ----------------
extern "C" void kernel_launch(void* const* d_in, const int* in_sizes, int n_in,
                              void* d_out, int out_size)
{
    const float* x1      = (const float*)d_in[0];
    const float* x2      = (const float*)d_in[1];
    const float* W_ih_l0 = (const float*)d_in[2];
    const float* W_hh_l0 = (const float*)d_in[3];
    const float* b_ih_l0 = (const float*)d_in[4];
    const float* b_hh_l0 = (const float*)d_in[5];
    const float* W_ih_l1 = (const float*)d_in[6];
    const float* W_hh_l1 = (const float*)d_in[7];
    const float* b_ih_l1 = (const float*)d_in[8];
    const float* b_hh_l1 = (const float*)d_in[9];
    const float* fc1_w   = (const float*)d_in[10];
    const float* fc1_b   = (const float*)d_in[11];
    const float* fc2_w   = (const float*)d_in[12];
    const float* fc2_b   = (const float*)d_in[13];
    float* out = (float*)d_out;

    float *XG, *H1, *FEAT, *FC1P, *FC1R, *PART, *INV, *B0, *B1;
    __nv_bfloat16 *W0hi, *W0lo, *W1hi, *W1lo, *FWhi, *FWlo;
    __nv_bfloat16 *WH0hi, *WH0lo, *WH1hi, *WH1lo;
    cudaGetSymbolAddress((void**)&XG,   g_XG);
    cudaGetSymbolAddress((void**)&H1,   g_H1);
    cudaGetSymbolAddress((void**)&FEAT, g_FEAT);
    cudaGetSymbolAddress((void**)&FC1P, g_FC1P);
    cudaGetSymbolAddress((void**)&FC1R, g_FC1R);
    cudaGetSymbolAddress((void**)&PART, g_PART);
    cudaGetSymbolAddress((void**)&INV,  g_INV);
    cudaGetSymbolAddress((void**)&B0,   g_B0);
    cudaGetSymbolAddress((void**)&B1,   g_B1);
    cudaGetSymbolAddress((void**)&W0hi, g_W0hi);
    cudaGetSymbolAddress((void**)&W0lo, g_W0lo);
    cudaGetSymbolAddress((void**)&W1hi, g_W1hi);
    cudaGetSymbolAddress((void**)&W1lo, g_W1lo);
    cudaGetSymbolAddress((void**)&WH0hi, g_WH0hi);
    cudaGetSymbolAddress((void**)&WH0lo, g_WH0lo);
    cudaGetSymbolAddress((void**)&WH1hi, g_WH1hi);
    cudaGetSymbolAddress((void**)&WH1lo, g_WH1lo);
    cudaGetSymbolAddress((void**)&FWhi, g_FWhi);
    cudaGetSymbolAddress((void**)&FWlo, g_FWlo);

    cudaFuncSetAttribute(lstm_tc, cudaFuncAttributeMaxDynamicSharedMemorySize, LSTM_SMEM);

    // weight conversions + bias combines
    convert_w<<<(256 * K0P + 255) / 256, 256>>>(W_ih_l0, Dsz, K0P, 256 * K0P, W0hi, W0lo);
    convert_w<<<(256 * 64 + 255) / 256, 256>>>(W_ih_l1, Hsz, 64, 256 * 64, W1hi, W1lo);
    convert_w<<<(256 * 64 + 255) / 256, 256>>>(W_hh_l0, Hsz, 64, 256 * 64, WH0hi, WH0lo);
    convert_w<<<(256 * 64 + 255) / 256, 256>>>(W_hh_l1, Hsz, 64, 256 * 64, WH1hi, WH1lo);
    convert_w<<<(128 * FCK + 255) / 256, 256>>>(fc1_w, FCK, FCK, 128 * FCK, FWhi, FWlo);
    combine_bias<<<1, 256>>>(b_ih_l0, b_hh_l0, B0);
    combine_bias<<<1, 256>>>(b_ih_l1, b_hh_l1, B1);

    // layer-0 input projection: XG = [x1;x2] @ W_ih0^T + B0
    gemm_mma<<<dim3(M2 / 128, 2, 1), 256>>>(
        x1, x2, BT, Dsz, K0P / 16, W0hi, W0lo, K0P, B0, XG, 256, 0);

    // layer-0 recurrence (tensor cores) -> H1
    lstm_tc<<<128, 512, LSTM_SMEM>>>(XG, WH0hi, WH0lo, H1, 0);

    // layer-1 input projection: XG = H1 @ W_ih1^T + B1
    gemm_mma<<<dim3(M2 / 128, 2, 1), 256>>>(
        H1, H1, 1 << 30, Hsz, 4, W1hi, W1lo, 64, B1, XG, 256, 0);

    // layer-1 recurrence (tensor cores) -> relu(FEAT)
    lstm_tc<<<128, 512, LSTM_SMEM>>>(XG, WH1hi, WH1lo, FEAT, 1);

    // FC1: split-K x8, then reduce(+bias,+relu)
    gemm_mma<<<dim3(Bsz / 128, 1, FSPLIT), 256>>>(
        FEAT, FEAT, 1 << 30, FCK, FSTEPS, FWhi, FWlo, FCK, nullptr,
        FC1P, 128, (size_t)Bsz * 128);
    fc1_reduce<<<(Bsz * 128) / 256, 256>>>(FC1P, fc1_b, FC1R);

    // FC2 + deterministic norm + scale
    fc2_norm<<<240, 256>>>(FC1R, fc2_w, fc2_b, out, PART);
    reduce_norm<<<1, 256>>>(PART, INV);
    scale_out<<<240, 256>>>(out, INV);
}

// round 9
// speedup vs baseline: 4.9682x; 1.2250x over previous
#include <cuda_runtime.h>
#include <cuda_bf16.h>
#include <cuda_fp16.h>
#include <cstdint>
#include <cstddef>

#define Bsz 4096
#define Tsz 60
#define Dsz 200
#define K0P 208             // Dsz padded to multiple of 16
#define Hsz 64
#define G4  256
#define BT  (Bsz*Tsz)       // 245760
#define M2  (2*BT)          // 491520
#define FCK (2*Tsz*Hsz)     // 7680
#define FSPLIT 8
#define FSTEPS (FCK/FSPLIT/16)  // 60 k-steps per split

// fused-lstm smem layout (bytes); 144B-padded rows (conflict-free ldmatrix)
#define OW0  0              // Whh0 fp16 256x144
#define OWI  36864          // Wih1
#define OWH  73728          // Whh1
#define OH0H 110592         // h0 hi 64x144
#define OH0L 119808         // h0 lo
#define OH1H 129024         // h1 hi
#define OH1L 138240         // h1 lo
#define OXG  147456         // xg 64x256 f32
#define OB1  212992         // bias1 (permuted) 256 f32
#define FUSED_SMEM 214016

// ---------------- scratch (device globals: allocation-free) ----------------
__device__ float g_XG[(size_t)M2 * G4];
__device__ float g_FEAT[(size_t)Bsz * FCK];
__device__ float g_FC1P[(size_t)FSPLIT * Bsz * 128];
__device__ float g_FC1R[(size_t)Bsz * 128];
__device__ float g_PART[240];
__device__ float g_INV[1];
__device__ __nv_bfloat16 g_W0hi[256 * K0P];
__device__ __nv_bfloat16 g_W0lo[256 * K0P];
__device__ __half g_WR0[256 * 64];   // permuted Whh0 (fp16)
__device__ __half g_WI1[256 * 64];   // permuted Wih1
__device__ __half g_WH1[256 * 64];   // permuted Whh1
__device__ __nv_bfloat16 g_FWhi[(size_t)128 * FCK];
__device__ __nv_bfloat16 g_FWlo[(size_t)128 * FCK];
__device__ float g_B0[256];
__device__ float g_B1[256];

// ---------------- activations ----------------
__device__ __forceinline__ float tanh_fast(float x) {
    float y;
    asm("tanh.approx.f32 %0, %1;" : "=f"(y) : "f"(x));
    return y;
}
__device__ __forceinline__ float sig_fast(float x) {
    return fmaf(tanh_fast(0.5f * x), 0.5f, 0.5f);
}

// ---------------- mma/ldmatrix helpers (baseline PTX) ----------------
__device__ __forceinline__ uint32_t smem_u32(const void* p) {
    uint32_t a;
    asm("{ .reg .u64 t; cvta.to.shared.u64 t, %1; cvt.u32.u64 %0, t; }" : "=r"(a) : "l"(p));
    return a;
}
#define LDSM_X4(r, addr) \
    asm volatile("ldmatrix.sync.aligned.m8n8.x4.shared.b16 {%0,%1,%2,%3}, [%4];" \
        : "=r"((r)[0]), "=r"((r)[1]), "=r"((r)[2]), "=r"((r)[3]) : "r"(addr))
#define LDSM_X2(r, addr) \
    asm volatile("ldmatrix.sync.aligned.m8n8.x2.shared.b16 {%0,%1}, [%2];" \
        : "=r"((r)[0]), "=r"((r)[1]) : "r"(addr))

__device__ __forceinline__ void mma_bf16(float* c, const uint32_t* a, const uint32_t* b) {
    asm volatile(
        "mma.sync.aligned.m16n8k16.row.col.f32.bf16.bf16.f32 "
        "{%0,%1,%2,%3}, {%4,%5,%6,%7}, {%8,%9}, {%0,%1,%2,%3};"
        : "+f"(c[0]), "+f"(c[1]), "+f"(c[2]), "+f"(c[3])
        : "r"(a[0]), "r"(a[1]), "r"(a[2]), "r"(a[3]), "r"(b[0]), "r"(b[1]));
}
__device__ __forceinline__ void mma_f16(float* c, const uint32_t* a, const uint32_t* b) {
    asm volatile(
        "mma.sync.aligned.m16n8k16.row.col.f32.f16.f16.f32 "
        "{%0,%1,%2,%3}, {%4,%5,%6,%7}, {%8,%9}, {%0,%1,%2,%3};"
        : "+f"(c[0]), "+f"(c[1]), "+f"(c[2]), "+f"(c[3])
        : "r"(a[0]), "r"(a[1]), "r"(a[2]), "r"(a[3]), "r"(b[0]), "r"(b[1]));
}

__device__ __forceinline__ void cp16(uint32_t dst, const void* src) {
    asm volatile("cp.async.cg.shared.global [%0], [%1], 16;" :: "r"(dst), "l"(src));
}
#define CP_COMMIT() asm volatile("cp.async.commit_group;" ::: "memory")
#define CP_WAIT0()  asm volatile("cp.async.wait_group 0;" ::: "memory")

__device__ __forceinline__ uint32_t pack_hi(float v0, float v1, float& l0, float& l1) {
    __nv_bfloat16 h0 = __float2bfloat16(v0);
    __nv_bfloat16 h1 = __float2bfloat16(v1);
    l0 = v0 - __bfloat162float(h0);
    l1 = v1 - __bfloat162float(h1);
    return (uint32_t)__bfloat16_as_ushort(h0) | ((uint32_t)__bfloat16_as_ushort(h1) << 16);
}
__device__ __forceinline__ uint32_t pack_lo(float l0, float l1) {
    return (uint32_t)__bfloat16_as_ushort(__float2bfloat16(l0))
         | ((uint32_t)__bfloat16_as_ushort(__float2bfloat16(l1)) << 16);
}

// ---------------- conversions ----------------
// perm: output row n_out corresponds to input row (n_out&3)*64 + (n_out>>2)
__global__ void convert_w(const float* __restrict__ W, int K, int ldwp, int total,
                          int perm,
                          __nv_bfloat16* __restrict__ hi, __nv_bfloat16* __restrict__ lo)
{
    int idx = blockIdx.x * 256 + threadIdx.x;
    if (idx >= total) return;
    int n = idx / ldwp, k = idx - n * ldwp;
    int n_in = perm ? ((n & 3) * 64 + (n >> 2)) : n;
    float v = (k < K) ? W[n_in * K + k] : 0.f;
    __nv_bfloat16 h = __float2bfloat16(v);
    hi[idx] = h;
    lo[idx] = __float2bfloat16(v - __bfloat162float(h));
}
// recurrence weight: [256][64] fp32 -> permuted fp16
__global__ void convert_rec(const float* __restrict__ W, __half* __restrict__ o)
{
    int idx = blockIdx.x * 256 + threadIdx.x;   // < 16384
    int n = idx >> 6, k = idx & 63;
    int n_in = (n & 3) * 64 + (n >> 2);
    o[idx] = __float2half_rn(W[n_in * 64 + k]);
}
__global__ void combine_bias(const float* a, const float* b, float* o) {
    int i = threadIdx.x;
    int n_in = (i & 3) * 64 + (i >> 2);
    o[i] = a[n_in] + b[n_in];
}

// ---------------- tensor-core GEMM (mma.sync bf16 hi/lo) — R6 proven --------
__global__ void __launch_bounds__(256) gemm_mma(
    const float* __restrict__ A0, const float* __restrict__ A1, int rowsplit,
    int lda, int nch,
    const __nv_bfloat16* __restrict__ Whi, const __nv_bfloat16* __restrict__ Wlo,
    int ldw, const float* __restrict__ bias,
    float* __restrict__ C, int ldc, size_t csplit)
{
    __shared__ __align__(16) uint32_t sm[12288];   // 48 KB
    const uint32_t sb = smem_u32(sm);

    const int tid  = threadIdx.x;
    const int lane = tid & 31;
    const int wid  = tid >> 5;
    const int warpM = wid >> 2;
    const int warpN = wid & 3;
    const int row0 = blockIdx.x * 128;
    const int col0 = blockIdx.y * 128;

    const float* Ab = (row0 < rowsplit)
        ? A0 + (size_t)row0 * lda
        : A1 + (size_t)(row0 - rowsplit) * lda;

    const int sr = tid >> 3;
    const int scp = tid & 7;

    const uint32_t laneA = (uint32_t)((((lane >> 3) & 1) * 8 + (lane & 7)) * 48
                                      + ((lane >> 4) * 8) * 2);
    const uint32_t laneB = (uint32_t)((lane & 7) * 48 + (((lane >> 3) & 1) * 8) * 2);
    const uint32_t aBase = sb + (uint32_t)(warpM * 64) * 48 + laneA;
    const uint32_t bBase = sb + 24576u + (uint32_t)(warpN * 32) * 48 + laneB;

    float acc[4][4][4];
#pragma unroll
    for (int mt = 0; mt < 4; mt++)
#pragma unroll
        for (int nt = 0; nt < 4; nt++)
#pragma unroll
            for (int e = 0; e < 4; e++) acc[mt][nt][e] = 0.f;

    float2 av[4];
    uint32_t wh[4], wl[4];
    auto ldg_step = [&](int k0) {
#pragma unroll
        for (int i = 0; i < 4; i++) {
            int r = sr + 32 * i;
            int k = k0 + 2 * scp;
            if (k + 2 <= lda)
                av[i] = *reinterpret_cast<const float2*>(Ab + (size_t)r * lda + k);
            else
                av[i] = make_float2(0.f, 0.f);
            wh[i] = *reinterpret_cast<const uint32_t*>(Whi + (size_t)(col0 + r) * ldw + k0 + 2 * scp);
            wl[i] = *reinterpret_cast<const uint32_t*>(Wlo + (size_t)(col0 + r) * ldw + k0 + 2 * scp);
        }
    };
    auto sts_step = [&](int buf) {
        char* base = reinterpret_cast<char*>(sm) + buf * 12288;
#pragma unroll
        for (int i = 0; i < 4; i++) {
            int r = sr + 32 * i;
            float l0, l1;
            uint32_t hp = pack_hi(av[i].x, av[i].y, l0, l1);
            uint32_t lp = pack_lo(l0, l1);
            *reinterpret_cast<uint32_t*>(base + r * 48 + scp * 4) = hp;
            *reinterpret_cast<uint32_t*>(base + 6144 + r * 48 + scp * 4) = lp;
            *reinterpret_cast<uint32_t*>(base + 24576 + r * 48 + scp * 4) = wh[i];
            *reinterpret_cast<uint32_t*>(base + 24576 + 6144 + r * 48 + scp * 4) = wl[i];
        }
    };

    ldg_step(blockIdx.z * nch * 16);
    sts_step(0);
    __syncthreads();

    int buf = 0;
    for (int s = 0;; s++) {
        const bool more = (s + 1) < nch;
        if (more) ldg_step((blockIdx.z * nch + s + 1) * 16);

        uint32_t ah[4][4], al[4][4], bh[4][2], bl[4][2];
        uint32_t aOff = aBase + buf * 12288u;
        uint32_t bOff = bBase + buf * 12288u;
#pragma unroll
        for (int mt = 0; mt < 4; mt++) {
            LDSM_X4(ah[mt], aOff + mt * 768u);
            LDSM_X4(al[mt], aOff + mt * 768u + 6144u);
        }
#pragma unroll
        for (int nt = 0; nt < 4; nt++) {
            LDSM_X2(bh[nt], bOff + nt * 384u);
            LDSM_X2(bl[nt], bOff + nt * 384u + 6144u);
        }
#pragma unroll
        for (int mt = 0; mt < 4; mt++)
#pragma unroll
            for (int nt = 0; nt < 4; nt++) {
                mma_bf16(acc[mt][nt], ah[mt], bh[nt]);
                mma_bf16(acc[mt][nt], ah[mt], bl[nt]);
                mma_bf16(acc[mt][nt], al[mt], bh[nt]);
            }

        if (!more) break;
        sts_step(buf ^ 1);
        __syncthreads();
        buf ^= 1;
    }

    float* Cb = C + (size_t)blockIdx.z * csplit;
    const int gid = lane >> 2;
    const int tig = lane & 3;
#pragma unroll
    for (int mt = 0; mt < 4; mt++) {
        int r = row0 + warpM * 64 + mt * 16 + gid;
#pragma unroll
        for (int nt = 0; nt < 4; nt++) {
            int cc = col0 + warpN * 32 + nt * 8 + 2 * tig;
            float b0 = bias ? bias[cc] : 0.f;
            float b1 = bias ? bias[cc + 1] : 0.f;
            float2 v0 = make_float2(acc[mt][nt][0] + b0, acc[mt][nt][1] + b1);
            float2 v1 = make_float2(acc[mt][nt][2] + b0, acc[mt][nt][3] + b1);
            *reinterpret_cast<float2*>(Cb + (size_t)r * ldc + cc) = v0;
            *reinterpret_cast<float2*>(Cb + (size_t)(r + 8) * ldc + cc) = v1;
        }
    }
}

// ---------------- fused 2-layer tensor-core LSTM (fp16) ----------------
// 64 batch rows/CTA, 256 threads (8 warps). Gate-interleaved weights
// (col = 4j+gate): activations in MMA warps via one shfl_xor(1) exchange.
// Weights fp16 single; h fp16 hi/lo; xg fp32.
__global__ void __launch_bounds__(256, 1) lstm_fused_tc(
    const float* __restrict__ XG,       // [8192*T, 256] permuted cols, B0 folded
    const __half* __restrict__ W0,      // permuted Whh0 [256][64]
    const __half* __restrict__ Wi1,     // permuted Wih1
    const __half* __restrict__ Wh1,     // permuted Whh1
    const float* __restrict__ B1,       // permuted bias1
    float* __restrict__ FEAT)
{
    extern __shared__ char smem[];
    const uint32_t sb = smem_u32(smem);
    const int tid = threadIdx.x;
    const int lane = tid & 31;
    const int wid = tid >> 5;
    const int warpM = wid & 3;
    const int warpN = wid >> 2;
    const int row0 = blockIdx.x * 64;

    // ---- stage weights (144B rows), zero h, load bias ----
    {
        const uint32_t* w0 = reinterpret_cast<const uint32_t*>(W0);
        const uint32_t* wi = reinterpret_cast<const uint32_t*>(Wi1);
        const uint32_t* wh = reinterpret_cast<const uint32_t*>(Wh1);
#pragma unroll
        for (int i = 0; i < 32; i++) {
            int idx = tid + 256 * i;          // 8192 u32
            int r = idx >> 5, c = idx & 31;
            *reinterpret_cast<uint32_t*>(smem + OW0 + r * 144 + c * 4) = w0[idx];
            *reinterpret_cast<uint32_t*>(smem + OWI + r * 144 + c * 4) = wi[idx];
            *reinterpret_cast<uint32_t*>(smem + OWH + r * 144 + c * 4) = wh[idx];
        }
#pragma unroll
        for (int i = 0; i < 9; i++) {
            int idx = tid + 256 * i;          // 2304 u32 per region
            *reinterpret_cast<uint32_t*>(smem + OH0H + idx * 4) = 0;
            *reinterpret_cast<uint32_t*>(smem + OH0L + idx * 4) = 0;
            *reinterpret_cast<uint32_t*>(smem + OH1H + idx * 4) = 0;
            *reinterpret_cast<uint32_t*>(smem + OH1L + idx * 4) = 0;
        }
        reinterpret_cast<float*>(smem + OB1)[tid] = B1[tid];
    }

    // prefetch xg(0): 64 rows x 64 16B-chunks
#pragma unroll
    for (int i = 0; i < 16; i++) {
        int idx = tid + 256 * i;
        int r = idx >> 6, ch = idx & 63;
        cp16(sb + OXG + r * 1024 + ch * 16,
             XG + ((size_t)(row0 + r) * Tsz + 0) * 256 + ch * 4);
    }
    CP_COMMIT();

    const uint32_t aoff = (uint32_t)((warpM * 16 + (lane & 7) + ((lane >> 3) & 1) * 8) * 144
                                     + (lane >> 4) * 16);
    const uint32_t boff = (uint32_t)((warpN * 128 + (lane & 7) + (lane >> 4) * 8) * 144
                                     + ((lane >> 3) & 1) * 16);
    const uint32_t a0h = sb + OH0H + aoff, a0l = sb + OH0L + aoff;
    const uint32_t a1h = sb + OH1H + aoff, a1l = sb + OH1L + aoff;
    const uint32_t bW0 = sb + OW0 + boff, bWi = sb + OWI + boff, bWh = sb + OWH + boff;

    const int rbase = warpM * 16 + (lane >> 2) + ((lane & 1) << 3);
    const int jbase = warpN * 32 + ((lane & 3) >> 1);
    const bool evn = (lane & 1) == 0;
    const float* xgs = reinterpret_cast<const float*>(smem + OXG);
    const float* b1s = reinterpret_cast<const float*>(smem + OB1);

    const int grow = row0 + rbase;
    const int inp = grow >> 12, bb = grow & (Bsz - 1);
    float* featp = FEAT + (size_t)bb * FCK + (size_t)inp * (Tsz * Hsz);

    float c0st[16], c1st[16];
#pragma unroll
    for (int i = 0; i < 16; i++) { c0st[i] = 0.f; c1st[i] = 0.f; }

    __syncthreads();

    for (int t = 0; t < Tsz; t++) {
        float acc[16][4];
        // ---- MMA0: gates0 = (h0hi + h0lo) @ Whh0^T ----
#pragma unroll
        for (int nt = 0; nt < 16; nt++)
#pragma unroll
            for (int e = 0; e < 4; e++) acc[nt][e] = 0.f;
#pragma unroll
        for (int ks = 0; ks < 4; ks++) {
            uint32_t ah[4], al[4];
            LDSM_X4(ah, a0h + ks * 32);
            LDSM_X4(al, a0l + ks * 32);
#pragma unroll
            for (int np = 0; np < 8; np++) {
                uint32_t bv[4];
                LDSM_X4(bv, bW0 + np * 2304 + ks * 32);
                mma_f16(acc[2 * np],     ah, bv);
                mma_f16(acc[2 * np],     al, bv);
                mma_f16(acc[2 * np + 1], ah, bv + 2);
                mma_f16(acc[2 * np + 1], al, bv + 2);
            }
        }
        CP_WAIT0();
        __syncthreads();

        // ---- act0 (gates in registers; pair exchange via shfl) ----
#pragma unroll
        for (int nt = 0; nt < 16; nt++) {
            float p0 = __shfl_xor_sync(0xFFFFFFFFu, acc[nt][0], 1);
            float p1 = __shfl_xor_sync(0xFFFFFFFFu, acc[nt][1], 1);
            float p2 = __shfl_xor_sync(0xFFFFFFFFu, acc[nt][2], 1);
            float p3 = __shfl_xor_sync(0xFFFFFFFFu, acc[nt][3], 1);
            float gi = evn ? acc[nt][0] : p2;
            float gf = evn ? acc[nt][1] : p3;
            float gg = evn ? p0 : acc[nt][2];
            float go = evn ? p1 : acc[nt][3];
            int j = jbase + 2 * nt;
            float4 xv = *reinterpret_cast<const float4*>(xgs + rbase * 256 + 4 * j);
            gi += xv.x; gf += xv.y; gg += xv.z; go += xv.w;
            c0st[nt] = sig_fast(gf) * c0st[nt] + sig_fast(gi) * tanh_fast(gg);
            float h = sig_fast(go) * tanh_fast(c0st[nt]);
            __half hh = __float2half_rn(h);
            float lo = h - __half2float(hh);
            *reinterpret_cast<unsigned short*>(smem + OH0H + rbase * 144 + j * 2)
                = __half_as_ushort(hh);
            *reinterpret_cast<unsigned short*>(smem + OH0L + rbase * 144 + j * 2)
                = __half_as_ushort(__float2half_rn(lo));
        }
        __syncthreads();

        // prefetch xg(t+1) (overlaps MMA1/act1)
        if (t + 1 < Tsz) {
#pragma unroll
            for (int i = 0; i < 16; i++) {
                int idx = tid + 256 * i;
                int r = idx >> 6, ch = idx & 63;
                cp16(sb + OXG + r * 1024 + ch * 16,
                     XG + ((size_t)(row0 + r) * Tsz + t + 1) * 256 + ch * 4);
            }
            CP_COMMIT();
        }

        // ---- MMA1: gates1 = h0 @ Wih1^T + h1 @ Whh1^T ----
#pragma unroll
        for (int nt = 0; nt < 16; nt++)
#pragma unroll
            for (int e = 0; e < 4; e++) acc[nt][e] = 0.f;
#pragma unroll
        for (int ks = 0; ks < 4; ks++) {
            uint32_t ah[4], al[4];
            LDSM_X4(ah, a0h + ks * 32);
            LDSM_X4(al, a0l + ks * 32);
#pragma unroll
            for (int np = 0; np < 8; np++) {
                uint32_t bv[4];
                LDSM_X4(bv, bWi + np * 2304 + ks * 32);
                mma_f16(acc[2 * np],     ah, bv);
                mma_f16(acc[2 * np],     al, bv);
                mma_f16(acc[2 * np + 1], ah, bv + 2);
                mma_f16(acc[2 * np + 1], al, bv + 2);
            }
        }
#pragma unroll
        for (int ks = 0; ks < 4; ks++) {
            uint32_t ah[4], al[4];
            LDSM_X4(ah, a1h + ks * 32);
            LDSM_X4(al, a1l + ks * 32);
#pragma unroll
            for (int np = 0; np < 8; np++) {
                uint32_t bv[4];
                LDSM_X4(bv, bWh + np * 2304 + ks * 32);
                mma_f16(acc[2 * np],     ah, bv);
                mma_f16(acc[2 * np],     al, bv);
                mma_f16(acc[2 * np + 1], ah, bv + 2);
                mma_f16(acc[2 * np + 1], al, bv + 2);
            }
        }
        __syncthreads();   // protect h1 overwrite in act1 vs sibling MMA1 reads

        // ---- act1 + FEAT store ----
#pragma unroll
        for (int nt = 0; nt < 16; nt++) {
            float p0 = __shfl_xor_sync(0xFFFFFFFFu, acc[nt][0], 1);
            float p1 = __shfl_xor_sync(0xFFFFFFFFu, acc[nt][1], 1);
            float p2 = __shfl_xor_sync(0xFFFFFFFFu, acc[nt][2], 1);
            float p3 = __shfl_xor_sync(0xFFFFFFFFu, acc[nt][3], 1);
            float gi = evn ? acc[nt][0] : p2;
            float gf = evn ? acc[nt][1] : p3;
            float gg = evn ? p0 : acc[nt][2];
            float go = evn ? p1 : acc[nt][3];
            int j = jbase + 2 * nt;
            float4 bv = *reinterpret_cast<const float4*>(b1s + 4 * j);
            gi += bv.x; gf += bv.y; gg += bv.z; go += bv.w;
            c1st[nt] = sig_fast(gf) * c1st[nt] + sig_fast(gi) * tanh_fast(gg);
            float h = sig_fast(go) * tanh_fast(c1st[nt]);
            __half hh = __float2half_rn(h);
            float lo = h - __half2float(hh);
            *reinterpret_cast<unsigned short*>(smem + OH1H + rbase * 144 + j * 2)
                = __half_as_ushort(hh);
            *reinterpret_cast<unsigned short*>(smem + OH1L + rbase * 144 + j * 2)
                = __half_as_ushort(__float2half_rn(lo));
            featp[(size_t)t * Hsz + j] = fmaxf(h, 0.f);
        }
        __syncthreads();
    }
}

// ---------------- FC1 split-K reduction (+bias, +relu) ----------------
__global__ void __launch_bounds__(256) fc1_reduce(
    const float* __restrict__ part, const float* __restrict__ bias,
    float* __restrict__ outp)
{
    const size_t S = (size_t)Bsz * 128;
    size_t i = (size_t)blockIdx.x * 256 + threadIdx.x;
    int n = (int)(i & 127);
    float s = bias[n];
#pragma unroll
    for (int z = 0; z < FSPLIT; z++) s += part[i + z * S];
    outp[i] = fmaxf(s, 0.f);
}

// ---------------- FC2 + partial sum-of-squares ----------------
__global__ void __launch_bounds__(256) fc2_norm(
    const float* __restrict__ fc1, const float* __restrict__ w,
    const float* __restrict__ bias, float* __restrict__ out,
    float* __restrict__ partial)
{
    __shared__ float sw[15 * 132];
    __shared__ float red[256];
    const int tid = threadIdx.x;
    for (int i = tid; i < 15 * 128; i += 256) {
        int n = i >> 7, k = i & 127;
        sw[n * 132 + k] = w[i];
    }
    __syncthreads();

    int idx = blockIdx.x * 256 + tid;
    int b = idx / 15, n = idx - b * 15;
    const float4* fr = reinterpret_cast<const float4*>(fc1 + (size_t)b * 128);
    const float4* wn = reinterpret_cast<const float4*>(sw + n * 132);
    float acc = bias[n];
#pragma unroll
    for (int k = 0; k < 32; k++) {
        float4 f4 = fr[k];
        float4 w4 = wn[k];
        acc = fmaf(f4.x, w4.x, acc);
        acc = fmaf(f4.y, w4.y, acc);
        acc = fmaf(f4.z, w4.z, acc);
        acc = fmaf(f4.w, w4.w, acc);
    }
    out[idx] = acc;
    red[tid] = acc * acc;
    __syncthreads();
#pragma unroll
    for (int s = 128; s > 0; s >>= 1) {
        if (tid < s) red[tid] += red[tid + s];
        __syncthreads();
    }
    if (tid == 0) partial[blockIdx.x] = red[0];
}

__global__ void reduce_norm(const float* __restrict__ partial, float* __restrict__ inv)
{
    __shared__ float red[256];
    float s = 0.f;
    for (int i = threadIdx.x; i < 240; i += 256) s += partial[i];
    red[threadIdx.x] = s;
    __syncthreads();
#pragma unroll
    for (int st = 128; st > 0; st >>= 1) {
        if (threadIdx.x < st) red[threadIdx.x] += red[threadIdx.x + st];
        __syncthreads();
    }
    if (threadIdx.x == 0) inv[0] = 1.0f / sqrtf(red[0]);
}

__global__ void scale_out(float* __restrict__ out, const float* __restrict__ inv)
{
    int i = blockIdx.x * 256 + threadIdx.x;
    out[i] *= inv[0];
}

// ---------------- launch ----------------
extern "C" void kernel_launch(void* const* d_in, const int* in_sizes, int n_in,
                              void* d_out, int out_size)
{
    const float* x1      = (const float*)d_in[0];
    const float* x2      = (const float*)d_in[1];
    const float* W_ih_l0 = (const float*)d_in[2];
    const float* W_hh_l0 = (const float*)d_in[3];
    const float* b_ih_l0 = (const float*)d_in[4];
    const float* b_hh_l0 = (const float*)d_in[5];
    const float* W_ih_l1 = (const float*)d_in[6];
    const float* W_hh_l1 = (const float*)d_in[7];
    const float* b_ih_l1 = (const float*)d_in[8];
    const float* b_hh_l1 = (const float*)d_in[9];
    const float* fc1_w   = (const float*)d_in[10];
    const float* fc1_b   = (const float*)d_in[11];
    const float* fc2_w   = (const float*)d_in[12];
    const float* fc2_b   = (const float*)d_in[13];
    float* out = (float*)d_out;

    float *XG, *FEAT, *FC1P, *FC1R, *PART, *INV, *B0, *B1;
    __nv_bfloat16 *W0hi, *W0lo, *FWhi, *FWlo;
    __half *WR0, *WI1, *WH1;
    cudaGetSymbolAddress((void**)&XG,   g_XG);
    cudaGetSymbolAddress((void**)&FEAT, g_FEAT);
    cudaGetSymbolAddress((void**)&FC1P, g_FC1P);
    cudaGetSymbolAddress((void**)&FC1R, g_FC1R);
    cudaGetSymbolAddress((void**)&PART, g_PART);
    cudaGetSymbolAddress((void**)&INV,  g_INV);
    cudaGetSymbolAddress((void**)&B0,   g_B0);
    cudaGetSymbolAddress((void**)&B1,   g_B1);
    cudaGetSymbolAddress((void**)&W0hi, g_W0hi);
    cudaGetSymbolAddress((void**)&W0lo, g_W0lo);
    cudaGetSymbolAddress((void**)&WR0,  g_WR0);
    cudaGetSymbolAddress((void**)&WI1,  g_WI1);
    cudaGetSymbolAddress((void**)&WH1,  g_WH1);
    cudaGetSymbolAddress((void**)&FWhi, g_FWhi);
    cudaGetSymbolAddress((void**)&FWlo, g_FWlo);

    cudaFuncSetAttribute(lstm_fused_tc, cudaFuncAttributeMaxDynamicSharedMemorySize,
                         FUSED_SMEM);

    // conversions (W0 permuted hi/lo bf16; recurrence weights permuted fp16)
    convert_w<<<(256 * K0P + 255) / 256, 256>>>(W_ih_l0, Dsz, K0P, 256 * K0P, 1, W0hi, W0lo);
    convert_rec<<<64, 256>>>(W_hh_l0, WR0);
    convert_rec<<<64, 256>>>(W_ih_l1, WI1);
    convert_rec<<<64, 256>>>(W_hh_l1, WH1);
    convert_w<<<(128 * FCK + 255) / 256, 256>>>(fc1_w, FCK, FCK, 128 * FCK, 0, FWhi, FWlo);
    combine_bias<<<1, 256>>>(b_ih_l0, b_hh_l0, B0);
    combine_bias<<<1, 256>>>(b_ih_l1, b_hh_l1, B1);

    // layer-0 input projection (permuted gate columns): XG = [x1;x2] @ W0^T + B0
    gemm_mma<<<dim3(M2 / 128, 2, 1), 256>>>(
        x1, x2, BT, Dsz, K0P / 16, W0hi, W0lo, K0P, B0, XG, 256, 0);

    // fused 2-layer recurrence -> relu(FEAT)
    lstm_fused_tc<<<128, 256, FUSED_SMEM>>>(XG, WR0, WI1, WH1, B1, FEAT);

    // FC1: split-K x8, then reduce(+bias,+relu)
    gemm_mma<<<dim3(Bsz / 128, 1, FSPLIT), 256>>>(
        FEAT, FEAT, 1 << 30, FCK, FSTEPS, FWhi, FWlo, FCK, nullptr,
        FC1P, 128, (size_t)Bsz * 128);
    fc1_reduce<<<(Bsz * 128) / 256, 256>>>(FC1P, fc1_b, FC1R);

    // FC2 + deterministic norm + scale
    fc2_norm<<<240, 256>>>(FC1R, fc2_w, fc2_b, out, PART);
    reduce_norm<<<1, 256>>>(PART, INV);
    scale_out<<<240, 256>>>(out, INV);
}

// round 10
// speedup vs baseline: 5.5907x; 1.1253x over previous
#include <cuda_runtime.h>
#include <cuda_fp16.h>
#include <cstdint>
#include <cstddef>

#define Bsz 4096
#define Tsz 60
#define Dsz 200
#define K0P 208             // Dsz padded to multiple of 16
#define Hsz 64
#define G4  256
#define BT  (Bsz*Tsz)       // 245760
#define M2  (2*BT)          // 491520
#define FCK (2*Tsz*Hsz)     // 7680
#define FSPLIT 8
#define FSTEPS (FCK/FSPLIT/16)  // 60 k-steps per split

// fused-lstm smem layout (bytes); 144B-padded rows (conflict-free ldmatrix)
#define OW0  0              // Whh0 fp16 256x144
#define OWI  36864          // Wih1
#define OWH  73728          // Whh1
#define OH0H 110592         // h0 hi 64x144
#define OH0L 119808         // h0 lo
#define OH1H 129024         // h1 hi
#define OH1L 138240         // h1 lo
#define OXG  147456         // xg 64x256 fp16 (32768 B)
#define OB1  180224         // bias1 (permuted) 256 f32
#define FUSED_SMEM 181248

// ---------------- scratch (device globals: allocation-free) ----------------
__device__ __half g_XG[(size_t)M2 * G4];
__device__ __half g_FEAT[(size_t)Bsz * FCK];
__device__ float g_FC1P[(size_t)FSPLIT * Bsz * 128];
__device__ float g_FC1R[(size_t)Bsz * 128];
__device__ float g_PART[240];
__device__ float g_INV[1];
__device__ __half g_W0[256 * K0P];   // permuted W_ih0 fp16 (zero-padded K)
__device__ __half g_WR0[256 * 64];   // permuted Whh0
__device__ __half g_WI1[256 * 64];   // permuted Wih1
__device__ __half g_WH1[256 * 64];   // permuted Whh1
__device__ __half g_FW[(size_t)128 * FCK];  // fc1_w fp16
__device__ float g_B0[256];
__device__ float g_B1[256];

// ---------------- activations ----------------
__device__ __forceinline__ float tanh_fast(float x) {
    float y;
    asm("tanh.approx.f32 %0, %1;" : "=f"(y) : "f"(x));
    return y;
}
__device__ __forceinline__ float sig_fast(float x) {
    return fmaf(tanh_fast(0.5f * x), 0.5f, 0.5f);
}

// ---------------- mma/ldmatrix helpers (baseline PTX) ----------------
__device__ __forceinline__ uint32_t smem_u32(const void* p) {
    uint32_t a;
    asm("{ .reg .u64 t; cvta.to.shared.u64 t, %1; cvt.u32.u64 %0, t; }" : "=r"(a) : "l"(p));
    return a;
}
#define LDSM_X4(r, addr) \
    asm volatile("ldmatrix.sync.aligned.m8n8.x4.shared.b16 {%0,%1,%2,%3}, [%4];" \
        : "=r"((r)[0]), "=r"((r)[1]), "=r"((r)[2]), "=r"((r)[3]) : "r"(addr))
#define LDSM_X2(r, addr) \
    asm volatile("ldmatrix.sync.aligned.m8n8.x2.shared.b16 {%0,%1}, [%2];" \
        : "=r"((r)[0]), "=r"((r)[1]) : "r"(addr))

__device__ __forceinline__ void mma_f16(float* c, const uint32_t* a, const uint32_t* b) {
    asm volatile(
        "mma.sync.aligned.m16n8k16.row.col.f32.f16.f16.f32 "
        "{%0,%1,%2,%3}, {%4,%5,%6,%7}, {%8,%9}, {%0,%1,%2,%3};"
        : "+f"(c[0]), "+f"(c[1]), "+f"(c[2]), "+f"(c[3])
        : "r"(a[0]), "r"(a[1]), "r"(a[2]), "r"(a[3]), "r"(b[0]), "r"(b[1]));
}

__device__ __forceinline__ void cp16(uint32_t dst, const void* src) {
    asm volatile("cp.async.cg.shared.global [%0], [%1], 16;" :: "r"(dst), "l"(src));
}
#define CP_COMMIT() asm volatile("cp.async.commit_group;" ::: "memory")
#define CP_WAIT0()  asm volatile("cp.async.wait_group 0;" ::: "memory")

// ---------------- conversions ----------------
// perm: output row n_out corresponds to input row (n_out&3)*64 + (n_out>>2)
__global__ void convert_f16(const float* __restrict__ W, int K, int ldwp, int total,
                            int perm, __half* __restrict__ o)
{
    int idx = blockIdx.x * 256 + threadIdx.x;
    if (idx >= total) return;
    int n = idx / ldwp, k = idx - n * ldwp;
    int n_in = perm ? ((n & 3) * 64 + (n >> 2)) : n;
    float v = (k < K) ? W[n_in * K + k] : 0.f;
    o[idx] = __float2half_rn(v);
}
__global__ void combine_bias(const float* a, const float* b, float* o) {
    int i = threadIdx.x;
    int n_in = (i & 3) * 64 + (i >> 2);
    o[i] = a[n_in] + b[n_in];
}

// ---------------- fp16 tensor-core GEMM: C = A[M,K] * W[N,K]^T (+bias) ------
// CTA 128x128, 8 warps (warpM=wid>>2 in {0,1} -> 64 rows; warpN=wid&3 -> 32 cols).
// fp16 single operands, fp32 accum. Double-buffered (2 x 12288 B), 1 sync/iter.
// AHALF: A is fp16 (copied); else fp32 (converted on the fly). OutT half/float.
template<int AHALF, typename OutT>
__global__ void __launch_bounds__(256) gemm_f16(
    const void* __restrict__ A0v, const void* __restrict__ A1v, int rowsplit,
    int lda, int nch,
    const __half* __restrict__ W, int ldw, const float* __restrict__ bias,
    OutT* __restrict__ C, int ldc, size_t csplit)
{
    __shared__ __align__(16) uint32_t sm[6144];   // 24 KB
    const uint32_t sb = smem_u32(sm);

    const int tid  = threadIdx.x;
    const int lane = tid & 31;
    const int wid  = tid >> 5;
    const int warpM = wid >> 2;          // 0..1
    const int warpN = wid & 3;           // 0..3
    const int row0 = blockIdx.x * 128;
    const int col0 = blockIdx.y * 128;

    const size_t elt = AHALF ? 2 : 4;
    const char* Ab = (const char*)((row0 < rowsplit) ? A0v : A1v)
        + (size_t)((row0 < rowsplit) ? row0 : row0 - rowsplit) * lda * elt;

    const uint32_t laneA = (uint32_t)((((lane >> 3) & 1) * 8 + (lane & 7)) * 48
                                      + (lane >> 4) * 16);
    const uint32_t laneB = (uint32_t)((lane & 7) * 48 + ((lane >> 3) & 1) * 16);
    const uint32_t aBase = sb + (uint32_t)(warpM * 64) * 48 + laneA;
    const uint32_t bBase = sb + 6144u + (uint32_t)(warpN * 32) * 48 + laneB;

    float acc[4][4][4];
#pragma unroll
    for (int mt = 0; mt < 4; mt++)
#pragma unroll
        for (int nt = 0; nt < 4; nt++)
#pragma unroll
            for (int e = 0; e < 4; e++) acc[mt][nt][e] = 0.f;

    uint32_t areg[4], wreg[4];
    auto ldg_step = [&](int k0) {
#pragma unroll
        for (int i = 0; i < 4; i++) {
            int idx = tid + 256 * i;     // < 1024
            int r = idx >> 3, cp = idx & 7;
            int k = k0 + 2 * cp;
            if (AHALF) {
                areg[i] = (k + 2 <= lda)
                    ? *reinterpret_cast<const uint32_t*>(
                        Ab + ((size_t)r * lda + k) * 2)
                    : 0u;
            } else {
                if (k + 2 <= lda) {
                    float2 f = *reinterpret_cast<const float2*>(
                        Ab + ((size_t)r * lda + k) * 4);
                    __half2 hh = __floats2half2_rn(f.x, f.y);
                    areg[i] = *reinterpret_cast<uint32_t*>(&hh);
                } else {
                    areg[i] = 0u;
                }
            }
            wreg[i] = *reinterpret_cast<const uint32_t*>(
                W + (size_t)(col0 + r) * ldw + k0 + 2 * cp);
        }
    };
    auto sts_step = [&](int buf) {
        char* base = reinterpret_cast<char*>(sm) + buf * 12288;
#pragma unroll
        for (int i = 0; i < 4; i++) {
            int idx = tid + 256 * i;
            int r = idx >> 3, cp = idx & 7;
            *reinterpret_cast<uint32_t*>(base + r * 48 + cp * 4) = areg[i];
            *reinterpret_cast<uint32_t*>(base + 6144 + r * 48 + cp * 4) = wreg[i];
        }
    };

    ldg_step(blockIdx.z * nch * 16);
    sts_step(0);
    __syncthreads();

    int buf = 0;
    for (int s = 0;; s++) {
        const bool more = (s + 1) < nch;
        if (more) ldg_step((blockIdx.z * nch + s + 1) * 16);

        uint32_t af[4][4], bf[4][2];
        uint32_t aOff = aBase + buf * 12288u;
        uint32_t bOff = bBase + buf * 12288u;
#pragma unroll
        for (int mt = 0; mt < 4; mt++) LDSM_X4(af[mt], aOff + mt * 768u);
#pragma unroll
        for (int nt = 0; nt < 4; nt++) LDSM_X2(bf[nt], bOff + nt * 384u);
#pragma unroll
        for (int mt = 0; mt < 4; mt++)
#pragma unroll
            for (int nt = 0; nt < 4; nt++)
                mma_f16(acc[mt][nt], af[mt], bf[nt]);

        if (!more) break;
        sts_step(buf ^ 1);
        __syncthreads();
        buf ^= 1;
    }

    OutT* Cb = C + (size_t)blockIdx.z * csplit;
    const int gid = lane >> 2;
    const int tig = lane & 3;
#pragma unroll
    for (int mt = 0; mt < 4; mt++) {
        int r = row0 + warpM * 64 + mt * 16 + gid;
#pragma unroll
        for (int nt = 0; nt < 4; nt++) {
            int cc = col0 + warpN * 32 + nt * 8 + 2 * tig;
            float b0 = bias ? bias[cc] : 0.f;
            float b1 = bias ? bias[cc + 1] : 0.f;
            float v00 = acc[mt][nt][0] + b0, v01 = acc[mt][nt][1] + b1;
            float v10 = acc[mt][nt][2] + b0, v11 = acc[mt][nt][3] + b1;
            if (sizeof(OutT) == 2) {
                __half2 h0 = __floats2half2_rn(v00, v01);
                __half2 h1 = __floats2half2_rn(v10, v11);
                *reinterpret_cast<__half2*>((__half*)Cb + (size_t)r * ldc + cc) = h0;
                *reinterpret_cast<__half2*>((__half*)Cb + (size_t)(r + 8) * ldc + cc) = h1;
            } else {
                *reinterpret_cast<float2*>((float*)Cb + (size_t)r * ldc + cc)
                    = make_float2(v00, v01);
                *reinterpret_cast<float2*>((float*)Cb + (size_t)(r + 8) * ldc + cc)
                    = make_float2(v10, v11);
            }
        }
    }
}

// ---------------- fused 2-layer tensor-core LSTM (fp16) ----------------
// 64 batch rows/CTA, 256 threads (8 warps). Gate-interleaved weights
// (col = 4j+gate): activations in MMA warps via one shfl_xor(1) exchange.
// Weights fp16 single; h fp16 hi/lo; xg fp16.
__global__ void __launch_bounds__(256, 1) lstm_fused_tc(
    const __half* __restrict__ XG,      // [8192*T, 256] permuted cols, B0 folded
    const __half* __restrict__ W0,      // permuted Whh0 [256][64]
    const __half* __restrict__ Wi1,     // permuted Wih1
    const __half* __restrict__ Wh1,     // permuted Whh1
    const float* __restrict__ B1,       // permuted bias1
    __half* __restrict__ FEAT)
{
    extern __shared__ char smem[];
    const uint32_t sb = smem_u32(smem);
    const int tid = threadIdx.x;
    const int lane = tid & 31;
    const int wid = tid >> 5;
    const int warpM = wid & 3;
    const int warpN = wid >> 2;
    const int row0 = blockIdx.x * 64;

    // ---- stage weights (144B rows), zero h, load bias ----
    {
        const uint32_t* w0 = reinterpret_cast<const uint32_t*>(W0);
        const uint32_t* wi = reinterpret_cast<const uint32_t*>(Wi1);
        const uint32_t* wh = reinterpret_cast<const uint32_t*>(Wh1);
#pragma unroll
        for (int i = 0; i < 32; i++) {
            int idx = tid + 256 * i;          // 8192 u32
            int r = idx >> 5, c = idx & 31;
            *reinterpret_cast<uint32_t*>(smem + OW0 + r * 144 + c * 4) = w0[idx];
            *reinterpret_cast<uint32_t*>(smem + OWI + r * 144 + c * 4) = wi[idx];
            *reinterpret_cast<uint32_t*>(smem + OWH + r * 144 + c * 4) = wh[idx];
        }
#pragma unroll
        for (int i = 0; i < 9; i++) {
            int idx = tid + 256 * i;          // 2304 u32 per region
            *reinterpret_cast<uint32_t*>(smem + OH0H + idx * 4) = 0;
            *reinterpret_cast<uint32_t*>(smem + OH0L + idx * 4) = 0;
            *reinterpret_cast<uint32_t*>(smem + OH1H + idx * 4) = 0;
            *reinterpret_cast<uint32_t*>(smem + OH1L + idx * 4) = 0;
        }
        reinterpret_cast<float*>(smem + OB1)[tid] = B1[tid];
    }

    // prefetch xg(0): 64 rows x 32 16B-chunks (fp16)
#pragma unroll
    for (int i = 0; i < 8; i++) {
        int idx = tid + 256 * i;              // < 2048
        int r = idx >> 5, ch = idx & 31;
        cp16(sb + OXG + r * 512 + ch * 16,
             XG + ((size_t)(row0 + r) * Tsz + 0) * 256 + ch * 8);
    }
    CP_COMMIT();

    const uint32_t aoff = (uint32_t)((warpM * 16 + (lane & 7) + ((lane >> 3) & 1) * 8) * 144
                                     + (lane >> 4) * 16);
    const uint32_t boff = (uint32_t)((warpN * 128 + (lane & 7) + (lane >> 4) * 8) * 144
                                     + ((lane >> 3) & 1) * 16);
    const uint32_t a0h = sb + OH0H + aoff, a0l = sb + OH0L + aoff;
    const uint32_t a1h = sb + OH1H + aoff, a1l = sb + OH1L + aoff;
    const uint32_t bW0 = sb + OW0 + boff, bWi = sb + OWI + boff, bWh = sb + OWH + boff;

    const int rbase = warpM * 16 + (lane >> 2) + ((lane & 1) << 3);
    const int jbase = warpN * 32 + ((lane & 3) >> 1);
    const bool evn = (lane & 1) == 0;
    const __half* xgs = reinterpret_cast<const __half*>(smem + OXG);
    const float* b1s = reinterpret_cast<const float*>(smem + OB1);

    const int grow = row0 + rbase;
    const int inp = grow >> 12, bb = grow & (Bsz - 1);
    __half* featp = FEAT + (size_t)bb * FCK + (size_t)inp * (Tsz * Hsz);

    float c0st[16], c1st[16];
#pragma unroll
    for (int i = 0; i < 16; i++) { c0st[i] = 0.f; c1st[i] = 0.f; }

    __syncthreads();

    for (int t = 0; t < Tsz; t++) {
        float acc[16][4];
        // ---- MMA0: gates0 = (h0hi + h0lo) @ Whh0^T ----
#pragma unroll
        for (int nt = 0; nt < 16; nt++)
#pragma unroll
            for (int e = 0; e < 4; e++) acc[nt][e] = 0.f;
#pragma unroll
        for (int ks = 0; ks < 4; ks++) {
            uint32_t ah[4], al[4];
            LDSM_X4(ah, a0h + ks * 32);
            LDSM_X4(al, a0l + ks * 32);
#pragma unroll
            for (int np = 0; np < 8; np++) {
                uint32_t bv[4];
                LDSM_X4(bv, bW0 + np * 2304 + ks * 32);
                mma_f16(acc[2 * np],     ah, bv);
                mma_f16(acc[2 * np],     al, bv);
                mma_f16(acc[2 * np + 1], ah, bv + 2);
                mma_f16(acc[2 * np + 1], al, bv + 2);
            }
        }
        CP_WAIT0();
        __syncthreads();

        // ---- act0 (gates in registers; pair exchange via shfl) ----
#pragma unroll
        for (int nt = 0; nt < 16; nt++) {
            float p0 = __shfl_xor_sync(0xFFFFFFFFu, acc[nt][0], 1);
            float p1 = __shfl_xor_sync(0xFFFFFFFFu, acc[nt][1], 1);
            float p2 = __shfl_xor_sync(0xFFFFFFFFu, acc[nt][2], 1);
            float p3 = __shfl_xor_sync(0xFFFFFFFFu, acc[nt][3], 1);
            float gi = evn ? acc[nt][0] : p2;
            float gf = evn ? acc[nt][1] : p3;
            float gg = evn ? p0 : acc[nt][2];
            float go = evn ? p1 : acc[nt][3];
            int j = jbase + 2 * nt;
            __half2 x01 = *reinterpret_cast<const __half2*>(xgs + rbase * 256 + 4 * j);
            __half2 x23 = *reinterpret_cast<const __half2*>(xgs + rbase * 256 + 4 * j + 2);
            float2 f01 = __half22float2(x01);
            float2 f23 = __half22float2(x23);
            gi += f01.x; gf += f01.y; gg += f23.x; go += f23.y;
            c0st[nt] = sig_fast(gf) * c0st[nt] + sig_fast(gi) * tanh_fast(gg);
            float h = sig_fast(go) * tanh_fast(c0st[nt]);
            __half hh = __float2half_rn(h);
            float lo = h - __half2float(hh);
            *reinterpret_cast<unsigned short*>(smem + OH0H + rbase * 144 + j * 2)
                = __half_as_ushort(hh);
            *reinterpret_cast<unsigned short*>(smem + OH0L + rbase * 144 + j * 2)
                = __half_as_ushort(__float2half_rn(lo));
        }
        __syncthreads();

        // prefetch xg(t+1) (overlaps MMA1/act1)
        if (t + 1 < Tsz) {
#pragma unroll
            for (int i = 0; i < 8; i++) {
                int idx = tid + 256 * i;
                int r = idx >> 5, ch = idx & 31;
                cp16(sb + OXG + r * 512 + ch * 16,
                     XG + ((size_t)(row0 + r) * Tsz + t + 1) * 256 + ch * 8);
            }
            CP_COMMIT();
        }

        // ---- MMA1: gates1 = h0 @ Wih1^T + h1 @ Whh1^T ----
#pragma unroll
        for (int nt = 0; nt < 16; nt++)
#pragma unroll
            for (int e = 0; e < 4; e++) acc[nt][e] = 0.f;
#pragma unroll
        for (int ks = 0; ks < 4; ks++) {
            uint32_t ah[4], al[4];
            LDSM_X4(ah, a0h + ks * 32);
            LDSM_X4(al, a0l + ks * 32);
#pragma unroll
            for (int np = 0; np < 8; np++) {
                uint32_t bv[4];
                LDSM_X4(bv, bWi + np * 2304 + ks * 32);
                mma_f16(acc[2 * np],     ah, bv);
                mma_f16(acc[2 * np],     al, bv);
                mma_f16(acc[2 * np + 1], ah, bv + 2);
                mma_f16(acc[2 * np + 1], al, bv + 2);
            }
        }
#pragma unroll
        for (int ks = 0; ks < 4; ks++) {
            uint32_t ah[4], al[4];
            LDSM_X4(ah, a1h + ks * 32);
            LDSM_X4(al, a1l + ks * 32);
#pragma unroll
            for (int np = 0; np < 8; np++) {
                uint32_t bv[4];
                LDSM_X4(bv, bWh + np * 2304 + ks * 32);
                mma_f16(acc[2 * np],     ah, bv);
                mma_f16(acc[2 * np],     al, bv);
                mma_f16(acc[2 * np + 1], ah, bv + 2);
                mma_f16(acc[2 * np + 1], al, bv + 2);
            }
        }
        __syncthreads();   // protect h1 overwrite in act1 vs sibling MMA1 reads

        // ---- act1 + FEAT store ----
#pragma unroll
        for (int nt = 0; nt < 16; nt++) {
            float p0 = __shfl_xor_sync(0xFFFFFFFFu, acc[nt][0], 1);
            float p1 = __shfl_xor_sync(0xFFFFFFFFu, acc[nt][1], 1);
            float p2 = __shfl_xor_sync(0xFFFFFFFFu, acc[nt][2], 1);
            float p3 = __shfl_xor_sync(0xFFFFFFFFu, acc[nt][3], 1);
            float gi = evn ? acc[nt][0] : p2;
            float gf = evn ? acc[nt][1] : p3;
            float gg = evn ? p0 : acc[nt][2];
            float go = evn ? p1 : acc[nt][3];
            int j = jbase + 2 * nt;
            float4 bv = *reinterpret_cast<const float4*>(b1s + 4 * j);
            gi += bv.x; gf += bv.y; gg += bv.z; go += bv.w;
            c1st[nt] = sig_fast(gf) * c1st[nt] + sig_fast(gi) * tanh_fast(gg);
            float h = sig_fast(go) * tanh_fast(c1st[nt]);
            __half hh = __float2half_rn(h);
            float lo = h - __half2float(hh);
            *reinterpret_cast<unsigned short*>(smem + OH1H + rbase * 144 + j * 2)
                = __half_as_ushort(hh);
            *reinterpret_cast<unsigned short*>(smem + OH1L + rbase * 144 + j * 2)
                = __half_as_ushort(__float2half_rn(lo));
            featp[(size_t)t * Hsz + j] = __float2half_rn(fmaxf(h, 0.f));
        }
        __syncthreads();
    }
}

// ---------------- FC1 split-K reduction (+bias, +relu) ----------------
__global__ void __launch_bounds__(256) fc1_reduce(
    const float* __restrict__ part, const float* __restrict__ bias,
    float* __restrict__ outp)
{
    const size_t S = (size_t)Bsz * 128;
    size_t i = (size_t)blockIdx.x * 256 + threadIdx.x;
    int n = (int)(i & 127);
    float s = bias[n];
#pragma unroll
    for (int z = 0; z < FSPLIT; z++) s += part[i + z * S];
    outp[i] = fmaxf(s, 0.f);
}

// ---------------- FC2 + partial sum-of-squares ----------------
__global__ void __launch_bounds__(256) fc2_norm(
    const float* __restrict__ fc1, const float* __restrict__ w,
    const float* __restrict__ bias, float* __restrict__ out,
    float* __restrict__ partial)
{
    __shared__ float sw[15 * 132];
    __shared__ float red[256];
    const int tid = threadIdx.x;
    for (int i = tid; i < 15 * 128; i += 256) {
        int n = i >> 7, k = i & 127;
        sw[n * 132 + k] = w[i];
    }
    __syncthreads();

    int idx = blockIdx.x * 256 + tid;
    int b = idx / 15, n = idx - b * 15;
    const float4* fr = reinterpret_cast<const float4*>(fc1 + (size_t)b * 128);
    const float4* wn = reinterpret_cast<const float4*>(sw + n * 132);
    float acc = bias[n];
#pragma unroll
    for (int k = 0; k < 32; k++) {
        float4 f4 = fr[k];
        float4 w4 = wn[k];
        acc = fmaf(f4.x, w4.x, acc);
        acc = fmaf(f4.y, w4.y, acc);
        acc = fmaf(f4.z, w4.z, acc);
        acc = fmaf(f4.w, w4.w, acc);
    }
    out[idx] = acc;
    red[tid] = acc * acc;
    __syncthreads();
#pragma unroll
    for (int s = 128; s > 0; s >>= 1) {
        if (tid < s) red[tid] += red[tid + s];
        __syncthreads();
    }
    if (tid == 0) partial[blockIdx.x] = red[0];
}

__global__ void reduce_norm(const float* __restrict__ partial, float* __restrict__ inv)
{
    __shared__ float red[256];
    float s = 0.f;
    for (int i = threadIdx.x; i < 240; i += 256) s += partial[i];
    red[threadIdx.x] = s;
    __syncthreads();
#pragma unroll
    for (int st = 128; st > 0; st >>= 1) {
        if (threadIdx.x < st) red[threadIdx.x] += red[threadIdx.x + st];
        __syncthreads();
    }
    if (threadIdx.x == 0) inv[0] = 1.0f / sqrtf(red[0]);
}

__global__ void scale_out(float* __restrict__ out, const float* __restrict__ inv)
{
    int i = blockIdx.x * 256 + threadIdx.x;
    out[i] *= inv[0];
}

// ---------------- launch ----------------
extern "C" void kernel_launch(void* const* d_in, const int* in_sizes, int n_in,
                              void* d_out, int out_size)
{
    const float* x1      = (const float*)d_in[0];
    const float* x2      = (const float*)d_in[1];
    const float* W_ih_l0 = (const float*)d_in[2];
    const float* W_hh_l0 = (const float*)d_in[3];
    const float* b_ih_l0 = (const float*)d_in[4];
    const float* b_hh_l0 = (const float*)d_in[5];
    const float* W_ih_l1 = (const float*)d_in[6];
    const float* W_hh_l1 = (const float*)d_in[7];
    const float* b_ih_l1 = (const float*)d_in[8];
    const float* b_hh_l1 = (const float*)d_in[9];
    const float* fc1_w   = (const float*)d_in[10];
    const float* fc1_b   = (const float*)d_in[11];
    const float* fc2_w   = (const float*)d_in[12];
    const float* fc2_b   = (const float*)d_in[13];
    float* out = (float*)d_out;

    float *FC1P, *FC1R, *PART, *INV, *B0, *B1;
    __half *XG, *FEAT, *W0, *WR0, *WI1, *WH1, *FW;
    cudaGetSymbolAddress((void**)&XG,   g_XG);
    cudaGetSymbolAddress((void**)&FEAT, g_FEAT);
    cudaGetSymbolAddress((void**)&FC1P, g_FC1P);
    cudaGetSymbolAddress((void**)&FC1R, g_FC1R);
    cudaGetSymbolAddress((void**)&PART, g_PART);
    cudaGetSymbolAddress((void**)&INV,  g_INV);
    cudaGetSymbolAddress((void**)&B0,   g_B0);
    cudaGetSymbolAddress((void**)&B1,   g_B1);
    cudaGetSymbolAddress((void**)&W0,   g_W0);
    cudaGetSymbolAddress((void**)&WR0,  g_WR0);
    cudaGetSymbolAddress((void**)&WI1,  g_WI1);
    cudaGetSymbolAddress((void**)&WH1,  g_WH1);
    cudaGetSymbolAddress((void**)&FW,   g_FW);

    cudaFuncSetAttribute(lstm_fused_tc, cudaFuncAttributeMaxDynamicSharedMemorySize,
                         FUSED_SMEM);

    // conversions: all fp16, permuted gate-interleaved for recurrence+proj0
    convert_f16<<<(256 * K0P + 255) / 256, 256>>>(W_ih_l0, Dsz, K0P, 256 * K0P, 1, W0);
    convert_f16<<<(256 * 64 + 255) / 256, 256>>>(W_hh_l0, Hsz, 64, 256 * 64, 1, WR0);
    convert_f16<<<(256 * 64 + 255) / 256, 256>>>(W_ih_l1, Hsz, 64, 256 * 64, 1, WI1);
    convert_f16<<<(256 * 64 + 255) / 256, 256>>>(W_hh_l1, Hsz, 64, 256 * 64, 1, WH1);
    convert_f16<<<(128 * FCK + 255) / 256, 256>>>(fc1_w, FCK, FCK, 128 * FCK, 0, FW);
    combine_bias<<<1, 256>>>(b_ih_l0, b_hh_l0, B0);
    combine_bias<<<1, 256>>>(b_ih_l1, b_hh_l1, B1);

    // layer-0 input projection (fp16 -> fp16 XG): XG = [x1;x2] @ W0^T + B0
    gemm_f16<0, __half><<<dim3(M2 / 128, 2, 1), 256>>>(
        x1, x2, BT, Dsz, K0P / 16, W0, K0P, B0, XG, 256, 0);

    // fused 2-layer recurrence -> relu(FEAT) fp16
    lstm_fused_tc<<<128, 256, FUSED_SMEM>>>(XG, WR0, WI1, WH1, B1, FEAT);

    // FC1: fp16 split-K x8, then reduce(+bias,+relu)
    gemm_f16<1, float><<<dim3(Bsz / 128, 1, FSPLIT), 256>>>(
        FEAT, FEAT, 1 << 30, FCK, FSTEPS, FW, FCK, nullptr,
        FC1P, 128, (size_t)Bsz * 128);
    fc1_reduce<<<(Bsz * 128) / 256, 256>>>(FC1P, fc1_b, FC1R);

    // FC2 + deterministic norm + scale
    fc2_norm<<<240, 256>>>(FC1R, fc2_w, fc2_b, out, PART);
    reduce_norm<<<1, 256>>>(PART, INV);
    scale_out<<<240, 256>>>(out, INV);
}

// round 11
// speedup vs baseline: 5.8215x; 1.0413x over previous
#include <cuda_runtime.h>
#include <cuda_fp16.h>
#include <cstdint>
#include <cstddef>

#define Bsz 4096
#define Tsz 60
#define Dsz 200
#define K0P 208             // Dsz padded to multiple of 16
#define Hsz 64
#define G4  256
#define BT  (Bsz*Tsz)       // 245760
#define M2  (2*BT)          // 491520
#define FCK (2*Tsz*Hsz)     // 7680
#define FSPLIT 8
#define FSTEPS (FCK/FSPLIT/16)  // 60 k-steps per split

// fused-lstm smem layout (bytes); 144B-padded rows (conflict-free ldmatrix)
#define OW0  0              // Whh0 fp16 256x144
#define OWI  36864          // Wih1
#define OWH  73728          // Whh1
#define OH0H 110592         // h0 hi 64x144
#define OH0L 119808         // h0 lo
#define OH1H 129024         // h1 hi
#define OH1L 138240         // h1 lo
#define OXG0 147456         // xg buf0: 64x256 fp16 (32768 B)
#define OXG1 180224         // xg buf1
#define OB1  212992         // bias1 (permuted) 256 f32
#define FUSED_SMEM 214016

// ---------------- scratch (device globals: allocation-free) ----------------
__device__ __half g_XG[(size_t)M2 * G4];
__device__ __half g_FEAT[(size_t)Bsz * FCK];
__device__ float g_FC1P[(size_t)FSPLIT * Bsz * 128];
__device__ float g_FC1R[(size_t)Bsz * 128];
__device__ float g_PART[240];
__device__ float g_INV[1];
__device__ __half g_W0[256 * K0P];   // permuted W_ih0 fp16 (zero-padded K)
__device__ __half g_WR0[256 * 64];   // permuted Whh0
__device__ __half g_WI1[256 * 64];   // permuted Wih1
__device__ __half g_WH1[256 * 64];   // permuted Whh1
__device__ __half g_FW[(size_t)128 * FCK];  // fc1_w fp16
__device__ float g_B0[256];
__device__ float g_B1[256];

// ---------------- activations ----------------
__device__ __forceinline__ float tanh_fast(float x) {
    float y;
    asm("tanh.approx.f32 %0, %1;" : "=f"(y) : "f"(x));
    return y;
}
__device__ __forceinline__ float sig_fast(float x) {
    return fmaf(tanh_fast(0.5f * x), 0.5f, 0.5f);
}

// ---------------- mma/ldmatrix helpers (baseline PTX) ----------------
__device__ __forceinline__ uint32_t smem_u32(const void* p) {
    uint32_t a;
    asm("{ .reg .u64 t; cvta.to.shared.u64 t, %1; cvt.u32.u64 %0, t; }" : "=r"(a) : "l"(p));
    return a;
}
#define LDSM_X4(r, addr) \
    asm volatile("ldmatrix.sync.aligned.m8n8.x4.shared.b16 {%0,%1,%2,%3}, [%4];" \
        : "=r"((r)[0]), "=r"((r)[1]), "=r"((r)[2]), "=r"((r)[3]) : "r"(addr))
#define LDSM_X2(r, addr) \
    asm volatile("ldmatrix.sync.aligned.m8n8.x2.shared.b16 {%0,%1}, [%2];" \
        : "=r"((r)[0]), "=r"((r)[1]) : "r"(addr))

__device__ __forceinline__ void mma_f16(float* c, const uint32_t* a, const uint32_t* b) {
    asm volatile(
        "mma.sync.aligned.m16n8k16.row.col.f32.f16.f16.f32 "
        "{%0,%1,%2,%3}, {%4,%5,%6,%7}, {%8,%9}, {%0,%1,%2,%3};"
        : "+f"(c[0]), "+f"(c[1]), "+f"(c[2]), "+f"(c[3])
        : "r"(a[0]), "r"(a[1]), "r"(a[2]), "r"(a[3]), "r"(b[0]), "r"(b[1]));
}

__device__ __forceinline__ void cp16(uint32_t dst, const void* src) {
    asm volatile("cp.async.cg.shared.global [%0], [%1], 16;" :: "r"(dst), "l"(src));
}
#define CP_COMMIT() asm volatile("cp.async.commit_group;" ::: "memory")
#define CP_WAIT0()  asm volatile("cp.async.wait_group 0;" ::: "memory")
#define CP_WAIT1()  asm volatile("cp.async.wait_group 1;" ::: "memory")

// ---------------- conversions ----------------
// perm: output row n_out corresponds to input row (n_out&3)*64 + (n_out>>2)
__global__ void convert_f16(const float* __restrict__ W, int K, int ldwp, int total,
                            int perm, __half* __restrict__ o)
{
    int idx = blockIdx.x * 256 + threadIdx.x;
    if (idx >= total) return;
    int n = idx / ldwp, k = idx - n * ldwp;
    int n_in = perm ? ((n & 3) * 64 + (n >> 2)) : n;
    float v = (k < K) ? W[n_in * K + k] : 0.f;
    o[idx] = __float2half_rn(v);
}
__global__ void combine_bias(const float* a, const float* b, float* o) {
    int i = threadIdx.x;
    int n_in = (i & 3) * 64 + (i >> 2);
    o[i] = a[n_in] + b[n_in];
}

// ---------------- fp16 tensor-core GEMM: C = A[M,K] * W[N,K]^T (+bias) ------
// R10-proven. CTA 128x128, 8 warps. fp16 single operands, fp32 accum.
template<int AHALF, typename OutT>
__global__ void __launch_bounds__(256) gemm_f16(
    const void* __restrict__ A0v, const void* __restrict__ A1v, int rowsplit,
    int lda, int nch,
    const __half* __restrict__ W, int ldw, const float* __restrict__ bias,
    OutT* __restrict__ C, int ldc, size_t csplit)
{
    __shared__ __align__(16) uint32_t sm[6144];   // 24 KB
    const uint32_t sb = smem_u32(sm);

    const int tid  = threadIdx.x;
    const int lane = tid & 31;
    const int wid  = tid >> 5;
    const int warpM = wid >> 2;
    const int warpN = wid & 3;
    const int row0 = blockIdx.x * 128;
    const int col0 = blockIdx.y * 128;

    const size_t elt = AHALF ? 2 : 4;
    const char* Ab = (const char*)((row0 < rowsplit) ? A0v : A1v)
        + (size_t)((row0 < rowsplit) ? row0 : row0 - rowsplit) * lda * elt;

    const uint32_t laneA = (uint32_t)((((lane >> 3) & 1) * 8 + (lane & 7)) * 48
                                      + (lane >> 4) * 16);
    const uint32_t laneB = (uint32_t)((lane & 7) * 48 + ((lane >> 3) & 1) * 16);
    const uint32_t aBase = sb + (uint32_t)(warpM * 64) * 48 + laneA;
    const uint32_t bBase = sb + 6144u + (uint32_t)(warpN * 32) * 48 + laneB;

    float acc[4][4][4];
#pragma unroll
    for (int mt = 0; mt < 4; mt++)
#pragma unroll
        for (int nt = 0; nt < 4; nt++)
#pragma unroll
            for (int e = 0; e < 4; e++) acc[mt][nt][e] = 0.f;

    uint32_t areg[4], wreg[4];
    auto ldg_step = [&](int k0) {
#pragma unroll
        for (int i = 0; i < 4; i++) {
            int idx = tid + 256 * i;
            int r = idx >> 3, cp = idx & 7;
            int k = k0 + 2 * cp;
            if (AHALF) {
                areg[i] = (k + 2 <= lda)
                    ? *reinterpret_cast<const uint32_t*>(
                        Ab + ((size_t)r * lda + k) * 2)
                    : 0u;
            } else {
                if (k + 2 <= lda) {
                    float2 f = *reinterpret_cast<const float2*>(
                        Ab + ((size_t)r * lda + k) * 4);
                    __half2 hh = __floats2half2_rn(f.x, f.y);
                    areg[i] = *reinterpret_cast<uint32_t*>(&hh);
                } else {
                    areg[i] = 0u;
                }
            }
            wreg[i] = *reinterpret_cast<const uint32_t*>(
                W + (size_t)(col0 + r) * ldw + k0 + 2 * cp);
        }
    };
    auto sts_step = [&](int buf) {
        char* base = reinterpret_cast<char*>(sm) + buf * 12288;
#pragma unroll
        for (int i = 0; i < 4; i++) {
            int idx = tid + 256 * i;
            int r = idx >> 3, cp = idx & 7;
            *reinterpret_cast<uint32_t*>(base + r * 48 + cp * 4) = areg[i];
            *reinterpret_cast<uint32_t*>(base + 6144 + r * 48 + cp * 4) = wreg[i];
        }
    };

    ldg_step(blockIdx.z * nch * 16);
    sts_step(0);
    __syncthreads();

    int buf = 0;
    for (int s = 0;; s++) {
        const bool more = (s + 1) < nch;
        if (more) ldg_step((blockIdx.z * nch + s + 1) * 16);

        uint32_t af[4][4], bf[4][2];
        uint32_t aOff = aBase + buf * 12288u;
        uint32_t bOff = bBase + buf * 12288u;
#pragma unroll
        for (int mt = 0; mt < 4; mt++) LDSM_X4(af[mt], aOff + mt * 768u);
#pragma unroll
        for (int nt = 0; nt < 4; nt++) LDSM_X2(bf[nt], bOff + nt * 384u);
#pragma unroll
        for (int mt = 0; mt < 4; mt++)
#pragma unroll
            for (int nt = 0; nt < 4; nt++)
                mma_f16(acc[mt][nt], af[mt], bf[nt]);

        if (!more) break;
        sts_step(buf ^ 1);
        __syncthreads();
        buf ^= 1;
    }

    OutT* Cb = C + (size_t)blockIdx.z * csplit;
    const int gid = lane >> 2;
    const int tig = lane & 3;
#pragma unroll
    for (int mt = 0; mt < 4; mt++) {
        int r = row0 + warpM * 64 + mt * 16 + gid;
#pragma unroll
        for (int nt = 0; nt < 4; nt++) {
            int cc = col0 + warpN * 32 + nt * 8 + 2 * tig;
            float b0 = bias ? bias[cc] : 0.f;
            float b1 = bias ? bias[cc + 1] : 0.f;
            float v00 = acc[mt][nt][0] + b0, v01 = acc[mt][nt][1] + b1;
            float v10 = acc[mt][nt][2] + b0, v11 = acc[mt][nt][3] + b1;
            if (sizeof(OutT) == 2) {
                __half2 h0 = __floats2half2_rn(v00, v01);
                __half2 h1 = __floats2half2_rn(v10, v11);
                *reinterpret_cast<__half2*>((__half*)Cb + (size_t)r * ldc + cc) = h0;
                *reinterpret_cast<__half2*>((__half*)Cb + (size_t)(r + 8) * ldc + cc) = h1;
            } else {
                *reinterpret_cast<float2*>((float*)Cb + (size_t)r * ldc + cc)
                    = make_float2(v00, v01);
                *reinterpret_cast<float2*>((float*)Cb + (size_t)(r + 8) * ldc + cc)
                    = make_float2(v10, v11);
            }
        }
    }
}

// ---------------- fused 2-layer tensor-core LSTM (fp16, skewed) -------------
// 64 batch rows/CTA, 512 threads (16 warps: warpM=wid&3 rows, warpN=wid>>2
// covering 64 gate cols each). One-step skew: at iter m one MMA phase computes
// gates0(m) = xg(m) + h0(m-1)@W0 AND gates1(m-1) = h0(m-1)@Wi1 + h1(m-2)@Wh1;
// one ACT phase applies both. 2 barriers/step. xg double-buffered via cp.async
// issued at top of the MMA phase (wait_group 1 before ACT).
__global__ void __launch_bounds__(512, 1) lstm_fused_tc(
    const __half* __restrict__ XG,      // [8192*T, 256] permuted cols, B0 folded
    const __half* __restrict__ W0,      // permuted Whh0 [256][64]
    const __half* __restrict__ Wi1,     // permuted Wih1
    const __half* __restrict__ Wh1,     // permuted Whh1
    const float* __restrict__ B1,       // permuted bias1
    __half* __restrict__ FEAT)
{
    extern __shared__ char smem[];
    const uint32_t sb = smem_u32(smem);
    const int tid = threadIdx.x;
    const int lane = tid & 31;
    const int wid = tid >> 5;
    const int warpM = wid & 3;          // 16 rows
    const int warpN = wid >> 2;         // 0..3, 64 gate cols
    const int row0 = blockIdx.x * 64;

    // ---- stage weights (144B rows), zero h, load bias ----
    {
        const uint32_t* w0 = reinterpret_cast<const uint32_t*>(W0);
        const uint32_t* wi = reinterpret_cast<const uint32_t*>(Wi1);
        const uint32_t* wh = reinterpret_cast<const uint32_t*>(Wh1);
#pragma unroll
        for (int i = 0; i < 16; i++) {
            int idx = tid + 512 * i;          // 8192 u32
            int r = idx >> 5, c = idx & 31;
            *reinterpret_cast<uint32_t*>(smem + OW0 + r * 144 + c * 4) = w0[idx];
            *reinterpret_cast<uint32_t*>(smem + OWI + r * 144 + c * 4) = wi[idx];
            *reinterpret_cast<uint32_t*>(smem + OWH + r * 144 + c * 4) = wh[idx];
        }
#pragma unroll
        for (int i = 0; i < 5; i++) {
            int idx = tid + 512 * i;          // 2304 u32 per region
            if (idx < 2304) {
                *reinterpret_cast<uint32_t*>(smem + OH0H + idx * 4) = 0;
                *reinterpret_cast<uint32_t*>(smem + OH0L + idx * 4) = 0;
                *reinterpret_cast<uint32_t*>(smem + OH1H + idx * 4) = 0;
                *reinterpret_cast<uint32_t*>(smem + OH1L + idx * 4) = 0;
            }
        }
        if (tid < 256) reinterpret_cast<float*>(smem + OB1)[tid] = B1[tid];
    }

    // prologue: prefetch xg(0) into buf0 (2048 16B chunks)
#pragma unroll
    for (int i = 0; i < 4; i++) {
        int idx = tid + 512 * i;
        int r = idx >> 5, ch = idx & 31;
        cp16(sb + OXG0 + r * 512 + ch * 16,
             XG + ((size_t)(row0 + r) * Tsz + 0) * 256 + ch * 8);
    }
    CP_COMMIT();

    const uint32_t aoff = (uint32_t)((warpM * 16 + (lane & 7) + ((lane >> 3) & 1) * 8) * 144
                                     + (lane >> 4) * 16);
    const uint32_t boff = (uint32_t)((warpN * 64 + (lane & 7) + (lane >> 4) * 8) * 144
                                     + ((lane >> 3) & 1) * 16);
    const uint32_t a0h = sb + OH0H + aoff, a0l = sb + OH0L + aoff;
    const uint32_t a1h = sb + OH1H + aoff, a1l = sb + OH1L + aoff;
    const uint32_t bW0 = sb + OW0 + boff, bWi = sb + OWI + boff, bWh = sb + OWH + boff;

    const int rbase = warpM * 16 + (lane >> 2) + ((lane & 1) << 3);
    const int jbase = warpN * 16 + ((lane & 3) >> 1);
    const bool evn = (lane & 1) == 0;
    const float* b1s = reinterpret_cast<const float*>(smem + OB1);

    const int grow = row0 + rbase;
    const int inp = grow >> 12, bb = grow & (Bsz - 1);
    __half* featp = FEAT + (size_t)bb * FCK + (size_t)inp * (Tsz * Hsz);

    float c0st[8], c1st[8];
#pragma unroll
    for (int i = 0; i < 8; i++) { c0st[i] = 0.f; c1st[i] = 0.f; }

    __syncthreads();

    for (int m = 0; m <= Tsz; m++) {
        // issue xg(m+1) prefetch into alternate buffer (overlaps the MMAs)
        if (m + 1 < Tsz) {
            uint32_t xdst = sb + (((m + 1) & 1) ? OXG1 : OXG0);
#pragma unroll
            for (int i = 0; i < 4; i++) {
                int idx = tid + 512 * i;
                int r = idx >> 5, ch = idx & 31;
                cp16(xdst + r * 512 + ch * 16,
                     XG + ((size_t)(row0 + r) * Tsz + m + 1) * 256 + ch * 8);
            }
        }
        CP_COMMIT();

        // ---- merged MMA phase (edges compute-and-discard; no divergence) ----
        float acc0[8][4], acc1[8][4];
#pragma unroll
        for (int nt = 0; nt < 8; nt++)
#pragma unroll
            for (int e = 0; e < 4; e++) { acc0[nt][e] = 0.f; acc1[nt][e] = 0.f; }

#pragma unroll
        for (int ks = 0; ks < 4; ks++) {
            uint32_t ah[4], al[4];
            LDSM_X4(ah, a0h + ks * 32);
            LDSM_X4(al, a0l + ks * 32);
#pragma unroll
            for (int np = 0; np < 4; np++) {
                uint32_t bv[4];
                LDSM_X4(bv, bW0 + np * 2304 + ks * 32);
                mma_f16(acc0[2 * np],     ah, bv);
                mma_f16(acc0[2 * np],     al, bv);
                mma_f16(acc0[2 * np + 1], ah, bv + 2);
                mma_f16(acc0[2 * np + 1], al, bv + 2);
                uint32_t bw[4];
                LDSM_X4(bw, bWi + np * 2304 + ks * 32);
                mma_f16(acc1[2 * np],     ah, bw);
                mma_f16(acc1[2 * np],     al, bw);
                mma_f16(acc1[2 * np + 1], ah, bw + 2);
                mma_f16(acc1[2 * np + 1], al, bw + 2);
            }
        }
#pragma unroll
        for (int ks = 0; ks < 4; ks++) {
            uint32_t ah[4], al[4];
            LDSM_X4(ah, a1h + ks * 32);
            LDSM_X4(al, a1l + ks * 32);
#pragma unroll
            for (int np = 0; np < 4; np++) {
                uint32_t bv[4];
                LDSM_X4(bv, bWh + np * 2304 + ks * 32);
                mma_f16(acc1[2 * np],     ah, bv);
                mma_f16(acc1[2 * np],     al, bv);
                mma_f16(acc1[2 * np + 1], ah, bv + 2);
                mma_f16(acc1[2 * np + 1], al, bv + 2);
            }
        }

        CP_WAIT1();          // xg(m) resident (newest group may be in flight)
        __syncthreads();

        // ---- ACT phase ----
        if (m < Tsz) {
            const __half* xbuf = reinterpret_cast<const __half*>(
                smem + ((m & 1) ? OXG1 : OXG0));
#pragma unroll
            for (int nt = 0; nt < 8; nt++) {
                float p0 = __shfl_xor_sync(0xFFFFFFFFu, acc0[nt][0], 1);
                float p1 = __shfl_xor_sync(0xFFFFFFFFu, acc0[nt][1], 1);
                float p2 = __shfl_xor_sync(0xFFFFFFFFu, acc0[nt][2], 1);
                float p3 = __shfl_xor_sync(0xFFFFFFFFu, acc0[nt][3], 1);
                float gi = evn ? acc0[nt][0] : p2;
                float gf = evn ? acc0[nt][1] : p3;
                float gg = evn ? p0 : acc0[nt][2];
                float go = evn ? p1 : acc0[nt][3];
                int j = jbase + 2 * nt;
                __half2 x01 = *reinterpret_cast<const __half2*>(xbuf + rbase * 256 + 4 * j);
                __half2 x23 = *reinterpret_cast<const __half2*>(xbuf + rbase * 256 + 4 * j + 2);
                float2 f01 = __half22float2(x01);
                float2 f23 = __half22float2(x23);
                gi += f01.x; gf += f01.y; gg += f23.x; go += f23.y;
                c0st[nt] = sig_fast(gf) * c0st[nt] + sig_fast(gi) * tanh_fast(gg);
                float h = sig_fast(go) * tanh_fast(c0st[nt]);
                __half hh = __float2half_rn(h);
                float lo = h - __half2float(hh);
                *reinterpret_cast<unsigned short*>(smem + OH0H + rbase * 144 + j * 2)
                    = __half_as_ushort(hh);
                *reinterpret_cast<unsigned short*>(smem + OH0L + rbase * 144 + j * 2)
                    = __half_as_ushort(__float2half_rn(lo));
            }
        }
        if (m >= 1) {
#pragma unroll
            for (int nt = 0; nt < 8; nt++) {
                float p0 = __shfl_xor_sync(0xFFFFFFFFu, acc1[nt][0], 1);
                float p1 = __shfl_xor_sync(0xFFFFFFFFu, acc1[nt][1], 1);
                float p2 = __shfl_xor_sync(0xFFFFFFFFu, acc1[nt][2], 1);
                float p3 = __shfl_xor_sync(0xFFFFFFFFu, acc1[nt][3], 1);
                float gi = evn ? acc1[nt][0] : p2;
                float gf = evn ? acc1[nt][1] : p3;
                float gg = evn ? p0 : acc1[nt][2];
                float go = evn ? p1 : acc1[nt][3];
                int j = jbase + 2 * nt;
                float4 bv = *reinterpret_cast<const float4*>(b1s + 4 * j);
                gi += bv.x; gf += bv.y; gg += bv.z; go += bv.w;
                c1st[nt] = sig_fast(gf) * c1st[nt] + sig_fast(gi) * tanh_fast(gg);
                float h = sig_fast(go) * tanh_fast(c1st[nt]);
                __half hh = __float2half_rn(h);
                float lo = h - __half2float(hh);
                *reinterpret_cast<unsigned short*>(smem + OH1H + rbase * 144 + j * 2)
                    = __half_as_ushort(hh);
                *reinterpret_cast<unsigned short*>(smem + OH1L + rbase * 144 + j * 2)
                    = __half_as_ushort(__float2half_rn(lo));
                featp[(size_t)(m - 1) * Hsz + j] = __float2half_rn(fmaxf(h, 0.f));
            }
        }
        __syncthreads();
    }
}

// ---------------- FC1 split-K reduction (+bias, +relu) ----------------
__global__ void __launch_bounds__(256) fc1_reduce(
    const float* __restrict__ part, const float* __restrict__ bias,
    float* __restrict__ outp)
{
    const size_t S = (size_t)Bsz * 128;
    size_t i = (size_t)blockIdx.x * 256 + threadIdx.x;
    int n = (int)(i & 127);
    float s = bias[n];
#pragma unroll
    for (int z = 0; z < FSPLIT; z++) s += part[i + z * S];
    outp[i] = fmaxf(s, 0.f);
}

// ---------------- FC2 + partial sum-of-squares ----------------
__global__ void __launch_bounds__(256) fc2_norm(
    const float* __restrict__ fc1, const float* __restrict__ w,
    const float* __restrict__ bias, float* __restrict__ out,
    float* __restrict__ partial)
{
    __shared__ float sw[15 * 132];
    __shared__ float red[256];
    const int tid = threadIdx.x;
    for (int i = tid; i < 15 * 128; i += 256) {
        int n = i >> 7, k = i & 127;
        sw[n * 132 + k] = w[i];
    }
    __syncthreads();

    int idx = blockIdx.x * 256 + tid;
    int b = idx / 15, n = idx - b * 15;
    const float4* fr = reinterpret_cast<const float4*>(fc1 + (size_t)b * 128);
    const float4* wn = reinterpret_cast<const float4*>(sw + n * 132);
    float acc = bias[n];
#pragma unroll
    for (int k = 0; k < 32; k++) {
        float4 f4 = fr[k];
        float4 w4 = wn[k];
        acc = fmaf(f4.x, w4.x, acc);
        acc = fmaf(f4.y, w4.y, acc);
        acc = fmaf(f4.z, w4.z, acc);
        acc = fmaf(f4.w, w4.w, acc);
    }
    out[idx] = acc;
    red[tid] = acc * acc;
    __syncthreads();
#pragma unroll
    for (int s = 128; s > 0; s >>= 1) {
        if (tid < s) red[tid] += red[tid + s];
        __syncthreads();
    }
    if (tid == 0) partial[blockIdx.x] = red[0];
}

__global__ void reduce_norm(const float* __restrict__ partial, float* __restrict__ inv)
{
    __shared__ float red[256];
    float s = 0.f;
    for (int i = threadIdx.x; i < 240; i += 256) s += partial[i];
    red[threadIdx.x] = s;
    __syncthreads();
#pragma unroll
    for (int st = 128; st > 0; st >>= 1) {
        if (threadIdx.x < st) red[threadIdx.x] += red[threadIdx.x + st];
        __syncthreads();
    }
    if (threadIdx.x == 0) inv[0] = 1.0f / sqrtf(red[0]);
}

__global__ void scale_out(float* __restrict__ out, const float* __restrict__ inv)
{
    int i = blockIdx.x * 256 + threadIdx.x;
    out[i] *= inv[0];
}

// ---------------- launch ----------------
extern "C" void kernel_launch(void* const* d_in, const int* in_sizes, int n_in,
                              void* d_out, int out_size)
{
    const float* x1      = (const float*)d_in[0];
    const float* x2      = (const float*)d_in[1];
    const float* W_ih_l0 = (const float*)d_in[2];
    const float* W_hh_l0 = (const float*)d_in[3];
    const float* b_ih_l0 = (const float*)d_in[4];
    const float* b_hh_l0 = (const float*)d_in[5];
    const float* W_ih_l1 = (const float*)d_in[6];
    const float* W_hh_l1 = (const float*)d_in[7];
    const float* b_ih_l1 = (const float*)d_in[8];
    const float* b_hh_l1 = (const float*)d_in[9];
    const float* fc1_w   = (const float*)d_in[10];
    const float* fc1_b   = (const float*)d_in[11];
    const float* fc2_w   = (const float*)d_in[12];
    const float* fc2_b   = (const float*)d_in[13];
    float* out = (float*)d_out;

    float *FC1P, *FC1R, *PART, *INV, *B0, *B1;
    __half *XG, *FEAT, *W0, *WR0, *WI1, *WH1, *FW;
    cudaGetSymbolAddress((void**)&XG,   g_XG);
    cudaGetSymbolAddress((void**)&FEAT, g_FEAT);
    cudaGetSymbolAddress((void**)&FC1P, g_FC1P);
    cudaGetSymbolAddress((void**)&FC1R, g_FC1R);
    cudaGetSymbolAddress((void**)&PART, g_PART);
    cudaGetSymbolAddress((void**)&INV,  g_INV);
    cudaGetSymbolAddress((void**)&B0,   g_B0);
    cudaGetSymbolAddress((void**)&B1,   g_B1);
    cudaGetSymbolAddress((void**)&W0,   g_W0);
    cudaGetSymbolAddress((void**)&WR0,  g_WR0);
    cudaGetSymbolAddress((void**)&WI1,  g_WI1);
    cudaGetSymbolAddress((void**)&WH1,  g_WH1);
    cudaGetSymbolAddress((void**)&FW,   g_FW);

    cudaFuncSetAttribute(lstm_fused_tc, cudaFuncAttributeMaxDynamicSharedMemorySize,
                         FUSED_SMEM);

    // conversions: all fp16, permuted gate-interleaved for recurrence+proj0
    convert_f16<<<(256 * K0P + 255) / 256, 256>>>(W_ih_l0, Dsz, K0P, 256 * K0P, 1, W0);
    convert_f16<<<(256 * 64 + 255) / 256, 256>>>(W_hh_l0, Hsz, 64, 256 * 64, 1, WR0);
    convert_f16<<<(256 * 64 + 255) / 256, 256>>>(W_ih_l1, Hsz, 64, 256 * 64, 1, WI1);
    convert_f16<<<(256 * 64 + 255) / 256, 256>>>(W_hh_l1, Hsz, 64, 256 * 64, 1, WH1);
    convert_f16<<<(128 * FCK + 255) / 256, 256>>>(fc1_w, FCK, FCK, 128 * FCK, 0, FW);
    combine_bias<<<1, 256>>>(b_ih_l0, b_hh_l0, B0);
    combine_bias<<<1, 256>>>(b_ih_l1, b_hh_l1, B1);

    // layer-0 input projection (fp16 -> fp16 XG): XG = [x1;x2] @ W0^T + B0
    gemm_f16<0, __half><<<dim3(M2 / 128, 2, 1), 256>>>(
        x1, x2, BT, Dsz, K0P / 16, W0, K0P, B0, XG, 256, 0);

    // fused 2-layer recurrence (skewed, 512 thr) -> relu(FEAT) fp16
    lstm_fused_tc<<<128, 512, FUSED_SMEM>>>(XG, WR0, WI1, WH1, B1, FEAT);

    // FC1: fp16 split-K x8, then reduce(+bias,+relu)
    gemm_f16<1, float><<<dim3(Bsz / 128, 1, FSPLIT), 256>>>(
        FEAT, FEAT, 1 << 30, FCK, FSTEPS, FW, FCK, nullptr,
        FC1P, 128, (size_t)Bsz * 128);
    fc1_reduce<<<(Bsz * 128) / 256, 256>>>(FC1P, fc1_b, FC1R);

    // FC2 + deterministic norm + scale
    fc2_norm<<<240, 256>>>(FC1R, fc2_w, fc2_b, out, PART);
    reduce_norm<<<1, 256>>>(PART, INV);
    scale_out<<<240, 256>>>(out, INV);
}

// round 12
// speedup vs baseline: 6.6310x; 1.1391x over previous
#include <cuda_runtime.h>
#include <cuda_fp16.h>
#include <cstdint>
#include <cstddef>

#define Bsz 4096
#define Tsz 60
#define Dsz 200
#define K0P 208             // Dsz padded to multiple of 16
#define Hsz 64
#define G4  256
#define BT  (Bsz*Tsz)       // 245760
#define M2  (2*BT)          // 491520
#define FCK (2*Tsz*Hsz)     // 7680
#define FSPLIT 8
#define FSTEPS (FCK/FSPLIT/16)  // 60 k-steps per split

// fused-lstm smem layout (bytes); 144B-padded rows (conflict-free ldmatrix)
#define OW0  0              // Whh0 fp16 256x144
#define OWI  36864          // Wih1
#define OWH  73728          // Whh1
#define OH0H 110592         // h0 hi 64x144
#define OH0L 119808         // h0 lo
#define OH1H 129024         // h1 hi
#define OH1L 138240         // h1 lo
#define OXG0 147456         // xg buf0: 64x256 fp16 (32768 B)
#define OXG1 180224         // xg buf1
#define OB1  212992         // bias1 (permuted) 256 f32
#define FUSED_SMEM 214016

// gate permutation: col(j,gate) = (j>>2)*16 + (gate>>1)*8 + (j&3)*2 + (gate&1)
// inverse: for permuted col p: gate = 2*((p>>3)&1) + (p&1),
//          j = (p>>4)*4 + ((p>>1)&3),  n_in = gate*64 + j

// ---------------- scratch (device globals: allocation-free) ----------------
__device__ __half g_XG[(size_t)M2 * G4];
__device__ __half g_FEAT[(size_t)Bsz * FCK];
__device__ float g_FC1P[(size_t)FSPLIT * Bsz * 128];
__device__ float g_FC1R[(size_t)Bsz * 128];
__device__ float g_PART[240];
__device__ float g_INV[1];
__device__ __half g_W0[256 * K0P];   // permuted W_ih0 fp16 (zero-padded K)
__device__ __half g_WR0[256 * 64];   // permuted Whh0
__device__ __half g_WI1[256 * 64];   // permuted Wih1
__device__ __half g_WH1[256 * 64];   // permuted Whh1
__device__ __half g_FW[(size_t)128 * FCK];  // fc1_w fp16
__device__ float g_B0[256];
__device__ float g_B1[256];

// ---------------- activations ----------------
__device__ __forceinline__ float tanh_fast(float x) {
    float y;
    asm("tanh.approx.f32 %0, %1;" : "=f"(y) : "f"(x));
    return y;
}
__device__ __forceinline__ float sig_fast(float x) {
    return fmaf(tanh_fast(0.5f * x), 0.5f, 0.5f);
}

// ---------------- mma/ldmatrix helpers (baseline PTX) ----------------
__device__ __forceinline__ uint32_t smem_u32(const void* p) {
    uint32_t a;
    asm("{ .reg .u64 t; cvta.to.shared.u64 t, %1; cvt.u32.u64 %0, t; }" : "=r"(a) : "l"(p));
    return a;
}
#define LDSM_X4(r, addr) \
    asm volatile("ldmatrix.sync.aligned.m8n8.x4.shared.b16 {%0,%1,%2,%3}, [%4];" \
        : "=r"((r)[0]), "=r"((r)[1]), "=r"((r)[2]), "=r"((r)[3]) : "r"(addr))
#define LDSM_X2(r, addr) \
    asm volatile("ldmatrix.sync.aligned.m8n8.x2.shared.b16 {%0,%1}, [%2];" \
        : "=r"((r)[0]), "=r"((r)[1]) : "r"(addr))

__device__ __forceinline__ void mma_f16(float* c, const uint32_t* a, const uint32_t* b) {
    asm volatile(
        "mma.sync.aligned.m16n8k16.row.col.f32.f16.f16.f32 "
        "{%0,%1,%2,%3}, {%4,%5,%6,%7}, {%8,%9}, {%0,%1,%2,%3};"
        : "+f"(c[0]), "+f"(c[1]), "+f"(c[2]), "+f"(c[3])
        : "r"(a[0]), "r"(a[1]), "r"(a[2]), "r"(a[3]), "r"(b[0]), "r"(b[1]));
}

__device__ __forceinline__ void cp16(uint32_t dst, const void* src) {
    asm volatile("cp.async.cg.shared.global [%0], [%1], 16;" :: "r"(dst), "l"(src));
}
#define CP_COMMIT() asm volatile("cp.async.commit_group;" ::: "memory")
#define CP_WAIT1()  asm volatile("cp.async.wait_group 1;" ::: "memory")

// ---------------- conversions ----------------
// perm: output row p corresponds to input row gate*64+j (see mapping above)
__global__ void convert_f16(const float* __restrict__ W, int K, int ldwp, int total,
                            int perm, __half* __restrict__ o)
{
    int idx = blockIdx.x * 256 + threadIdx.x;
    if (idx >= total) return;
    int n = idx / ldwp, k = idx - n * ldwp;
    int n_in = n;
    if (perm) {
        int gate = 2 * ((n >> 3) & 1) + (n & 1);
        int j = (n >> 4) * 4 + ((n >> 1) & 3);
        n_in = gate * 64 + j;
    }
    float v = (k < K) ? W[n_in * K + k] : 0.f;
    o[idx] = __float2half_rn(v);
}
__global__ void combine_bias(const float* a, const float* b, float* o) {
    int i = threadIdx.x;
    int gate = 2 * ((i >> 3) & 1) + (i & 1);
    int j = (i >> 4) * 4 + ((i >> 1) & 3);
    int n_in = gate * 64 + j;
    o[i] = a[n_in] + b[n_in];
}

// ---------------- fp16 tensor-core GEMM: C = A[M,K] * W[N,K]^T (+bias) ------
// R10-proven. CTA 128x128, 8 warps. fp16 single operands, fp32 accum.
template<int AHALF, typename OutT>
__global__ void __launch_bounds__(256) gemm_f16(
    const void* __restrict__ A0v, const void* __restrict__ A1v, int rowsplit,
    int lda, int nch,
    const __half* __restrict__ W, int ldw, const float* __restrict__ bias,
    OutT* __restrict__ C, int ldc, size_t csplit)
{
    __shared__ __align__(16) uint32_t sm[6144];   // 24 KB
    const uint32_t sb = smem_u32(sm);

    const int tid  = threadIdx.x;
    const int lane = tid & 31;
    const int wid  = tid >> 5;
    const int warpM = wid >> 2;
    const int warpN = wid & 3;
    const int row0 = blockIdx.x * 128;
    const int col0 = blockIdx.y * 128;

    const size_t elt = AHALF ? 2 : 4;
    const char* Ab = (const char*)((row0 < rowsplit) ? A0v : A1v)
        + (size_t)((row0 < rowsplit) ? row0 : row0 - rowsplit) * lda * elt;

    const uint32_t laneA = (uint32_t)((((lane >> 3) & 1) * 8 + (lane & 7)) * 48
                                      + (lane >> 4) * 16);
    const uint32_t laneB = (uint32_t)((lane & 7) * 48 + ((lane >> 3) & 1) * 16);
    const uint32_t aBase = sb + (uint32_t)(warpM * 64) * 48 + laneA;
    const uint32_t bBase = sb + 6144u + (uint32_t)(warpN * 32) * 48 + laneB;

    float acc[4][4][4];
#pragma unroll
    for (int mt = 0; mt < 4; mt++)
#pragma unroll
        for (int nt = 0; nt < 4; nt++)
#pragma unroll
            for (int e = 0; e < 4; e++) acc[mt][nt][e] = 0.f;

    uint32_t areg[4], wreg[4];
    auto ldg_step = [&](int k0) {
#pragma unroll
        for (int i = 0; i < 4; i++) {
            int idx = tid + 256 * i;
            int r = idx >> 3, cp = idx & 7;
            int k = k0 + 2 * cp;
            if (AHALF) {
                areg[i] = (k + 2 <= lda)
                    ? *reinterpret_cast<const uint32_t*>(
                        Ab + ((size_t)r * lda + k) * 2)
                    : 0u;
            } else {
                if (k + 2 <= lda) {
                    float2 f = *reinterpret_cast<const float2*>(
                        Ab + ((size_t)r * lda + k) * 4);
                    __half2 hh = __floats2half2_rn(f.x, f.y);
                    areg[i] = *reinterpret_cast<uint32_t*>(&hh);
                } else {
                    areg[i] = 0u;
                }
            }
            wreg[i] = *reinterpret_cast<const uint32_t*>(
                W + (size_t)(col0 + r) * ldw + k0 + 2 * cp);
        }
    };
    auto sts_step = [&](int buf) {
        char* base = reinterpret_cast<char*>(sm) + buf * 12288;
#pragma unroll
        for (int i = 0; i < 4; i++) {
            int idx = tid + 256 * i;
            int r = idx >> 3, cp = idx & 7;
            *reinterpret_cast<uint32_t*>(base + r * 48 + cp * 4) = areg[i];
            *reinterpret_cast<uint32_t*>(base + 6144 + r * 48 + cp * 4) = wreg[i];
        }
    };

    ldg_step(blockIdx.z * nch * 16);
    sts_step(0);
    __syncthreads();

    int buf = 0;
    for (int s = 0;; s++) {
        const bool more = (s + 1) < nch;
        if (more) ldg_step((blockIdx.z * nch + s + 1) * 16);

        uint32_t af[4][4], bf[4][2];
        uint32_t aOff = aBase + buf * 12288u;
        uint32_t bOff = bBase + buf * 12288u;
#pragma unroll
        for (int mt = 0; mt < 4; mt++) LDSM_X4(af[mt], aOff + mt * 768u);
#pragma unroll
        for (int nt = 0; nt < 4; nt++) LDSM_X2(bf[nt], bOff + nt * 384u);
#pragma unroll
        for (int mt = 0; mt < 4; mt++)
#pragma unroll
            for (int nt = 0; nt < 4; nt++)
                mma_f16(acc[mt][nt], af[mt], bf[nt]);

        if (!more) break;
        sts_step(buf ^ 1);
        __syncthreads();
        buf ^= 1;
    }

    OutT* Cb = C + (size_t)blockIdx.z * csplit;
    const int gid = lane >> 2;
    const int tig = lane & 3;
#pragma unroll
    for (int mt = 0; mt < 4; mt++) {
        int r = row0 + warpM * 64 + mt * 16 + gid;
#pragma unroll
        for (int nt = 0; nt < 4; nt++) {
            int cc = col0 + warpN * 32 + nt * 8 + 2 * tig;
            float b0 = bias ? bias[cc] : 0.f;
            float b1 = bias ? bias[cc + 1] : 0.f;
            float v00 = acc[mt][nt][0] + b0, v01 = acc[mt][nt][1] + b1;
            float v10 = acc[mt][nt][2] + b0, v11 = acc[mt][nt][3] + b1;
            if (sizeof(OutT) == 2) {
                __half2 h0 = __floats2half2_rn(v00, v01);
                __half2 h1 = __floats2half2_rn(v10, v11);
                *reinterpret_cast<__half2*>((__half*)Cb + (size_t)r * ldc + cc) = h0;
                *reinterpret_cast<__half2*>((__half*)Cb + (size_t)(r + 8) * ldc + cc) = h1;
            } else {
                *reinterpret_cast<float2*>((float*)Cb + (size_t)r * ldc + cc)
                    = make_float2(v00, v01);
                *reinterpret_cast<float2*>((float*)Cb + (size_t)(r + 8) * ldc + cc)
                    = make_float2(v10, v11);
            }
        }
    }
}

// ---------------- fused 2-layer tensor-core LSTM (fp16, skewed, no-shfl) ----
// 64 batch rows/CTA, 512 threads (16 warps: warpM=wid&3 rows, warpN=wid>>2 64
// gate cols). Gate permutation col(j,g) = (j>>2)*16 + (g>>1)*8 + (j&3)*2 + (g&1)
// puts i,f in even tiles and g,o in odd tiles of the SAME thread: no shfl/selects.
// One-step skew, 2 barriers/step, xg double-buffered cp.async.
__global__ void __launch_bounds__(512, 1) lstm_fused_tc(
    const __half* __restrict__ XG,      // [8192*T, 256] permuted cols, B0 folded
    const __half* __restrict__ W0,      // permuted Whh0 [256][64]
    const __half* __restrict__ Wi1,     // permuted Wih1
    const __half* __restrict__ Wh1,     // permuted Whh1
    const float* __restrict__ B1,       // permuted bias1
    __half* __restrict__ FEAT)
{
    extern __shared__ char smem[];
    const uint32_t sb = smem_u32(smem);
    const int tid = threadIdx.x;
    const int lane = tid & 31;
    const int wid = tid >> 5;
    const int warpM = wid & 3;          // 16 rows
    const int warpN = wid >> 2;         // 0..3, 64 gate cols
    const int row0 = blockIdx.x * 64;

    // ---- stage weights (144B rows), zero h, load bias ----
    {
        const uint32_t* w0 = reinterpret_cast<const uint32_t*>(W0);
        const uint32_t* wi = reinterpret_cast<const uint32_t*>(Wi1);
        const uint32_t* wh = reinterpret_cast<const uint32_t*>(Wh1);
#pragma unroll
        for (int i = 0; i < 16; i++) {
            int idx = tid + 512 * i;          // 8192 u32
            int r = idx >> 5, c = idx & 31;
            *reinterpret_cast<uint32_t*>(smem + OW0 + r * 144 + c * 4) = w0[idx];
            *reinterpret_cast<uint32_t*>(smem + OWI + r * 144 + c * 4) = wi[idx];
            *reinterpret_cast<uint32_t*>(smem + OWH + r * 144 + c * 4) = wh[idx];
        }
#pragma unroll
        for (int i = 0; i < 5; i++) {
            int idx = tid + 512 * i;          // 2304 u32 per region
            if (idx < 2304) {
                *reinterpret_cast<uint32_t*>(smem + OH0H + idx * 4) = 0;
                *reinterpret_cast<uint32_t*>(smem + OH0L + idx * 4) = 0;
                *reinterpret_cast<uint32_t*>(smem + OH1H + idx * 4) = 0;
                *reinterpret_cast<uint32_t*>(smem + OH1L + idx * 4) = 0;
            }
        }
        if (tid < 256) reinterpret_cast<float*>(smem + OB1)[tid] = B1[tid];
    }

    // prologue: prefetch xg(0) into buf0 (2048 16B chunks)
#pragma unroll
    for (int i = 0; i < 4; i++) {
        int idx = tid + 512 * i;
        int r = idx >> 5, ch = idx & 31;
        cp16(sb + OXG0 + r * 512 + ch * 16,
             XG + ((size_t)(row0 + r) * Tsz + 0) * 256 + ch * 8);
    }
    CP_COMMIT();

    const uint32_t aoff = (uint32_t)((warpM * 16 + (lane & 7) + ((lane >> 3) & 1) * 8) * 144
                                     + (lane >> 4) * 16);
    const uint32_t boff = (uint32_t)((warpN * 64 + (lane & 7) + (lane >> 4) * 8) * 144
                                     + ((lane >> 3) & 1) * 16);
    const uint32_t a0h = sb + OH0H + aoff, a0l = sb + OH0L + aoff;
    const uint32_t a1h = sb + OH1H + aoff, a1l = sb + OH1L + aoff;
    const uint32_t bW0 = sb + OW0 + boff, bWi = sb + OWI + boff, bWh = sb + OWH + boff;

    const int gid = lane >> 2;          // 0..7
    const int tig = lane & 3;           // 0..3
    const int rowA = warpM * 16 + gid;  // rows rowA, rowA+8
    const float* b1s = reinterpret_cast<const float*>(smem + OB1);

    const int growA = row0 + rowA;
    const int inp = growA >> 12, bbA = growA & (Bsz - 1);
    __half* featA = FEAT + (size_t)bbA * FCK + (size_t)inp * (Tsz * Hsz);
    __half* featB = FEAT + (size_t)(bbA + 8) * FCK + (size_t)inp * (Tsz * Hsz);

    // c-state: [pair p][row half rh] for each layer
    float c0st[8], c1st[8];
#pragma unroll
    for (int i = 0; i < 8; i++) { c0st[i] = 0.f; c1st[i] = 0.f; }

    __syncthreads();

    for (int m = 0; m <= Tsz; m++) {
        // issue xg(m+1) prefetch into alternate buffer (overlaps the MMAs)
        if (m + 1 < Tsz) {
            uint32_t xdst = sb + (((m + 1) & 1) ? OXG1 : OXG0);
#pragma unroll
            for (int i = 0; i < 4; i++) {
                int idx = tid + 512 * i;
                int r = idx >> 5, ch = idx & 31;
                cp16(xdst + r * 512 + ch * 16,
                     XG + ((size_t)(row0 + r) * Tsz + m + 1) * 256 + ch * 8);
            }
        }
        CP_COMMIT();

        // ---- merged MMA phase (edges compute-and-discard; no divergence) ----
        float acc0[8][4], acc1[8][4];
#pragma unroll
        for (int nt = 0; nt < 8; nt++)
#pragma unroll
            for (int e = 0; e < 4; e++) { acc0[nt][e] = 0.f; acc1[nt][e] = 0.f; }

#pragma unroll
        for (int ks = 0; ks < 4; ks++) {
            uint32_t ah[4], al[4];
            LDSM_X4(ah, a0h + ks * 32);
            LDSM_X4(al, a0l + ks * 32);
#pragma unroll
            for (int np = 0; np < 4; np++) {
                uint32_t bv[4];
                LDSM_X4(bv, bW0 + np * 2304 + ks * 32);
                mma_f16(acc0[2 * np],     ah, bv);
                mma_f16(acc0[2 * np],     al, bv);
                mma_f16(acc0[2 * np + 1], ah, bv + 2);
                mma_f16(acc0[2 * np + 1], al, bv + 2);
                uint32_t bw[4];
                LDSM_X4(bw, bWi + np * 2304 + ks * 32);
                mma_f16(acc1[2 * np],     ah, bw);
                mma_f16(acc1[2 * np],     al, bw);
                mma_f16(acc1[2 * np + 1], ah, bw + 2);
                mma_f16(acc1[2 * np + 1], al, bw + 2);
            }
        }
#pragma unroll
        for (int ks = 0; ks < 4; ks++) {
            uint32_t ah[4], al[4];
            LDSM_X4(ah, a1h + ks * 32);
            LDSM_X4(al, a1l + ks * 32);
#pragma unroll
            for (int np = 0; np < 4; np++) {
                uint32_t bv[4];
                LDSM_X4(bv, bWh + np * 2304 + ks * 32);
                mma_f16(acc1[2 * np],     ah, bv);
                mma_f16(acc1[2 * np],     al, bv);
                mma_f16(acc1[2 * np + 1], ah, bv + 2);
                mma_f16(acc1[2 * np + 1], al, bv + 2);
            }
        }

        CP_WAIT1();          // xg(m) resident (newest group may be in flight)
        __syncthreads();

        // ---- ACT phase (no shfl: i,f in acc[2p], g,o in acc[2p+1]) ----
        if (m < Tsz) {
            const __half* xbuf = reinterpret_cast<const __half*>(
                smem + ((m & 1) ? OXG1 : OXG0));
#pragma unroll
            for (int p = 0; p < 4; p++) {
                int colb = warpN * 64 + p * 16 + 2 * tig;
                int j = warpN * 16 + p * 4 + tig;
#pragma unroll
                for (int rh = 0; rh < 2; rh++) {
                    int row = rowA + rh * 8;
                    int e = 2 * rh;
                    float2 xif = __half22float2(*reinterpret_cast<const __half2*>(
                        xbuf + row * 256 + colb));
                    float2 xgo = __half22float2(*reinterpret_cast<const __half2*>(
                        xbuf + row * 256 + colb + 8));
                    float gi = acc0[2 * p][e]     + xif.x;
                    float gf = acc0[2 * p][e + 1] + xif.y;
                    float gg = acc0[2 * p + 1][e]     + xgo.x;
                    float go = acc0[2 * p + 1][e + 1] + xgo.y;
                    float& c = c0st[2 * p + rh];
                    c = sig_fast(gf) * c + sig_fast(gi) * tanh_fast(gg);
                    float h = sig_fast(go) * tanh_fast(c);
                    __half hh = __float2half_rn(h);
                    float lo = h - __half2float(hh);
                    *reinterpret_cast<unsigned short*>(smem + OH0H + row * 144 + j * 2)
                        = __half_as_ushort(hh);
                    *reinterpret_cast<unsigned short*>(smem + OH0L + row * 144 + j * 2)
                        = __half_as_ushort(__float2half_rn(lo));
                }
            }
        }
        if (m >= 1) {
#pragma unroll
            for (int p = 0; p < 4; p++) {
                int colb = warpN * 64 + p * 16 + 2 * tig;
                int j = warpN * 16 + p * 4 + tig;
                float2 bif = *reinterpret_cast<const float2*>(b1s + colb);
                float2 bgo = *reinterpret_cast<const float2*>(b1s + colb + 8);
#pragma unroll
                for (int rh = 0; rh < 2; rh++) {
                    int row = rowA + rh * 8;
                    int e = 2 * rh;
                    float gi = acc1[2 * p][e]     + bif.x;
                    float gf = acc1[2 * p][e + 1] + bif.y;
                    float gg = acc1[2 * p + 1][e]     + bgo.x;
                    float go = acc1[2 * p + 1][e + 1] + bgo.y;
                    float& c = c1st[2 * p + rh];
                    c = sig_fast(gf) * c + sig_fast(gi) * tanh_fast(gg);
                    float h = sig_fast(go) * tanh_fast(c);
                    __half hh = __float2half_rn(h);
                    float lo = h - __half2float(hh);
                    *reinterpret_cast<unsigned short*>(smem + OH1H + row * 144 + j * 2)
                        = __half_as_ushort(hh);
                    *reinterpret_cast<unsigned short*>(smem + OH1L + row * 144 + j * 2)
                        = __half_as_ushort(__float2half_rn(lo));
                    __half* fp = rh ? featB : featA;
                    fp[(size_t)(m - 1) * Hsz + j] = __float2half_rn(fmaxf(h, 0.f));
                }
            }
        }
        __syncthreads();
    }
}

// ---------------- FC1 split-K reduction (+bias, +relu) ----------------
__global__ void __launch_bounds__(256) fc1_reduce(
    const float* __restrict__ part, const float* __restrict__ bias,
    float* __restrict__ outp)
{
    const size_t S = (size_t)Bsz * 128;
    size_t i = (size_t)blockIdx.x * 256 + threadIdx.x;
    int n = (int)(i & 127);
    float s = bias[n];
#pragma unroll
    for (int z = 0; z < FSPLIT; z++) s += part[i + z * S];
    outp[i] = fmaxf(s, 0.f);
}

// ---------------- FC2 + partial sum-of-squares ----------------
__global__ void __launch_bounds__(256) fc2_norm(
    const float* __restrict__ fc1, const float* __restrict__ w,
    const float* __restrict__ bias, float* __restrict__ out,
    float* __restrict__ partial)
{
    __shared__ float sw[15 * 132];
    __shared__ float red[256];
    const int tid = threadIdx.x;
    for (int i = tid; i < 15 * 128; i += 256) {
        int n = i >> 7, k = i & 127;
        sw[n * 132 + k] = w[i];
    }
    __syncthreads();

    int idx = blockIdx.x * 256 + tid;
    int b = idx / 15, n = idx - b * 15;
    const float4* fr = reinterpret_cast<const float4*>(fc1 + (size_t)b * 128);
    const float4* wn = reinterpret_cast<const float4*>(sw + n * 132);
    float acc = bias[n];
#pragma unroll
    for (int k = 0; k < 32; k++) {
        float4 f4 = fr[k];
        float4 w4 = wn[k];
        acc = fmaf(f4.x, w4.x, acc);
        acc = fmaf(f4.y, w4.y, acc);
        acc = fmaf(f4.z, w4.z, acc);
        acc = fmaf(f4.w, w4.w, acc);
    }
    out[idx] = acc;
    red[tid] = acc * acc;
    __syncthreads();
#pragma unroll
    for (int s = 128; s > 0; s >>= 1) {
        if (tid < s) red[tid] += red[tid + s];
        __syncthreads();
    }
    if (tid == 0) partial[blockIdx.x] = red[0];
}

__global__ void reduce_norm(const float* __restrict__ partial, float* __restrict__ inv)
{
    __shared__ float red[256];
    float s = 0.f;
    for (int i = threadIdx.x; i < 240; i += 256) s += partial[i];
    red[threadIdx.x] = s;
    __syncthreads();
#pragma unroll
    for (int st = 128; st > 0; st >>= 1) {
        if (threadIdx.x < st) red[threadIdx.x] += red[threadIdx.x + st];
        __syncthreads();
    }
    if (threadIdx.x == 0) inv[0] = 1.0f / sqrtf(red[0]);
}

__global__ void scale_out(float* __restrict__ out, const float* __restrict__ inv)
{
    int i = blockIdx.x * 256 + threadIdx.x;
    out[i] *= inv[0];
}

// ---------------- launch ----------------
extern "C" void kernel_launch(void* const* d_in, const int* in_sizes, int n_in,
                              void* d_out, int out_size)
{
    const float* x1      = (const float*)d_in[0];
    const float* x2      = (const float*)d_in[1];
    const float* W_ih_l0 = (const float*)d_in[2];
    const float* W_hh_l0 = (const float*)d_in[3];
    const float* b_ih_l0 = (const float*)d_in[4];
    const float* b_hh_l0 = (const float*)d_in[5];
    const float* W_ih_l1 = (const float*)d_in[6];
    const float* W_hh_l1 = (const float*)d_in[7];
    const float* b_ih_l1 = (const float*)d_in[8];
    const float* b_hh_l1 = (const float*)d_in[9];
    const float* fc1_w   = (const float*)d_in[10];
    const float* fc1_b   = (const float*)d_in[11];
    const float* fc2_w   = (const float*)d_in[12];
    const float* fc2_b   = (const float*)d_in[13];
    float* out = (float*)d_out;

    float *FC1P, *FC1R, *PART, *INV, *B0, *B1;
    __half *XG, *FEAT, *W0, *WR0, *WI1, *WH1, *FW;
    cudaGetSymbolAddress((void**)&XG,   g_XG);
    cudaGetSymbolAddress((void**)&FEAT, g_FEAT);
    cudaGetSymbolAddress((void**)&FC1P, g_FC1P);
    cudaGetSymbolAddress((void**)&FC1R, g_FC1R);
    cudaGetSymbolAddress((void**)&PART, g_PART);
    cudaGetSymbolAddress((void**)&INV,  g_INV);
    cudaGetSymbolAddress((void**)&B0,   g_B0);
    cudaGetSymbolAddress((void**)&B1,   g_B1);
    cudaGetSymbolAddress((void**)&W0,   g_W0);
    cudaGetSymbolAddress((void**)&WR0,  g_WR0);
    cudaGetSymbolAddress((void**)&WI1,  g_WI1);
    cudaGetSymbolAddress((void**)&WH1,  g_WH1);
    cudaGetSymbolAddress((void**)&FW,   g_FW);

    cudaFuncSetAttribute(lstm_fused_tc, cudaFuncAttributeMaxDynamicSharedMemorySize,
                         FUSED_SMEM);

    // conversions: all fp16, gate-permuted for recurrence+proj0
    convert_f16<<<(256 * K0P + 255) / 256, 256>>>(W_ih_l0, Dsz, K0P, 256 * K0P, 1, W0);
    convert_f16<<<(256 * 64 + 255) / 256, 256>>>(W_hh_l0, Hsz, 64, 256 * 64, 1, WR0);
    convert_f16<<<(256 * 64 + 255) / 256, 256>>>(W_ih_l1, Hsz, 64, 256 * 64, 1, WI1);
    convert_f16<<<(256 * 64 + 255) / 256, 256>>>(W_hh_l1, Hsz, 64, 256 * 64, 1, WH1);
    convert_f16<<<(128 * FCK + 255) / 256, 256>>>(fc1_w, FCK, FCK, 128 * FCK, 0, FW);
    combine_bias<<<1, 256>>>(b_ih_l0, b_hh_l0, B0);
    combine_bias<<<1, 256>>>(b_ih_l1, b_hh_l1, B1);

    // layer-0 input projection (fp16 -> fp16 XG): XG = [x1;x2] @ W0^T + B0
    gemm_f16<0, __half><<<dim3(M2 / 128, 2, 1), 256>>>(
        x1, x2, BT, Dsz, K0P / 16, W0, K0P, B0, XG, 256, 0);

    // fused 2-layer recurrence (skewed, 512 thr, no-shfl) -> relu(FEAT) fp16
    lstm_fused_tc<<<128, 512, FUSED_SMEM>>>(XG, WR0, WI1, WH1, B1, FEAT);

    // FC1: fp16 split-K x8, then reduce(+bias,+relu)
    gemm_f16<1, float><<<dim3(Bsz / 128, 1, FSPLIT), 256>>>(
        FEAT, FEAT, 1 << 30, FCK, FSTEPS, FW, FCK, nullptr,
        FC1P, 128, (size_t)Bsz * 128);
    fc1_reduce<<<(Bsz * 128) / 256, 256>>>(FC1P, fc1_b, FC1R);

    // FC2 + deterministic norm + scale
    fc2_norm<<<240, 256>>>(FC1R, fc2_w, fc2_b, out, PART);
    reduce_norm<<<1, 256>>>(PART, INV);
    scale_out<<<240, 256>>>(out, INV);
}

// round 13
// speedup vs baseline: 7.4500x; 1.1235x over previous
#include <cuda_runtime.h>
#include <cuda_fp16.h>
#include <cstdint>
#include <cstddef>

#define Bsz 4096
#define Tsz 60
#define Dsz 200
#define K0P 208             // Dsz padded to multiple of 16
#define Hsz 64
#define G4  256
#define BT  (Bsz*Tsz)       // 245760
#define M2  (2*BT)          // 491520
#define FCK (2*Tsz*Hsz)     // 7680
#define FSPLIT 8
#define FSTEPS (FCK/FSPLIT/16)  // 60 k-steps per split

// fused-lstm smem layout (bytes); 144B-padded rows (conflict-free ldmatrix)
#define OW0  0              // Whh0 fp16 256x144
#define OWI  36864          // Wih1
#define OWH  73728          // Whh1
#define OH0H 110592         // h0 (fp16 single) 64x144
#define OH1H 119808         // h1
#define OXG0 129024         // xg buf0: 64x256 fp16 (32768 B)
#define OXG1 161792         // xg buf1
#define OB1  194560         // bias1 (permuted) 256 f32
#define FUSED_SMEM 195584

// gate permutation: col(j,gate) = (j>>2)*16 + (gate>>1)*8 + (j&3)*2 + (gate&1)
// inverse: gate = 2*((p>>3)&1) + (p&1), j = (p>>4)*4 + ((p>>1)&3)

// ---------------- scratch (device globals: allocation-free) ----------------
__device__ __half g_XG[(size_t)M2 * G4];
__device__ __half g_FEAT[(size_t)Bsz * FCK];
__device__ float g_FC1P[(size_t)FSPLIT * Bsz * 128];
__device__ float g_FC1R[(size_t)Bsz * 128];
__device__ float g_PART[240];
__device__ float g_INV[1];
__device__ __half g_W0[256 * K0P];   // permuted W_ih0 fp16 (zero-padded K)
__device__ __half g_WR0[256 * 64];   // permuted Whh0
__device__ __half g_WI1[256 * 64];   // permuted Wih1
__device__ __half g_WH1[256 * 64];   // permuted Whh1
__device__ __half g_FW[(size_t)128 * FCK];  // fc1_w fp16
__device__ float g_B0[256];
__device__ float g_B1[256];

// ---------------- activations ----------------
__device__ __forceinline__ float tanh_fast(float x) {
    float y;
    asm("tanh.approx.f32 %0, %1;" : "=f"(y) : "f"(x));
    return y;
}
__device__ __forceinline__ float sig_fast(float x) {
    return fmaf(tanh_fast(0.5f * x), 0.5f, 0.5f);
}

// ---------------- mma/ldmatrix helpers (baseline PTX) ----------------
__device__ __forceinline__ uint32_t smem_u32(const void* p) {
    uint32_t a;
    asm("{ .reg .u64 t; cvta.to.shared.u64 t, %1; cvt.u32.u64 %0, t; }" : "=r"(a) : "l"(p));
    return a;
}
#define LDSM_X4(r, addr) \
    asm volatile("ldmatrix.sync.aligned.m8n8.x4.shared.b16 {%0,%1,%2,%3}, [%4];" \
        : "=r"((r)[0]), "=r"((r)[1]), "=r"((r)[2]), "=r"((r)[3]) : "r"(addr))
#define LDSM_X2(r, addr) \
    asm volatile("ldmatrix.sync.aligned.m8n8.x2.shared.b16 {%0,%1}, [%2];" \
        : "=r"((r)[0]), "=r"((r)[1]) : "r"(addr))

__device__ __forceinline__ void mma_f16(float* c, const uint32_t* a, const uint32_t* b) {
    asm volatile(
        "mma.sync.aligned.m16n8k16.row.col.f32.f16.f16.f32 "
        "{%0,%1,%2,%3}, {%4,%5,%6,%7}, {%8,%9}, {%0,%1,%2,%3};"
        : "+f"(c[0]), "+f"(c[1]), "+f"(c[2]), "+f"(c[3])
        : "r"(a[0]), "r"(a[1]), "r"(a[2]), "r"(a[3]), "r"(b[0]), "r"(b[1]));
}

__device__ __forceinline__ void cp16(uint32_t dst, const void* src) {
    asm volatile("cp.async.cg.shared.global [%0], [%1], 16;" :: "r"(dst), "l"(src));
}
#define CP_COMMIT() asm volatile("cp.async.commit_group;" ::: "memory")
#define CP_WAIT1()  asm volatile("cp.async.wait_group 1;" ::: "memory")

// ---------------- merged conversion (one launch) ----------------
// segments: [0,S0) W0 perm K=200 ldwp=K0P; [S0,S1) WR0; [S1,S2) WI1;
// [S2,S3) WH1 (perm K=64); [S3,S4) FW (no perm, K=FCK); [S4,S5) B0; [S5,S6) B1
#define SEG0 (256*K0P)
#define SEG1 (SEG0 + 256*64)
#define SEG2 (SEG1 + 256*64)
#define SEG3 (SEG2 + 256*64)
#define SEG4 (SEG3 + 128*FCK)
#define SEG5 (SEG4 + 256)
#define SEG6 (SEG5 + 256)

__device__ __forceinline__ int gate_perm_row(int n) {
    int gate = 2 * ((n >> 3) & 1) + (n & 1);
    int j = (n >> 4) * 4 + ((n >> 1) & 3);
    return gate * 64 + j;
}

__global__ void convert_all(
    const float* __restrict__ Wih0, const float* __restrict__ Whh0,
    const float* __restrict__ Wih1, const float* __restrict__ Whh1,
    const float* __restrict__ fc1w,
    const float* __restrict__ bih0, const float* __restrict__ bhh0,
    const float* __restrict__ bih1, const float* __restrict__ bhh1,
    __half* __restrict__ W0, __half* __restrict__ WR0,
    __half* __restrict__ WI1, __half* __restrict__ WH1,
    __half* __restrict__ FW, float* __restrict__ B0, float* __restrict__ B1)
{
    int idx = blockIdx.x * 256 + threadIdx.x;
    if (idx < SEG0) {
        int n = idx / K0P, k = idx - n * K0P;
        float v = (k < Dsz) ? Wih0[gate_perm_row(n) * Dsz + k] : 0.f;
        W0[idx] = __float2half_rn(v);
    } else if (idx < SEG3) {
        int r = idx - SEG0;
        const float* src; __half* dst;
        if (r < 16384)      { src = Whh0; dst = WR0; }
        else if (r < 32768) { src = Wih1; dst = WI1; r -= 16384; }
        else                { src = Whh1; dst = WH1; r -= 32768; }
        int n = r >> 6, k = r & 63;
        dst[r] = __float2half_rn(src[gate_perm_row(n) * 64 + k]);
    } else if (idx < SEG4) {
        int r = idx - SEG3;
        FW[r] = __float2half_rn(fc1w[r]);
    } else if (idx < SEG5) {
        int i = idx - SEG4;
        int n_in = gate_perm_row(i);
        B0[i] = bih0[n_in] + bhh0[n_in];
    } else if (idx < SEG6) {
        int i = idx - SEG5;
        int n_in = gate_perm_row(i);
        B1[i] = bih1[n_in] + bhh1[n_in];
    }
}

// ---------------- fp16 tensor-core GEMM: C = A[M,K] * W[N,K]^T (+bias) ------
// R10-proven. CTA 128x128, 8 warps. fp16 single operands, fp32 accum.
template<int AHALF, typename OutT>
__global__ void __launch_bounds__(256) gemm_f16(
    const void* __restrict__ A0v, const void* __restrict__ A1v, int rowsplit,
    int lda, int nch,
    const __half* __restrict__ W, int ldw, const float* __restrict__ bias,
    OutT* __restrict__ C, int ldc, size_t csplit)
{
    __shared__ __align__(16) uint32_t sm[6144];   // 24 KB
    const uint32_t sb = smem_u32(sm);

    const int tid  = threadIdx.x;
    const int lane = tid & 31;
    const int wid  = tid >> 5;
    const int warpM = wid >> 2;
    const int warpN = wid & 3;
    const int row0 = blockIdx.x * 128;
    const int col0 = blockIdx.y * 128;

    const size_t elt = AHALF ? 2 : 4;
    const char* Ab = (const char*)((row0 < rowsplit) ? A0v : A1v)
        + (size_t)((row0 < rowsplit) ? row0 : row0 - rowsplit) * lda * elt;

    const uint32_t laneA = (uint32_t)((((lane >> 3) & 1) * 8 + (lane & 7)) * 48
                                      + (lane >> 4) * 16);
    const uint32_t laneB = (uint32_t)((lane & 7) * 48 + ((lane >> 3) & 1) * 16);
    const uint32_t aBase = sb + (uint32_t)(warpM * 64) * 48 + laneA;
    const uint32_t bBase = sb + 6144u + (uint32_t)(warpN * 32) * 48 + laneB;

    float acc[4][4][4];
#pragma unroll
    for (int mt = 0; mt < 4; mt++)
#pragma unroll
        for (int nt = 0; nt < 4; nt++)
#pragma unroll
            for (int e = 0; e < 4; e++) acc[mt][nt][e] = 0.f;

    uint32_t areg[4], wreg[4];
    auto ldg_step = [&](int k0) {
#pragma unroll
        for (int i = 0; i < 4; i++) {
            int idx = tid + 256 * i;
            int r = idx >> 3, cp = idx & 7;
            int k = k0 + 2 * cp;
            if (AHALF) {
                areg[i] = (k + 2 <= lda)
                    ? *reinterpret_cast<const uint32_t*>(
                        Ab + ((size_t)r * lda + k) * 2)
                    : 0u;
            } else {
                if (k + 2 <= lda) {
                    float2 f = *reinterpret_cast<const float2*>(
                        Ab + ((size_t)r * lda + k) * 4);
                    __half2 hh = __floats2half2_rn(f.x, f.y);
                    areg[i] = *reinterpret_cast<uint32_t*>(&hh);
                } else {
                    areg[i] = 0u;
                }
            }
            wreg[i] = *reinterpret_cast<const uint32_t*>(
                W + (size_t)(col0 + r) * ldw + k0 + 2 * cp);
        }
    };
    auto sts_step = [&](int buf) {
        char* base = reinterpret_cast<char*>(sm) + buf * 12288;
#pragma unroll
        for (int i = 0; i < 4; i++) {
            int idx = tid + 256 * i;
            int r = idx >> 3, cp = idx & 7;
            *reinterpret_cast<uint32_t*>(base + r * 48 + cp * 4) = areg[i];
            *reinterpret_cast<uint32_t*>(base + 6144 + r * 48 + cp * 4) = wreg[i];
        }
    };

    ldg_step(blockIdx.z * nch * 16);
    sts_step(0);
    __syncthreads();

    int buf = 0;
    for (int s = 0;; s++) {
        const bool more = (s + 1) < nch;
        if (more) ldg_step((blockIdx.z * nch + s + 1) * 16);

        uint32_t af[4][4], bf[4][2];
        uint32_t aOff = aBase + buf * 12288u;
        uint32_t bOff = bBase + buf * 12288u;
#pragma unroll
        for (int mt = 0; mt < 4; mt++) LDSM_X4(af[mt], aOff + mt * 768u);
#pragma unroll
        for (int nt = 0; nt < 4; nt++) LDSM_X2(bf[nt], bOff + nt * 384u);
#pragma unroll
        for (int mt = 0; mt < 4; mt++)
#pragma unroll
            for (int nt = 0; nt < 4; nt++)
                mma_f16(acc[mt][nt], af[mt], bf[nt]);

        if (!more) break;
        sts_step(buf ^ 1);
        __syncthreads();
        buf ^= 1;
    }

    OutT* Cb = C + (size_t)blockIdx.z * csplit;
    const int gid = lane >> 2;
    const int tig = lane & 3;
#pragma unroll
    for (int mt = 0; mt < 4; mt++) {
        int r = row0 + warpM * 64 + mt * 16 + gid;
#pragma unroll
        for (int nt = 0; nt < 4; nt++) {
            int cc = col0 + warpN * 32 + nt * 8 + 2 * tig;
            float b0 = bias ? bias[cc] : 0.f;
            float b1 = bias ? bias[cc + 1] : 0.f;
            float v00 = acc[mt][nt][0] + b0, v01 = acc[mt][nt][1] + b1;
            float v10 = acc[mt][nt][2] + b0, v11 = acc[mt][nt][3] + b1;
            if (sizeof(OutT) == 2) {
                __half2 h0 = __floats2half2_rn(v00, v01);
                __half2 h1 = __floats2half2_rn(v10, v11);
                *reinterpret_cast<__half2*>((__half*)Cb + (size_t)r * ldc + cc) = h0;
                *reinterpret_cast<__half2*>((__half*)Cb + (size_t)(r + 8) * ldc + cc) = h1;
            } else {
                *reinterpret_cast<float2*>((float*)Cb + (size_t)r * ldc + cc)
                    = make_float2(v00, v01);
                *reinterpret_cast<float2*>((float*)Cb + (size_t)(r + 8) * ldc + cc)
                    = make_float2(v10, v11);
            }
        }
    }
}

// ---------------- fused 2-layer tensor-core LSTM (fp16, skewed, no-shfl) ----
// 64 batch rows/CTA, 512 threads (16 warps). h fp16 SINGLE (no hi/lo):
// 96 HMMA/warp/step. Gate permutation puts i,f in even tiles and g,o in odd
// tiles of the same thread. One-step skew, 2 barriers/step, xg double-buffered.
__global__ void __launch_bounds__(512, 1) lstm_fused_tc(
    const __half* __restrict__ XG,      // [8192*T, 256] permuted cols, B0 folded
    const __half* __restrict__ W0,      // permuted Whh0 [256][64]
    const __half* __restrict__ Wi1,     // permuted Wih1
    const __half* __restrict__ Wh1,     // permuted Whh1
    const float* __restrict__ B1,       // permuted bias1
    __half* __restrict__ FEAT)
{
    extern __shared__ char smem[];
    const uint32_t sb = smem_u32(smem);
    const int tid = threadIdx.x;
    const int lane = tid & 31;
    const int wid = tid >> 5;
    const int warpM = wid & 3;          // 16 rows
    const int warpN = wid >> 2;         // 0..3, 64 gate cols
    const int row0 = blockIdx.x * 64;

    // ---- stage weights (144B rows), zero h, load bias ----
    {
        const uint32_t* w0 = reinterpret_cast<const uint32_t*>(W0);
        const uint32_t* wi = reinterpret_cast<const uint32_t*>(Wi1);
        const uint32_t* wh = reinterpret_cast<const uint32_t*>(Wh1);
#pragma unroll
        for (int i = 0; i < 16; i++) {
            int idx = tid + 512 * i;          // 8192 u32
            int r = idx >> 5, c = idx & 31;
            *reinterpret_cast<uint32_t*>(smem + OW0 + r * 144 + c * 4) = w0[idx];
            *reinterpret_cast<uint32_t*>(smem + OWI + r * 144 + c * 4) = wi[idx];
            *reinterpret_cast<uint32_t*>(smem + OWH + r * 144 + c * 4) = wh[idx];
        }
#pragma unroll
        for (int i = 0; i < 5; i++) {
            int idx = tid + 512 * i;          // 2304 u32 per region
            if (idx < 2304) {
                *reinterpret_cast<uint32_t*>(smem + OH0H + idx * 4) = 0;
                *reinterpret_cast<uint32_t*>(smem + OH1H + idx * 4) = 0;
            }
        }
        if (tid < 256) reinterpret_cast<float*>(smem + OB1)[tid] = B1[tid];
    }

    // prologue: prefetch xg(0) into buf0 (2048 16B chunks)
#pragma unroll
    for (int i = 0; i < 4; i++) {
        int idx = tid + 512 * i;
        int r = idx >> 5, ch = idx & 31;
        cp16(sb + OXG0 + r * 512 + ch * 16,
             XG + ((size_t)(row0 + r) * Tsz + 0) * 256 + ch * 8);
    }
    CP_COMMIT();

    const uint32_t aoff = (uint32_t)((warpM * 16 + (lane & 7) + ((lane >> 3) & 1) * 8) * 144
                                     + (lane >> 4) * 16);
    const uint32_t boff = (uint32_t)((warpN * 64 + (lane & 7) + (lane >> 4) * 8) * 144
                                     + ((lane >> 3) & 1) * 16);
    const uint32_t a0h = sb + OH0H + aoff;
    const uint32_t a1h = sb + OH1H + aoff;
    const uint32_t bW0 = sb + OW0 + boff, bWi = sb + OWI + boff, bWh = sb + OWH + boff;

    const int gid = lane >> 2;          // 0..7
    const int tig = lane & 3;           // 0..3
    const int rowA = warpM * 16 + gid;  // rows rowA, rowA+8
    const float* b1s = reinterpret_cast<const float*>(smem + OB1);

    const int growA = row0 + rowA;
    const int inp = growA >> 12, bbA = growA & (Bsz - 1);
    __half* featA = FEAT + (size_t)bbA * FCK + (size_t)inp * (Tsz * Hsz);
    __half* featB = FEAT + (size_t)(bbA + 8) * FCK + (size_t)inp * (Tsz * Hsz);

    float c0st[8], c1st[8];
#pragma unroll
    for (int i = 0; i < 8; i++) { c0st[i] = 0.f; c1st[i] = 0.f; }

    __syncthreads();

    for (int m = 0; m <= Tsz; m++) {
        // issue xg(m+1) prefetch into alternate buffer (overlaps the MMAs)
        if (m + 1 < Tsz) {
            uint32_t xdst = sb + (((m + 1) & 1) ? OXG1 : OXG0);
#pragma unroll
            for (int i = 0; i < 4; i++) {
                int idx = tid + 512 * i;
                int r = idx >> 5, ch = idx & 31;
                cp16(xdst + r * 512 + ch * 16,
                     XG + ((size_t)(row0 + r) * Tsz + m + 1) * 256 + ch * 8);
            }
        }
        CP_COMMIT();

        // ---- merged MMA phase (h single fp16) ----
        float acc0[8][4], acc1[8][4];
#pragma unroll
        for (int nt = 0; nt < 8; nt++)
#pragma unroll
            for (int e = 0; e < 4; e++) { acc0[nt][e] = 0.f; acc1[nt][e] = 0.f; }

#pragma unroll
        for (int ks = 0; ks < 4; ks++) {
            uint32_t ah[4];
            LDSM_X4(ah, a0h + ks * 32);
#pragma unroll
            for (int np = 0; np < 4; np++) {
                uint32_t bv[4];
                LDSM_X4(bv, bW0 + np * 2304 + ks * 32);
                mma_f16(acc0[2 * np],     ah, bv);
                mma_f16(acc0[2 * np + 1], ah, bv + 2);
                uint32_t bw[4];
                LDSM_X4(bw, bWi + np * 2304 + ks * 32);
                mma_f16(acc1[2 * np],     ah, bw);
                mma_f16(acc1[2 * np + 1], ah, bw + 2);
            }
        }
        if (m >= 1) {       // h1 == 0 at m==0
#pragma unroll
            for (int ks = 0; ks < 4; ks++) {
                uint32_t ah[4];
                LDSM_X4(ah, a1h + ks * 32);
#pragma unroll
                for (int np = 0; np < 4; np++) {
                    uint32_t bv[4];
                    LDSM_X4(bv, bWh + np * 2304 + ks * 32);
                    mma_f16(acc1[2 * np],     ah, bv);
                    mma_f16(acc1[2 * np + 1], ah, bv + 2);
                }
            }
        }

        CP_WAIT1();          // xg(m) resident (newest group may be in flight)
        __syncthreads();

        // ---- ACT phase (no shfl: i,f in acc[2p], g,o in acc[2p+1]) ----
        if (m < Tsz) {
            const __half* xbuf = reinterpret_cast<const __half*>(
                smem + ((m & 1) ? OXG1 : OXG0));
#pragma unroll
            for (int p = 0; p < 4; p++) {
                int colb = warpN * 64 + p * 16 + 2 * tig;
                int j = warpN * 16 + p * 4 + tig;
#pragma unroll
                for (int rh = 0; rh < 2; rh++) {
                    int row = rowA + rh * 8;
                    int e = 2 * rh;
                    float2 xif = __half22float2(*reinterpret_cast<const __half2*>(
                        xbuf + row * 256 + colb));
                    float2 xgo = __half22float2(*reinterpret_cast<const __half2*>(
                        xbuf + row * 256 + colb + 8));
                    float gi = acc0[2 * p][e]     + xif.x;
                    float gf = acc0[2 * p][e + 1] + xif.y;
                    float gg = acc0[2 * p + 1][e]     + xgo.x;
                    float go = acc0[2 * p + 1][e + 1] + xgo.y;
                    float& c = c0st[2 * p + rh];
                    c = sig_fast(gf) * c + sig_fast(gi) * tanh_fast(gg);
                    float h = sig_fast(go) * tanh_fast(c);
                    *reinterpret_cast<unsigned short*>(smem + OH0H + row * 144 + j * 2)
                        = __half_as_ushort(__float2half_rn(h));
                }
            }
        }
        if (m >= 1) {
#pragma unroll
            for (int p = 0; p < 4; p++) {
                int colb = warpN * 64 + p * 16 + 2 * tig;
                int j = warpN * 16 + p * 4 + tig;
                float2 bif = *reinterpret_cast<const float2*>(b1s + colb);
                float2 bgo = *reinterpret_cast<const float2*>(b1s + colb + 8);
#pragma unroll
                for (int rh = 0; rh < 2; rh++) {
                    int row = rowA + rh * 8;
                    int e = 2 * rh;
                    float gi = acc1[2 * p][e]     + bif.x;
                    float gf = acc1[2 * p][e + 1] + bif.y;
                    float gg = acc1[2 * p + 1][e]     + bgo.x;
                    float go = acc1[2 * p + 1][e + 1] + bgo.y;
                    float& c = c1st[2 * p + rh];
                    c = sig_fast(gf) * c + sig_fast(gi) * tanh_fast(gg);
                    float h = sig_fast(go) * tanh_fast(c);
                    *reinterpret_cast<unsigned short*>(smem + OH1H + row * 144 + j * 2)
                        = __half_as_ushort(__float2half_rn(h));
                    __half* fp = rh ? featB : featA;
                    fp[(size_t)(m - 1) * Hsz + j] = __float2half_rn(fmaxf(h, 0.f));
                }
            }
        }
        __syncthreads();
    }
}

// ---------------- FC1 split-K reduction (+bias, +relu) ----------------
__global__ void __launch_bounds__(256) fc1_reduce(
    const float* __restrict__ part, const float* __restrict__ bias,
    float* __restrict__ outp)
{
    const size_t S = (size_t)Bsz * 128;
    size_t i = (size_t)blockIdx.x * 256 + threadIdx.x;
    int n = (int)(i & 127);
    float s = bias[n];
#pragma unroll
    for (int z = 0; z < FSPLIT; z++) s += part[i + z * S];
    outp[i] = fmaxf(s, 0.f);
}

// ---------------- FC2 + partial sum-of-squares ----------------
__global__ void __launch_bounds__(256) fc2_norm(
    const float* __restrict__ fc1, const float* __restrict__ w,
    const float* __restrict__ bias, float* __restrict__ out,
    float* __restrict__ partial)
{
    __shared__ float sw[15 * 132];
    __shared__ float red[256];
    const int tid = threadIdx.x;
    for (int i = tid; i < 15 * 128; i += 256) {
        int n = i >> 7, k = i & 127;
        sw[n * 132 + k] = w[i];
    }
    __syncthreads();

    int idx = blockIdx.x * 256 + tid;
    int b = idx / 15, n = idx - b * 15;
    const float4* fr = reinterpret_cast<const float4*>(fc1 + (size_t)b * 128);
    const float4* wn = reinterpret_cast<const float4*>(sw + n * 132);
    float acc = bias[n];
#pragma unroll
    for (int k = 0; k < 32; k++) {
        float4 f4 = fr[k];
        float4 w4 = wn[k];
        acc = fmaf(f4.x, w4.x, acc);
        acc = fmaf(f4.y, w4.y, acc);
        acc = fmaf(f4.z, w4.z, acc);
        acc = fmaf(f4.w, w4.w, acc);
    }
    out[idx] = acc;
    red[tid] = acc * acc;
    __syncthreads();
#pragma unroll
    for (int s = 128; s > 0; s >>= 1) {
        if (tid < s) red[tid] += red[tid + s];
        __syncthreads();
    }
    if (tid == 0) partial[blockIdx.x] = red[0];
}

__global__ void reduce_norm(const float* __restrict__ partial, float* __restrict__ inv)
{
    __shared__ float red[256];
    float s = 0.f;
    for (int i = threadIdx.x; i < 240; i += 256) s += partial[i];
    red[threadIdx.x] = s;
    __syncthreads();
#pragma unroll
    for (int st = 128; st > 0; st >>= 1) {
        if (threadIdx.x < st) red[threadIdx.x] += red[threadIdx.x + st];
        __syncthreads();
    }
    if (threadIdx.x == 0) inv[0] = 1.0f / sqrtf(red[0]);
}

__global__ void scale_out(float* __restrict__ out, const float* __restrict__ inv)
{
    int i = blockIdx.x * 256 + threadIdx.x;
    out[i] *= inv[0];
}

// ---------------- launch ----------------
extern "C" void kernel_launch(void* const* d_in, const int* in_sizes, int n_in,
                              void* d_out, int out_size)
{
    const float* x1      = (const float*)d_in[0];
    const float* x2      = (const float*)d_in[1];
    const float* W_ih_l0 = (const float*)d_in[2];
    const float* W_hh_l0 = (const float*)d_in[3];
    const float* b_ih_l0 = (const float*)d_in[4];
    const float* b_hh_l0 = (const float*)d_in[5];
    const float* W_ih_l1 = (const float*)d_in[6];
    const float* W_hh_l1 = (const float*)d_in[7];
    const float* b_ih_l1 = (const float*)d_in[8];
    const float* b_hh_l1 = (const float*)d_in[9];
    const float* fc1_w   = (const float*)d_in[10];
    const float* fc1_b   = (const float*)d_in[11];
    const float* fc2_w   = (const float*)d_in[12];
    const float* fc2_b   = (const float*)d_in[13];
    float* out = (float*)d_out;

    float *FC1P, *FC1R, *PART, *INV, *B0, *B1;
    __half *XG, *FEAT, *W0, *WR0, *WI1, *WH1, *FW;
    cudaGetSymbolAddress((void**)&XG,   g_XG);
    cudaGetSymbolAddress((void**)&FEAT, g_FEAT);
    cudaGetSymbolAddress((void**)&FC1P, g_FC1P);
    cudaGetSymbolAddress((void**)&FC1R, g_FC1R);
    cudaGetSymbolAddress((void**)&PART, g_PART);
    cudaGetSymbolAddress((void**)&INV,  g_INV);
    cudaGetSymbolAddress((void**)&B0,   g_B0);
    cudaGetSymbolAddress((void**)&B1,   g_B1);
    cudaGetSymbolAddress((void**)&W0,   g_W0);
    cudaGetSymbolAddress((void**)&WR0,  g_WR0);
    cudaGetSymbolAddress((void**)&WI1,  g_WI1);
    cudaGetSymbolAddress((void**)&WH1,  g_WH1);
    cudaGetSymbolAddress((void**)&FW,   g_FW);

    cudaFuncSetAttribute(lstm_fused_tc, cudaFuncAttributeMaxDynamicSharedMemorySize,
                         FUSED_SMEM);

    // all weight/bias conversions in ONE launch
    convert_all<<<(SEG6 + 255) / 256, 256>>>(
        W_ih_l0, W_hh_l0, W_ih_l1, W_hh_l1, fc1_w,
        b_ih_l0, b_hh_l0, b_ih_l1, b_hh_l1,
        W0, WR0, WI1, WH1, FW, B0, B1);

    // layer-0 input projection (fp16 -> fp16 XG): XG = [x1;x2] @ W0^T + B0
    gemm_f16<0, __half><<<dim3(M2 / 128, 2, 1), 256>>>(
        x1, x2, BT, Dsz, K0P / 16, W0, K0P, B0, XG, 256, 0);

    // fused 2-layer recurrence (skewed, 512 thr, h fp16 single) -> relu(FEAT)
    lstm_fused_tc<<<128, 512, FUSED_SMEM>>>(XG, WR0, WI1, WH1, B1, FEAT);

    // FC1: fp16 split-K x8, then reduce(+bias,+relu)
    gemm_f16<1, float><<<dim3(Bsz / 128, 1, FSPLIT), 256>>>(
        FEAT, FEAT, 1 << 30, FCK, FSTEPS, FW, FCK, nullptr,
        FC1P, 128, (size_t)Bsz * 128);
    fc1_reduce<<<(Bsz * 128) / 256, 256>>>(FC1P, fc1_b, FC1R);

    // FC2 + deterministic norm + scale
    fc2_norm<<<240, 256>>>(FC1R, fc2_w, fc2_b, out, PART);
    reduce_norm<<<1, 256>>>(PART, INV);
    scale_out<<<240, 256>>>(out, INV);
}

// round 15
// speedup vs baseline: 7.7274x; 1.0372x over previous
#include <cuda_runtime.h>
#include <cuda_fp16.h>
#include <cstdint>
#include <cstddef>

#define Bsz 4096
#define Tsz 60
#define Dsz 200
#define K0P 208             // Dsz padded to multiple of 16
#define Hsz 64
#define G4  256
#define BT  (Bsz*Tsz)       // 245760
#define M2  (2*BT)          // 491520
#define FCK (2*Tsz*Hsz)     // 7680
#define FSPLIT 16
#define FSTEPS (FCK/FSPLIT/16)  // 30 k-steps per split

// fused-lstm smem layout (bytes); 144B-padded rows (conflict-free ldmatrix)
// h buffers are parity double-buffered: MMA(m) reads parity (m-1)&1,
// ACT(m) writes parity m&1 -> only ONE barrier per step.
#define OW0   0              // Whh0 fp16 256x144
#define OWI   36864          // Wih1
#define OWH   73728          // Whh1
#define OH0A  110592         // h0 parity buffers (2 x 9216)
#define OH1A  129024         // h1 parity buffers (2 x 9216)
#define OXG0  147456         // xg buf0: 64x256 fp16 (32768 B)
#define OXG1  180224         // xg buf1
#define OB1   212992         // bias1 (permuted) 256 f32
#define FUSED_SMEM 214016

// gate permutation: col(j,gate) = (j>>2)*16 + (gate>>1)*8 + (j&3)*2 + (gate&1)
// inverse: gate = 2*((p>>3)&1) + (p&1), j = (p>>4)*4 + ((p>>1)&3)

// ---------------- scratch (device globals: allocation-free) ----------------
__device__ __half g_XG[(size_t)M2 * G4];
__device__ __half g_FEAT[(size_t)Bsz * FCK];
__device__ float g_FC1P[(size_t)FSPLIT * Bsz * 128];
__device__ float g_FC1R[(size_t)Bsz * 128];
__device__ float g_PART[240];
__device__ float g_INV[1];
__device__ __half g_W0[256 * K0P];   // permuted W_ih0 fp16 (zero-padded K)
__device__ __half g_WR0[256 * 64];   // permuted Whh0
__device__ __half g_WI1[256 * 64];   // permuted Wih1
__device__ __half g_WH1[256 * 64];   // permuted Whh1
__device__ __half g_FW[(size_t)128 * FCK];  // fc1_w fp16
__device__ float g_B0[256];
__device__ float g_B1[256];

// ---------------- activations ----------------
__device__ __forceinline__ float tanh_fast(float x) {
    float y;
    asm("tanh.approx.f32 %0, %1;" : "=f"(y) : "f"(x));
    return y;
}
__device__ __forceinline__ float sig_fast(float x) {
    return fmaf(tanh_fast(0.5f * x), 0.5f, 0.5f);
}

// ---------------- mma/ldmatrix helpers (baseline PTX) ----------------
__device__ __forceinline__ uint32_t smem_u32(const void* p) {
    uint32_t a;
    asm("{ .reg .u64 t; cvta.to.shared.u64 t, %1; cvt.u32.u64 %0, t; }" : "=r"(a) : "l"(p));
    return a;
}
#define LDSM_X4(r, addr) \
    asm volatile("ldmatrix.sync.aligned.m8n8.x4.shared.b16 {%0,%1,%2,%3}, [%4];" \
        : "=r"((r)[0]), "=r"((r)[1]), "=r"((r)[2]), "=r"((r)[3]) : "r"(addr))
#define LDSM_X2(r, addr) \
    asm volatile("ldmatrix.sync.aligned.m8n8.x2.shared.b16 {%0,%1}, [%2];" \
        : "=r"((r)[0]), "=r"((r)[1]) : "r"(addr))

__device__ __forceinline__ void mma_f16(float* c, const uint32_t* a, const uint32_t* b) {
    asm volatile(
        "mma.sync.aligned.m16n8k16.row.col.f32.f16.f16.f32 "
        "{%0,%1,%2,%3}, {%4,%5,%6,%7}, {%8,%9}, {%0,%1,%2,%3};"
        : "+f"(c[0]), "+f"(c[1]), "+f"(c[2]), "+f"(c[3])
        : "r"(a[0]), "r"(a[1]), "r"(a[2]), "r"(a[3]), "r"(b[0]), "r"(b[1]));
}

__device__ __forceinline__ void cp16(uint32_t dst, const void* src) {
    asm volatile("cp.async.cg.shared.global [%0], [%1], 16;" :: "r"(dst), "l"(src));
}
#define CP_COMMIT() asm volatile("cp.async.commit_group;" ::: "memory")
#define CP_WAIT0()  asm volatile("cp.async.wait_group 0;" ::: "memory")

// ---------------- merged conversion (one launch) ----------------
#define SEG0 (256*K0P)
#define SEG1 (SEG0 + 256*64)
#define SEG2 (SEG1 + 256*64)
#define SEG3 (SEG2 + 256*64)
#define SEG4 (SEG3 + 128*FCK)
#define SEG5 (SEG4 + 256)
#define SEG6 (SEG5 + 256)

__device__ __forceinline__ int gate_perm_row(int n) {
    int gate = 2 * ((n >> 3) & 1) + (n & 1);
    int j = (n >> 4) * 4 + ((n >> 1) & 3);
    return gate * 64 + j;
}

__global__ void convert_all(
    const float* __restrict__ Wih0, const float* __restrict__ Whh0,
    const float* __restrict__ Wih1, const float* __restrict__ Whh1,
    const float* __restrict__ fc1w,
    const float* __restrict__ bih0, const float* __restrict__ bhh0,
    const float* __restrict__ bih1, const float* __restrict__ bhh1,
    __half* __restrict__ W0, __half* __restrict__ WR0,
    __half* __restrict__ WI1, __half* __restrict__ WH1,
    __half* __restrict__ FW, float* __restrict__ B0, float* __restrict__ B1)
{
    int idx = blockIdx.x * 256 + threadIdx.x;
    if (idx < SEG0) {
        int n = idx / K0P, k = idx - n * K0P;
        float v = (k < Dsz) ? Wih0[gate_perm_row(n) * Dsz + k] : 0.f;
        W0[idx] = __float2half_rn(v);
    } else if (idx < SEG3) {
        int r = idx - SEG0;
        const float* src; __half* dst;
        if (r < 16384)      { src = Whh0; dst = WR0; }
        else if (r < 32768) { src = Wih1; dst = WI1; r -= 16384; }
        else                { src = Whh1; dst = WH1; r -= 32768; }
        int n = r >> 6, k = r & 63;
        dst[r] = __float2half_rn(src[gate_perm_row(n) * 64 + k]);
    } else if (idx < SEG4) {
        int r = idx - SEG3;
        FW[r] = __float2half_rn(fc1w[r]);
    } else if (idx < SEG5) {
        int i = idx - SEG4;
        int n_in = gate_perm_row(i);
        B0[i] = bih0[n_in] + bhh0[n_in];
    } else if (idx < SEG6) {
        int i = idx - SEG5;
        int n_in = gate_perm_row(i);
        B1[i] = bih1[n_in] + bhh1[n_in];
    }
}

// ---------------- fp16 tensor-core GEMM: C = A[M,K] * W[N,K]^T (+bias) ------
// CTA 128x128, 8 warps, fp16 single operands, fp32 accum.
// SWAPXY=1: row block from blockIdx.y, col from blockIdx.x (adjacent bids share
// the A tile through L2 when gridDim.x == #col-blocks).
template<int AHALF, int SWAPXY, typename OutT>
__global__ void __launch_bounds__(256) gemm_f16(
    const void* __restrict__ A0v, const void* __restrict__ A1v, int rowsplit,
    int lda, int nch,
    const __half* __restrict__ W, int ldw, const float* __restrict__ bias,
    OutT* __restrict__ C, int ldc, size_t csplit)
{
    __shared__ __align__(16) uint32_t sm[6144];   // 24 KB
    const uint32_t sb = smem_u32(sm);

    const int tid  = threadIdx.x;
    const int lane = tid & 31;
    const int wid  = tid >> 5;
    const int warpM = wid >> 2;
    const int warpN = wid & 3;
    const int row0 = (SWAPXY ? blockIdx.y : blockIdx.x) * 128;
    const int col0 = (SWAPXY ? blockIdx.x : blockIdx.y) * 128;

    const size_t elt = AHALF ? 2 : 4;
    const char* Ab = (const char*)((row0 < rowsplit) ? A0v : A1v)
        + (size_t)((row0 < rowsplit) ? row0 : row0 - rowsplit) * lda * elt;

    const uint32_t laneA = (uint32_t)((((lane >> 3) & 1) * 8 + (lane & 7)) * 48
                                      + (lane >> 4) * 16);
    const uint32_t laneB = (uint32_t)((lane & 7) * 48 + ((lane >> 3) & 1) * 16);
    const uint32_t aBase = sb + (uint32_t)(warpM * 64) * 48 + laneA;
    const uint32_t bBase = sb + 6144u + (uint32_t)(warpN * 32) * 48 + laneB;

    float acc[4][4][4];
#pragma unroll
    for (int mt = 0; mt < 4; mt++)
#pragma unroll
        for (int nt = 0; nt < 4; nt++)
#pragma unroll
            for (int e = 0; e < 4; e++) acc[mt][nt][e] = 0.f;

    uint32_t areg[4], wreg[4];
    auto ldg_step = [&](int k0) {
#pragma unroll
        for (int i = 0; i < 4; i++) {
            int idx = tid + 256 * i;
            int r = idx >> 3, cp = idx & 7;
            int k = k0 + 2 * cp;
            if (AHALF) {
                areg[i] = (k + 2 <= lda)
                    ? *reinterpret_cast<const uint32_t*>(
                        Ab + ((size_t)r * lda + k) * 2)
                    : 0u;
            } else {
                if (k + 2 <= lda) {
                    float2 f = *reinterpret_cast<const float2*>(
                        Ab + ((size_t)r * lda + k) * 4);
                    __half2 hh = __floats2half2_rn(f.x, f.y);
                    areg[i] = *reinterpret_cast<uint32_t*>(&hh);
                } else {
                    areg[i] = 0u;
                }
            }
            wreg[i] = *reinterpret_cast<const uint32_t*>(
                W + (size_t)(col0 + r) * ldw + k0 + 2 * cp);
        }
    };
    auto sts_step = [&](int buf) {
        char* base = reinterpret_cast<char*>(sm) + buf * 12288;
#pragma unroll
        for (int i = 0; i < 4; i++) {
            int idx = tid + 256 * i;
            int r = idx >> 3, cp = idx & 7;
            *reinterpret_cast<uint32_t*>(base + r * 48 + cp * 4) = areg[i];
            *reinterpret_cast<uint32_t*>(base + 6144 + r * 48 + cp * 4) = wreg[i];
        }
    };

    ldg_step(blockIdx.z * nch * 16);
    sts_step(0);
    __syncthreads();

    int buf = 0;
    for (int s = 0;; s++) {
        const bool more = (s + 1) < nch;
        if (more) ldg_step((blockIdx.z * nch + s + 1) * 16);

        uint32_t af[4][4], bf[4][2];
        uint32_t aOff = aBase + buf * 12288u;
        uint32_t bOff = bBase + buf * 12288u;
#pragma unroll
        for (int mt = 0; mt < 4; mt++) LDSM_X4(af[mt], aOff + mt * 768u);
#pragma unroll
        for (int nt = 0; nt < 4; nt++) LDSM_X2(bf[nt], bOff + nt * 384u);
#pragma unroll
        for (int mt = 0; mt < 4; mt++)
#pragma unroll
            for (int nt = 0; nt < 4; nt++)
                mma_f16(acc[mt][nt], af[mt], bf[nt]);

        if (!more) break;
        sts_step(buf ^ 1);
        __syncthreads();
        buf ^= 1;
    }

    OutT* Cb = C + (size_t)blockIdx.z * csplit;
    const int gid = lane >> 2;
    const int tig = lane & 3;
#pragma unroll
    for (int mt = 0; mt < 4; mt++) {
        int r = row0 + warpM * 64 + mt * 16 + gid;
#pragma unroll
        for (int nt = 0; nt < 4; nt++) {
            int cc = col0 + warpN * 32 + nt * 8 + 2 * tig;
            float b0 = bias ? bias[cc] : 0.f;
            float b1 = bias ? bias[cc + 1] : 0.f;
            float v00 = acc[mt][nt][0] + b0, v01 = acc[mt][nt][1] + b1;
            float v10 = acc[mt][nt][2] + b0, v11 = acc[mt][nt][3] + b1;
            if (sizeof(OutT) == 2) {
                __half2 h0 = __floats2half2_rn(v00, v01);
                __half2 h1 = __floats2half2_rn(v10, v11);
                *reinterpret_cast<__half2*>((__half*)Cb + (size_t)r * ldc + cc) = h0;
                *reinterpret_cast<__half2*>((__half*)Cb + (size_t)(r + 8) * ldc + cc) = h1;
            } else {
                *reinterpret_cast<float2*>((float*)Cb + (size_t)r * ldc + cc)
                    = make_float2(v00, v01);
                *reinterpret_cast<float2*>((float*)Cb + (size_t)(r + 8) * ldc + cc)
                    = make_float2(v10, v11);
            }
        }
    }
}

// ---------------- fused 2-layer tensor-core LSTM (fp16, 1 barrier/step) -----
// 64 batch rows/CTA, 512 threads (16 warps). h parity double-buffered:
// MMA(m) reads buf[(m-1)&1], ACT(m) writes buf[m&1] -> single __syncthreads
// per step. xg double-buffered; ALL cp.async groups drained by the CP_WAIT0
// at the end of the PREVIOUS step (and in the prologue for xg(0)).
__global__ void __launch_bounds__(512, 1) lstm_fused_tc(
    const __half* __restrict__ XG,      // [8192*T, 256] permuted cols, B0 folded
    const __half* __restrict__ W0,      // permuted Whh0 [256][64]
    const __half* __restrict__ Wi1,     // permuted Wih1
    const __half* __restrict__ Wh1,     // permuted Whh1
    const float* __restrict__ B1,       // permuted bias1
    __half* __restrict__ FEAT)
{
    extern __shared__ char smem[];
    const uint32_t sb = smem_u32(smem);
    const int tid = threadIdx.x;
    const int lane = tid & 31;
    const int wid = tid >> 5;
    const int warpM = wid & 3;          // 16 rows
    const int warpN = wid >> 2;         // 0..3, 64 gate cols
    const int row0 = blockIdx.x * 64;

    // ---- stage weights (144B rows), zero BOTH h parity buffers, load bias ----
    {
        const uint32_t* w0 = reinterpret_cast<const uint32_t*>(W0);
        const uint32_t* wi = reinterpret_cast<const uint32_t*>(Wi1);
        const uint32_t* wh = reinterpret_cast<const uint32_t*>(Wh1);
#pragma unroll
        for (int i = 0; i < 16; i++) {
            int idx = tid + 512 * i;          // 8192 u32
            int r = idx >> 5, c = idx & 31;
            *reinterpret_cast<uint32_t*>(smem + OW0 + r * 144 + c * 4) = w0[idx];
            *reinterpret_cast<uint32_t*>(smem + OWI + r * 144 + c * 4) = wi[idx];
            *reinterpret_cast<uint32_t*>(smem + OWH + r * 144 + c * 4) = wh[idx];
        }
#pragma unroll
        for (int i = 0; i < 18; i++) {
            int idx = tid + 512 * i;          // 9216 u32 = 36864 B (all h bufs)
            *reinterpret_cast<uint32_t*>(smem + OH0A + idx * 4) = 0;
        }
        if (tid < 256) reinterpret_cast<float*>(smem + OB1)[tid] = B1[tid];
    }

    // prologue: prefetch xg(0) into buf0 and DRAIN it (fixes R14 race)
#pragma unroll
    for (int i = 0; i < 4; i++) {
        int idx = tid + 512 * i;
        int r = idx >> 5, ch = idx & 31;
        cp16(sb + OXG0 + r * 512 + ch * 16,
             XG + ((size_t)(row0 + r) * Tsz + 0) * 256 + ch * 8);
    }
    CP_COMMIT();
    CP_WAIT0();

    const uint32_t aoff = (uint32_t)((warpM * 16 + (lane & 7) + ((lane >> 3) & 1) * 8) * 144
                                     + (lane >> 4) * 16);
    const uint32_t boff = (uint32_t)((warpN * 64 + (lane & 7) + (lane >> 4) * 8) * 144
                                     + ((lane >> 3) & 1) * 16);
    const uint32_t bW0 = sb + OW0 + boff, bWi = sb + OWI + boff, bWh = sb + OWH + boff;

    const int gid = lane >> 2;          // 0..7
    const int tig = lane & 3;           // 0..3
    const int rowA = warpM * 16 + gid;  // rows rowA, rowA+8
    const float* b1s = reinterpret_cast<const float*>(smem + OB1);

    const int growA = row0 + rowA;
    const int inp = growA >> 12, bbA = growA & (Bsz - 1);
    __half* featA = FEAT + (size_t)bbA * FCK + (size_t)inp * (Tsz * Hsz);
    __half* featB = FEAT + (size_t)(bbA + 8) * FCK + (size_t)inp * (Tsz * Hsz);

    float c0st[8], c1st[8];
#pragma unroll
    for (int i = 0; i < 8; i++) { c0st[i] = 0.f; c1st[i] = 0.f; }

    __syncthreads();   // weights + h zeros + xg(0) visible

    for (int m = 0; m <= Tsz; m++) {
        const int pr = (m + 1) & 1;     // parity MMA reads  (= (m-1)&1)
        const int pw = m & 1;           // parity ACT writes

        // issue xg(m+1) prefetch into buffer pr (disjoint from ACT's xg buf pw)
        if (m + 1 < Tsz) {
            uint32_t xdst = sb + OXG0 + (uint32_t)pr * 32768u;
#pragma unroll
            for (int i = 0; i < 4; i++) {
                int idx = tid + 512 * i;
                int r = idx >> 5, ch = idx & 31;
                cp16(xdst + r * 512 + ch * 16,
                     XG + ((size_t)(row0 + r) * Tsz + m + 1) * 256 + ch * 8);
            }
            CP_COMMIT();
        }

        const uint32_t a0 = sb + OH0A + (uint32_t)pr * 9216u + aoff;
        const uint32_t a1 = sb + OH1A + (uint32_t)pr * 9216u + aoff;

        // ---- merged MMA phase ----
        float acc0[8][4], acc1[8][4];
#pragma unroll
        for (int nt = 0; nt < 8; nt++)
#pragma unroll
            for (int e = 0; e < 4; e++) { acc0[nt][e] = 0.f; acc1[nt][e] = 0.f; }

#pragma unroll
        for (int ks = 0; ks < 4; ks++) {
            uint32_t ah[4];
            LDSM_X4(ah, a0 + ks * 32);
#pragma unroll
            for (int np = 0; np < 4; np++) {
                uint32_t bv[4];
                LDSM_X4(bv, bW0 + np * 2304 + ks * 32);
                mma_f16(acc0[2 * np],     ah, bv);
                mma_f16(acc0[2 * np + 1], ah, bv + 2);
                uint32_t bw[4];
                LDSM_X4(bw, bWi + np * 2304 + ks * 32);
                mma_f16(acc1[2 * np],     ah, bw);
                mma_f16(acc1[2 * np + 1], ah, bw + 2);
            }
        }
        if (m >= 1) {       // h1 contribution (h1 == 0 at m==0)
#pragma unroll
            for (int ks = 0; ks < 4; ks++) {
                uint32_t ah[4];
                LDSM_X4(ah, a1 + ks * 32);
#pragma unroll
                for (int np = 0; np < 4; np++) {
                    uint32_t bv[4];
                    LDSM_X4(bv, bWh + np * 2304 + ks * 32);
                    mma_f16(acc1[2 * np],     ah, bv);
                    mma_f16(acc1[2 * np + 1], ah, bv + 2);
                }
            }
        }

        // ---- ACT phase (xg(m) guaranteed resident by prior step's CP_WAIT0) --
        const uint32_t h0w = sb + OH0A + (uint32_t)pw * 9216u;
        const uint32_t h1w = sb + OH1A + (uint32_t)pw * 9216u;
        if (m < Tsz) {
            const __half* xbuf = reinterpret_cast<const __half*>(
                smem + OXG0 + pw * 32768);
#pragma unroll
            for (int p = 0; p < 4; p++) {
                int colb = warpN * 64 + p * 16 + 2 * tig;
                int j = warpN * 16 + p * 4 + tig;
#pragma unroll
                for (int rh = 0; rh < 2; rh++) {
                    int row = rowA + rh * 8;
                    int e = 2 * rh;
                    float2 xif = __half22float2(*reinterpret_cast<const __half2*>(
                        xbuf + row * 256 + colb));
                    float2 xgo = __half22float2(*reinterpret_cast<const __half2*>(
                        xbuf + row * 256 + colb + 8));
                    float gi = acc0[2 * p][e]     + xif.x;
                    float gf = acc0[2 * p][e + 1] + xif.y;
                    float gg = acc0[2 * p + 1][e]     + xgo.x;
                    float go = acc0[2 * p + 1][e + 1] + xgo.y;
                    float& c = c0st[2 * p + rh];
                    c = sig_fast(gf) * c + sig_fast(gi) * tanh_fast(gg);
                    float h = sig_fast(go) * tanh_fast(c);
                    *reinterpret_cast<unsigned short*>(
                        smem + (h0w - sb) + row * 144 + j * 2)
                        = __half_as_ushort(__float2half_rn(h));
                }
            }
        }
        if (m >= 1) {
#pragma unroll
            for (int p = 0; p < 4; p++) {
                int colb = warpN * 64 + p * 16 + 2 * tig;
                int j = warpN * 16 + p * 4 + tig;
                float2 bif = *reinterpret_cast<const float2*>(b1s + colb);
                float2 bgo = *reinterpret_cast<const float2*>(b1s + colb + 8);
#pragma unroll
                for (int rh = 0; rh < 2; rh++) {
                    int row = rowA + rh * 8;
                    int e = 2 * rh;
                    float gi = acc1[2 * p][e]     + bif.x;
                    float gf = acc1[2 * p][e + 1] + bif.y;
                    float gg = acc1[2 * p + 1][e]     + bgo.x;
                    float go = acc1[2 * p + 1][e + 1] + bgo.y;
                    float& c = c1st[2 * p + rh];
                    c = sig_fast(gf) * c + sig_fast(gi) * tanh_fast(gg);
                    float h = sig_fast(go) * tanh_fast(c);
                    *reinterpret_cast<unsigned short*>(
                        smem + (h1w - sb) + row * 144 + j * 2)
                        = __half_as_ushort(__float2half_rn(h));
                    __half* fp = rh ? featB : featA;
                    fp[(size_t)(m - 1) * Hsz + j] = __float2half_rn(fmaxf(h, 0.f));
                }
            }
        }

        CP_WAIT0();        // xg(m+1) fully resident before the barrier
        __syncthreads();   // single barrier: h(pw) + xg(m+1) visible to all
    }
}

// ---------------- FC1 split-K reduction (+bias, +relu) ----------------
__global__ void __launch_bounds__(256) fc1_reduce(
    const float* __restrict__ part, const float* __restrict__ bias,
    float* __restrict__ outp)
{
    const size_t S = (size_t)Bsz * 128;
    size_t i = (size_t)blockIdx.x * 256 + threadIdx.x;
    int n = (int)(i & 127);
    float s = bias[n];
#pragma unroll
    for (int z = 0; z < FSPLIT; z++) s += part[i + z * S];
    outp[i] = fmaxf(s, 0.f);
}

// ---------------- FC2 + partial sum-of-squares ----------------
__global__ void __launch_bounds__(256) fc2_norm(
    const float* __restrict__ fc1, const float* __restrict__ w,
    const float* __restrict__ bias, float* __restrict__ out,
    float* __restrict__ partial)
{
    __shared__ float sw[15 * 132];
    __shared__ float red[256];
    const int tid = threadIdx.x;
    for (int i = tid; i < 15 * 128; i += 256) {
        int n = i >> 7, k = i & 127;
        sw[n * 132 + k] = w[i];
    }
    __syncthreads();

    int idx = blockIdx.x * 256 + tid;
    int b = idx / 15, n = idx - b * 15;
    const float4* fr = reinterpret_cast<const float4*>(fc1 + (size_t)b * 128);
    const float4* wn = reinterpret_cast<const float4*>(sw + n * 132);
    float acc = bias[n];
#pragma unroll
    for (int k = 0; k < 32; k++) {
        float4 f4 = fr[k];
        float4 w4 = wn[k];
        acc = fmaf(f4.x, w4.x, acc);
        acc = fmaf(f4.y, w4.y, acc);
        acc = fmaf(f4.z, w4.z, acc);
        acc = fmaf(f4.w, w4.w, acc);
    }
    out[idx] = acc;
    red[tid] = acc * acc;
    __syncthreads();
#pragma unroll
    for (int s = 128; s > 0; s >>= 1) {
        if (tid < s) red[tid] += red[tid + s];
        __syncthreads();
    }
    if (tid == 0) partial[blockIdx.x] = red[0];
}

__global__ void reduce_norm(const float* __restrict__ partial, float* __restrict__ inv)
{
    __shared__ float red[256];
    float s = 0.f;
    for (int i = threadIdx.x; i < 240; i += 256) s += partial[i];
    red[threadIdx.x] = s;
    __syncthreads();
#pragma unroll
    for (int st = 128; st > 0; st >>= 1) {
        if (threadIdx.x < st) red[threadIdx.x] += red[threadIdx.x + st];
        __syncthreads();
    }
    if (threadIdx.x == 0) inv[0] = 1.0f / sqrtf(red[0]);
}

__global__ void scale_out(float* __restrict__ out, const float* __restrict__ inv)
{
    int i = blockIdx.x * 256 + threadIdx.x;
    out[i] *= inv[0];
}

// ---------------- launch ----------------
extern "C" void kernel_launch(void* const* d_in, const int* in_sizes, int n_in,
                              void* d_out, int out_size)
{
    const float* x1      = (const float*)d_in[0];
    const float* x2      = (const float*)d_in[1];
    const float* W_ih_l0 = (const float*)d_in[2];
    const float* W_hh_l0 = (const float*)d_in[3];
    const float* b_ih_l0 = (const float*)d_in[4];
    const float* b_hh_l0 = (const float*)d_in[5];
    const float* W_ih_l1 = (const float*)d_in[6];
    const float* W_hh_l1 = (const float*)d_in[7];
    const float* b_ih_l1 = (const float*)d_in[8];
    const float* b_hh_l1 = (const float*)d_in[9];
    const float* fc1_w   = (const float*)d_in[10];
    const float* fc1_b   = (const float*)d_in[11];
    const float* fc2_w   = (const float*)d_in[12];
    const float* fc2_b   = (const float*)d_in[13];
    float* out = (float*)d_out;

    float *FC1P, *FC1R, *PART, *INV, *B0, *B1;
    __half *XG, *FEAT, *W0, *WR0, *WI1, *WH1, *FW;
    cudaGetSymbolAddress((void**)&XG,   g_XG);
    cudaGetSymbolAddress((void**)&FEAT, g_FEAT);
    cudaGetSymbolAddress((void**)&FC1P, g_FC1P);
    cudaGetSymbolAddress((void**)&FC1R, g_FC1R);
    cudaGetSymbolAddress((void**)&PART, g_PART);
    cudaGetSymbolAddress((void**)&INV,  g_INV);
    cudaGetSymbolAddress((void**)&B0,   g_B0);
    cudaGetSymbolAddress((void**)&B1,   g_B1);
    cudaGetSymbolAddress((void**)&W0,   g_W0);
    cudaGetSymbolAddress((void**)&WR0,  g_WR0);
    cudaGetSymbolAddress((void**)&WI1,  g_WI1);
    cudaGetSymbolAddress((void**)&WH1,  g_WH1);
    cudaGetSymbolAddress((void**)&FW,   g_FW);

    cudaFuncSetAttribute(lstm_fused_tc, cudaFuncAttributeMaxDynamicSharedMemorySize,
                         FUSED_SMEM);

    // all weight/bias conversions in ONE launch
    convert_all<<<(SEG6 + 255) / 256, 256>>>(
        W_ih_l0, W_hh_l0, W_ih_l1, W_hh_l1, fc1_w,
        b_ih_l0, b_hh_l0, b_ih_l1, b_hh_l1,
        W0, WR0, WI1, WH1, FW, B0, B1);

    // layer-0 input projection; grid (cols=2, rows) so paired col-CTAs are
    // adjacent in schedule -> A tile read once from DRAM (L2 reuse)
    gemm_f16<0, 1, __half><<<dim3(2, M2 / 128, 1), 256>>>(
        x1, x2, BT, Dsz, K0P / 16, W0, K0P, B0, XG, 256, 0);

    // fused 2-layer recurrence (1 barrier/step, h parity buffers)
    lstm_fused_tc<<<128, 512, FUSED_SMEM>>>(XG, WR0, WI1, WH1, B1, FEAT);

    // FC1: fp16 split-K x16, then reduce(+bias,+relu)
    gemm_f16<1, 0, float><<<dim3(Bsz / 128, 1, FSPLIT), 256>>>(
        FEAT, FEAT, 1 << 30, FCK, FSTEPS, FW, FCK, nullptr,
        FC1P, 128, (size_t)Bsz * 128);
    fc1_reduce<<<(Bsz * 128) / 256, 256>>>(FC1P, fc1_b, FC1R);

    // FC2 + deterministic norm + scale
    fc2_norm<<<240, 256>>>(FC1R, fc2_w, fc2_b, out, PART);
    reduce_norm<<<1, 256>>>(PART, INV);
    scale_out<<<240, 256>>>(out, INV);
}

// round 16
// speedup vs baseline: 7.8157x; 1.0114x over previous
#include <cuda_runtime.h>
#include <cuda_fp16.h>
#include <cstdint>
#include <cstddef>

#define Bsz 4096
#define Tsz 60
#define Dsz 200
#define K0P 208             // Dsz padded to multiple of 16
#define Hsz 64
#define G4  256
#define BT  (Bsz*Tsz)       // 245760
#define M2  (2*BT)          // 491520
#define FCK (2*Tsz*Hsz)     // 7680
#define FSPLIT 16
#define FSTEPS (FCK/FSPLIT/16)  // 30 k-steps per split

// fused-lstm smem layout (bytes); 144B-padded rows (conflict-free ldmatrix)
// h buffers are parity double-buffered: MMA(m) reads parity (m-1)&1,
// ACT(m) writes parity m&1 -> only ONE barrier per step.
#define OW0   0              // Whh0 fp16 256x144
#define OWI   36864          // Wih1
#define OWH   73728          // Whh1
#define OH0A  110592         // h0 parity buffers (2 x 9216)
#define OH1A  129024         // h1 parity buffers (2 x 9216)
#define OXG0  147456         // xg buf0: 64x256 fp16 (32768 B)
#define OXG1  180224         // xg buf1
#define OB1   212992         // bias1 (permuted) 256 f32
#define FUSED_SMEM 214016

// gate permutation: col(j,gate) = (j>>2)*16 + (gate>>1)*8 + (j&3)*2 + (gate&1)
// inverse: gate = 2*((p>>3)&1) + (p&1), j = (p>>4)*4 + ((p>>1)&3)

// ---------------- scratch (device globals: allocation-free) ----------------
__device__ __half g_XG[(size_t)M2 * G4];
__device__ __half g_FEAT[(size_t)Bsz * FCK];
__device__ float g_FC1P[(size_t)FSPLIT * Bsz * 128];
__device__ float g_FC1R[(size_t)Bsz * 128];
__device__ float g_PART[240];
__device__ float g_INV[1];
__device__ __half g_W0[256 * K0P];   // permuted W_ih0 fp16 (zero-padded K)
__device__ __half g_WR0[256 * 64];   // permuted Whh0
__device__ __half g_WI1[256 * 64];   // permuted Wih1
__device__ __half g_WH1[256 * 64];   // permuted Whh1
__device__ __half g_FW[(size_t)128 * FCK];  // fc1_w fp16
__device__ float g_B0[256];
__device__ float g_B1[256];

// ---------------- activations ----------------
__device__ __forceinline__ float tanh_fast(float x) {
    float y;
    asm("tanh.approx.f32 %0, %1;" : "=f"(y) : "f"(x));
    return y;
}
__device__ __forceinline__ float sig_fast(float x) {
    return fmaf(tanh_fast(0.5f * x), 0.5f, 0.5f);
}

// ---------------- mma/ldmatrix helpers (baseline PTX) ----------------
__device__ __forceinline__ uint32_t smem_u32(const void* p) {
    uint32_t a;
    asm("{ .reg .u64 t; cvta.to.shared.u64 t, %1; cvt.u32.u64 %0, t; }" : "=r"(a) : "l"(p));
    return a;
}
#define LDSM_X4(r, addr) \
    asm volatile("ldmatrix.sync.aligned.m8n8.x4.shared.b16 {%0,%1,%2,%3}, [%4];" \
        : "=r"((r)[0]), "=r"((r)[1]), "=r"((r)[2]), "=r"((r)[3]) : "r"(addr))
#define LDSM_X2(r, addr) \
    asm volatile("ldmatrix.sync.aligned.m8n8.x2.shared.b16 {%0,%1}, [%2];" \
        : "=r"((r)[0]), "=r"((r)[1]) : "r"(addr))

__device__ __forceinline__ void mma_f16(float* c, const uint32_t* a, const uint32_t* b) {
    asm volatile(
        "mma.sync.aligned.m16n8k16.row.col.f32.f16.f16.f32 "
        "{%0,%1,%2,%3}, {%4,%5,%6,%7}, {%8,%9}, {%0,%1,%2,%3};"
        : "+f"(c[0]), "+f"(c[1]), "+f"(c[2]), "+f"(c[3])
        : "r"(a[0]), "r"(a[1]), "r"(a[2]), "r"(a[3]), "r"(b[0]), "r"(b[1]));
}

__device__ __forceinline__ void cp16(uint32_t dst, const void* src) {
    asm volatile("cp.async.cg.shared.global [%0], [%1], 16;" :: "r"(dst), "l"(src));
}
#define CP_COMMIT() asm volatile("cp.async.commit_group;" ::: "memory")
#define CP_WAIT0()  asm volatile("cp.async.wait_group 0;" ::: "memory")

// ---------------- merged conversion (one launch) ----------------
#define SEG0 (256*K0P)
#define SEG1 (SEG0 + 256*64)
#define SEG2 (SEG1 + 256*64)
#define SEG3 (SEG2 + 256*64)
#define SEG4 (SEG3 + 128*FCK)
#define SEG5 (SEG4 + 256)
#define SEG6 (SEG5 + 256)

__device__ __forceinline__ int gate_perm_row(int n) {
    int gate = 2 * ((n >> 3) & 1) + (n & 1);
    int j = (n >> 4) * 4 + ((n >> 1) & 3);
    return gate * 64 + j;
}

__global__ void convert_all(
    const float* __restrict__ Wih0, const float* __restrict__ Whh0,
    const float* __restrict__ Wih1, const float* __restrict__ Whh1,
    const float* __restrict__ fc1w,
    const float* __restrict__ bih0, const float* __restrict__ bhh0,
    const float* __restrict__ bih1, const float* __restrict__ bhh1,
    __half* __restrict__ W0, __half* __restrict__ WR0,
    __half* __restrict__ WI1, __half* __restrict__ WH1,
    __half* __restrict__ FW, float* __restrict__ B0, float* __restrict__ B1)
{
    int idx = blockIdx.x * 256 + threadIdx.x;
    if (idx < SEG0) {
        int n = idx / K0P, k = idx - n * K0P;
        float v = (k < Dsz) ? Wih0[gate_perm_row(n) * Dsz + k] : 0.f;
        W0[idx] = __float2half_rn(v);
    } else if (idx < SEG3) {
        int r = idx - SEG0;
        const float* src; __half* dst;
        if (r < 16384)      { src = Whh0; dst = WR0; }
        else if (r < 32768) { src = Wih1; dst = WI1; r -= 16384; }
        else                { src = Whh1; dst = WH1; r -= 32768; }
        int n = r >> 6, k = r & 63;
        dst[r] = __float2half_rn(src[gate_perm_row(n) * 64 + k]);
    } else if (idx < SEG4) {
        int r = idx - SEG3;
        FW[r] = __float2half_rn(fc1w[r]);
    } else if (idx < SEG5) {
        int i = idx - SEG4;
        int n_in = gate_perm_row(i);
        B0[i] = bih0[n_in] + bhh0[n_in];
    } else if (idx < SEG6) {
        int i = idx - SEG5;
        int n_in = gate_perm_row(i);
        B1[i] = bih1[n_in] + bhh1[n_in];
    }
}

// ---------------- fp16 tensor-core GEMM: C = A[M,K] * W[N,K]^T (+bias) ------
// CTA 128x128, 8 warps, fp16 single operands, fp32 accum.
// SWAPXY=1: row block from blockIdx.y, col from blockIdx.x (adjacent bids share
// the A tile through L2 when gridDim.x == #col-blocks).
template<int AHALF, int SWAPXY, typename OutT>
__global__ void __launch_bounds__(256, 2) gemm_f16(
    const void* __restrict__ A0v, const void* __restrict__ A1v, int rowsplit,
    int lda, int nch,
    const __half* __restrict__ W, int ldw, const float* __restrict__ bias,
    OutT* __restrict__ C, int ldc, size_t csplit)
{
    __shared__ __align__(16) uint32_t sm[6144];   // 24 KB
    const uint32_t sb = smem_u32(sm);

    const int tid  = threadIdx.x;
    const int lane = tid & 31;
    const int wid  = tid >> 5;
    const int warpM = wid >> 2;
    const int warpN = wid & 3;
    const int row0 = (SWAPXY ? blockIdx.y : blockIdx.x) * 128;
    const int col0 = (SWAPXY ? blockIdx.x : blockIdx.y) * 128;

    const size_t elt = AHALF ? 2 : 4;
    const char* Ab = (const char*)((row0 < rowsplit) ? A0v : A1v)
        + (size_t)((row0 < rowsplit) ? row0 : row0 - rowsplit) * lda * elt;

    const uint32_t laneA = (uint32_t)((((lane >> 3) & 1) * 8 + (lane & 7)) * 48
                                      + (lane >> 4) * 16);
    const uint32_t laneB = (uint32_t)((lane & 7) * 48 + ((lane >> 3) & 1) * 16);
    const uint32_t aBase = sb + (uint32_t)(warpM * 64) * 48 + laneA;
    const uint32_t bBase = sb + 6144u + (uint32_t)(warpN * 32) * 48 + laneB;

    float acc[4][4][4];
#pragma unroll
    for (int mt = 0; mt < 4; mt++)
#pragma unroll
        for (int nt = 0; nt < 4; nt++)
#pragma unroll
            for (int e = 0; e < 4; e++) acc[mt][nt][e] = 0.f;

    uint32_t areg[4], wreg[4];
    auto ldg_step = [&](int k0) {
#pragma unroll
        for (int i = 0; i < 4; i++) {
            int idx = tid + 256 * i;
            int r = idx >> 3, cp = idx & 7;
            int k = k0 + 2 * cp;
            if (AHALF) {
                areg[i] = (k + 2 <= lda)
                    ? *reinterpret_cast<const uint32_t*>(
                        Ab + ((size_t)r * lda + k) * 2)
                    : 0u;
            } else {
                if (k + 2 <= lda) {
                    float2 f = *reinterpret_cast<const float2*>(
                        Ab + ((size_t)r * lda + k) * 4);
                    __half2 hh = __floats2half2_rn(f.x, f.y);
                    areg[i] = *reinterpret_cast<uint32_t*>(&hh);
                } else {
                    areg[i] = 0u;
                }
            }
            wreg[i] = *reinterpret_cast<const uint32_t*>(
                W + (size_t)(col0 + r) * ldw + k0 + 2 * cp);
        }
    };
    auto sts_step = [&](int buf) {
        char* base = reinterpret_cast<char*>(sm) + buf * 12288;
#pragma unroll
        for (int i = 0; i < 4; i++) {
            int idx = tid + 256 * i;
            int r = idx >> 3, cp = idx & 7;
            *reinterpret_cast<uint32_t*>(base + r * 48 + cp * 4) = areg[i];
            *reinterpret_cast<uint32_t*>(base + 6144 + r * 48 + cp * 4) = wreg[i];
        }
    };

    ldg_step(blockIdx.z * nch * 16);
    sts_step(0);
    __syncthreads();

    int buf = 0;
    for (int s = 0;; s++) {
        const bool more = (s + 1) < nch;
        if (more) ldg_step((blockIdx.z * nch + s + 1) * 16);

        uint32_t af[4][4], bf[4][2];
        uint32_t aOff = aBase + buf * 12288u;
        uint32_t bOff = bBase + buf * 12288u;
#pragma unroll
        for (int mt = 0; mt < 4; mt++) LDSM_X4(af[mt], aOff + mt * 768u);
#pragma unroll
        for (int nt = 0; nt < 4; nt++) LDSM_X2(bf[nt], bOff + nt * 384u);
#pragma unroll
        for (int mt = 0; mt < 4; mt++)
#pragma unroll
            for (int nt = 0; nt < 4; nt++)
                mma_f16(acc[mt][nt], af[mt], bf[nt]);

        if (!more) break;
        sts_step(buf ^ 1);
        __syncthreads();
        buf ^= 1;
    }

    OutT* Cb = C + (size_t)blockIdx.z * csplit;
    const int gid = lane >> 2;
    const int tig = lane & 3;
#pragma unroll
    for (int mt = 0; mt < 4; mt++) {
        int r = row0 + warpM * 64 + mt * 16 + gid;
#pragma unroll
        for (int nt = 0; nt < 4; nt++) {
            int cc = col0 + warpN * 32 + nt * 8 + 2 * tig;
            float b0 = bias ? bias[cc] : 0.f;
            float b1 = bias ? bias[cc + 1] : 0.f;
            float v00 = acc[mt][nt][0] + b0, v01 = acc[mt][nt][1] + b1;
            float v10 = acc[mt][nt][2] + b0, v11 = acc[mt][nt][3] + b1;
            if (sizeof(OutT) == 2) {
                __half2 h0 = __floats2half2_rn(v00, v01);
                __half2 h1 = __floats2half2_rn(v10, v11);
                *reinterpret_cast<__half2*>((__half*)Cb + (size_t)r * ldc + cc) = h0;
                *reinterpret_cast<__half2*>((__half*)Cb + (size_t)(r + 8) * ldc + cc) = h1;
            } else {
                *reinterpret_cast<float2*>((float*)Cb + (size_t)r * ldc + cc)
                    = make_float2(v00, v01);
                *reinterpret_cast<float2*>((float*)Cb + (size_t)(r + 8) * ldc + cc)
                    = make_float2(v10, v11);
            }
        }
    }
}

// ---------------- fused 2-layer tensor-core LSTM (fp16, 1 barrier/step) -----
// 64 batch rows/CTA, 512 threads (16 warps). h parity double-buffered.
// Phase order per step: MMA0 -> ACT0 -> MMA1 -> ACT1 (parity makes ACT0's
// h0[pw] write disjoint from MMA1's h0[pr] read) so ACT0's MUFU stream
// overlaps MMA1's LDSM/HMMA, and acc0/acc1 are never live simultaneously.
__global__ void __launch_bounds__(512, 1) lstm_fused_tc(
    const __half* __restrict__ XG,      // [8192*T, 256] permuted cols, B0 folded
    const __half* __restrict__ W0,      // permuted Whh0 [256][64]
    const __half* __restrict__ Wi1,     // permuted Wih1
    const __half* __restrict__ Wh1,     // permuted Whh1
    const float* __restrict__ B1,       // permuted bias1
    __half* __restrict__ FEAT)
{
    extern __shared__ char smem[];
    const uint32_t sb = smem_u32(smem);
    const int tid = threadIdx.x;
    const int lane = tid & 31;
    const int wid = tid >> 5;
    const int warpM = wid & 3;          // 16 rows
    const int warpN = wid >> 2;         // 0..3, 64 gate cols
    const int row0 = blockIdx.x * 64;

    // ---- stage weights (144B rows), zero BOTH h parity buffers, load bias ----
    {
        const uint32_t* w0 = reinterpret_cast<const uint32_t*>(W0);
        const uint32_t* wi = reinterpret_cast<const uint32_t*>(Wi1);
        const uint32_t* wh = reinterpret_cast<const uint32_t*>(Wh1);
#pragma unroll
        for (int i = 0; i < 16; i++) {
            int idx = tid + 512 * i;          // 8192 u32
            int r = idx >> 5, c = idx & 31;
            *reinterpret_cast<uint32_t*>(smem + OW0 + r * 144 + c * 4) = w0[idx];
            *reinterpret_cast<uint32_t*>(smem + OWI + r * 144 + c * 4) = wi[idx];
            *reinterpret_cast<uint32_t*>(smem + OWH + r * 144 + c * 4) = wh[idx];
        }
#pragma unroll
        for (int i = 0; i < 18; i++) {
            int idx = tid + 512 * i;          // 9216 u32 = 36864 B (all h bufs)
            *reinterpret_cast<uint32_t*>(smem + OH0A + idx * 4) = 0;
        }
        if (tid < 256) reinterpret_cast<float*>(smem + OB1)[tid] = B1[tid];
    }

    // prologue: prefetch xg(0) into buf0 and DRAIN it
#pragma unroll
    for (int i = 0; i < 4; i++) {
        int idx = tid + 512 * i;
        int r = idx >> 5, ch = idx & 31;
        cp16(sb + OXG0 + r * 512 + ch * 16,
             XG + ((size_t)(row0 + r) * Tsz + 0) * 256 + ch * 8);
    }
    CP_COMMIT();
    CP_WAIT0();

    const uint32_t aoff = (uint32_t)((warpM * 16 + (lane & 7) + ((lane >> 3) & 1) * 8) * 144
                                     + (lane >> 4) * 16);
    const uint32_t boff = (uint32_t)((warpN * 64 + (lane & 7) + (lane >> 4) * 8) * 144
                                     + ((lane >> 3) & 1) * 16);
    const uint32_t bW0 = sb + OW0 + boff, bWi = sb + OWI + boff, bWh = sb + OWH + boff;

    const int gid = lane >> 2;          // 0..7
    const int tig = lane & 3;           // 0..3
    const int rowA = warpM * 16 + gid;  // rows rowA, rowA+8
    const float* b1s = reinterpret_cast<const float*>(smem + OB1);

    const int growA = row0 + rowA;
    const int inp = growA >> 12, bbA = growA & (Bsz - 1);
    __half* featA = FEAT + (size_t)bbA * FCK + (size_t)inp * (Tsz * Hsz);
    __half* featB = FEAT + (size_t)(bbA + 8) * FCK + (size_t)inp * (Tsz * Hsz);

    float c0st[8], c1st[8];
#pragma unroll
    for (int i = 0; i < 8; i++) { c0st[i] = 0.f; c1st[i] = 0.f; }

    __syncthreads();   // weights + h zeros + xg(0) visible

    for (int m = 0; m <= Tsz; m++) {
        const int pr = (m + 1) & 1;     // parity MMA reads  (= (m-1)&1)
        const int pw = m & 1;           // parity ACT writes

        // issue xg(m+1) prefetch into buffer pr (disjoint from ACT's xg buf pw)
        if (m + 1 < Tsz) {
            uint32_t xdst = sb + OXG0 + (uint32_t)pr * 32768u;
#pragma unroll
            for (int i = 0; i < 4; i++) {
                int idx = tid + 512 * i;
                int r = idx >> 5, ch = idx & 31;
                cp16(xdst + r * 512 + ch * 16,
                     XG + ((size_t)(row0 + r) * Tsz + m + 1) * 256 + ch * 8);
            }
            CP_COMMIT();
        }

        const uint32_t a0 = sb + OH0A + (uint32_t)pr * 9216u + aoff;
        const uint32_t a1 = sb + OH1A + (uint32_t)pr * 9216u + aoff;
        const uint32_t h0w = sb + OH0A + (uint32_t)pw * 9216u;
        const uint32_t h1w = sb + OH1A + (uint32_t)pw * 9216u;

        // ---- MMA0 + ACT0 (layer 0) ----
        if (m < Tsz) {
            float acc0[8][4];
#pragma unroll
            for (int nt = 0; nt < 8; nt++)
#pragma unroll
                for (int e = 0; e < 4; e++) acc0[nt][e] = 0.f;
#pragma unroll
            for (int ks = 0; ks < 4; ks++) {
                uint32_t ah[4];
                LDSM_X4(ah, a0 + ks * 32);
#pragma unroll
                for (int np = 0; np < 4; np++) {
                    uint32_t bv[4];
                    LDSM_X4(bv, bW0 + np * 2304 + ks * 32);
                    mma_f16(acc0[2 * np],     ah, bv);
                    mma_f16(acc0[2 * np + 1], ah, bv + 2);
                }
            }
            const __half* xbuf = reinterpret_cast<const __half*>(
                smem + OXG0 + pw * 32768);
#pragma unroll
            for (int p = 0; p < 4; p++) {
                int colb = warpN * 64 + p * 16 + 2 * tig;
                int j = warpN * 16 + p * 4 + tig;
#pragma unroll
                for (int rh = 0; rh < 2; rh++) {
                    int row = rowA + rh * 8;
                    int e = 2 * rh;
                    float2 xif = __half22float2(*reinterpret_cast<const __half2*>(
                        xbuf + row * 256 + colb));
                    float2 xgo = __half22float2(*reinterpret_cast<const __half2*>(
                        xbuf + row * 256 + colb + 8));
                    float gi = acc0[2 * p][e]     + xif.x;
                    float gf = acc0[2 * p][e + 1] + xif.y;
                    float gg = acc0[2 * p + 1][e]     + xgo.x;
                    float go = acc0[2 * p + 1][e + 1] + xgo.y;
                    float& c = c0st[2 * p + rh];
                    c = sig_fast(gf) * c + sig_fast(gi) * tanh_fast(gg);
                    float h = sig_fast(go) * tanh_fast(c);
                    *reinterpret_cast<unsigned short*>(
                        smem + (h0w - sb) + row * 144 + j * 2)
                        = __half_as_ushort(__float2half_rn(h));
                }
            }
        }

        // ---- MMA1 + ACT1 (layer 1; operands all from parity pr) ----
        if (m >= 1) {
            float acc1[8][4];
#pragma unroll
            for (int nt = 0; nt < 8; nt++)
#pragma unroll
                for (int e = 0; e < 4; e++) acc1[nt][e] = 0.f;
#pragma unroll
            for (int ks = 0; ks < 4; ks++) {
                uint32_t ah[4];
                LDSM_X4(ah, a0 + ks * 32);
#pragma unroll
                for (int np = 0; np < 4; np++) {
                    uint32_t bw[4];
                    LDSM_X4(bw, bWi + np * 2304 + ks * 32);
                    mma_f16(acc1[2 * np],     ah, bw);
                    mma_f16(acc1[2 * np + 1], ah, bw + 2);
                }
            }
#pragma unroll
            for (int ks = 0; ks < 4; ks++) {
                uint32_t ah[4];
                LDSM_X4(ah, a1 + ks * 32);
#pragma unroll
                for (int np = 0; np < 4; np++) {
                    uint32_t bv[4];
                    LDSM_X4(bv, bWh + np * 2304 + ks * 32);
                    mma_f16(acc1[2 * np],     ah, bv);
                    mma_f16(acc1[2 * np + 1], ah, bv + 2);
                }
            }
#pragma unroll
            for (int p = 0; p < 4; p++) {
                int colb = warpN * 64 + p * 16 + 2 * tig;
                int j = warpN * 16 + p * 4 + tig;
                float2 bif = *reinterpret_cast<const float2*>(b1s + colb);
                float2 bgo = *reinterpret_cast<const float2*>(b1s + colb + 8);
#pragma unroll
                for (int rh = 0; rh < 2; rh++) {
                    int row = rowA + rh * 8;
                    int e = 2 * rh;
                    float gi = acc1[2 * p][e]     + bif.x;
                    float gf = acc1[2 * p][e + 1] + bif.y;
                    float gg = acc1[2 * p + 1][e]     + bgo.x;
                    float go = acc1[2 * p + 1][e + 1] + bgo.y;
                    float& c = c1st[2 * p + rh];
                    c = sig_fast(gf) * c + sig_fast(gi) * tanh_fast(gg);
                    float h = sig_fast(go) * tanh_fast(c);
                    *reinterpret_cast<unsigned short*>(
                        smem + (h1w - sb) + row * 144 + j * 2)
                        = __half_as_ushort(__float2half_rn(h));
                    __half* fp = rh ? featB : featA;
                    fp[(size_t)(m - 1) * Hsz + j] = __float2half_rn(fmaxf(h, 0.f));
                }
            }
        }

        CP_WAIT0();        // xg(m+1) fully resident before the barrier
        __syncthreads();   // single barrier: h(pw) + xg(m+1) visible to all
    }
}

// ---------------- FC1 split-K reduction (+bias, +relu) ----------------
__global__ void __launch_bounds__(256) fc1_reduce(
    const float* __restrict__ part, const float* __restrict__ bias,
    float* __restrict__ outp)
{
    const size_t S = (size_t)Bsz * 128;
    size_t i = (size_t)blockIdx.x * 256 + threadIdx.x;
    int n = (int)(i & 127);
    float s = bias[n];
#pragma unroll
    for (int z = 0; z < FSPLIT; z++) s += part[i + z * S];
    outp[i] = fmaxf(s, 0.f);
}

// ---------------- FC2 + partial sum-of-squares ----------------
__global__ void __launch_bounds__(256) fc2_norm(
    const float* __restrict__ fc1, const float* __restrict__ w,
    const float* __restrict__ bias, float* __restrict__ out,
    float* __restrict__ partial)
{
    __shared__ float sw[15 * 132];
    __shared__ float red[256];
    const int tid = threadIdx.x;
    for (int i = tid; i < 15 * 128; i += 256) {
        int n = i >> 7, k = i & 127;
        sw[n * 132 + k] = w[i];
    }
    __syncthreads();

    int idx = blockIdx.x * 256 + tid;
    int b = idx / 15, n = idx - b * 15;
    const float4* fr = reinterpret_cast<const float4*>(fc1 + (size_t)b * 128);
    const float4* wn = reinterpret_cast<const float4*>(sw + n * 132);
    float acc = bias[n];
#pragma unroll
    for (int k = 0; k < 32; k++) {
        float4 f4 = fr[k];
        float4 w4 = wn[k];
        acc = fmaf(f4.x, w4.x, acc);
        acc = fmaf(f4.y, w4.y, acc);
        acc = fmaf(f4.z, w4.z, acc);
        acc = fmaf(f4.w, w4.w, acc);
    }
    out[idx] = acc;
    red[tid] = acc * acc;
    __syncthreads();
#pragma unroll
    for (int s = 128; s > 0; s >>= 1) {
        if (tid < s) red[tid] += red[tid + s];
        __syncthreads();
    }
    if (tid == 0) partial[blockIdx.x] = red[0];
}

__global__ void reduce_norm(const float* __restrict__ partial, float* __restrict__ inv)
{
    __shared__ float red[256];
    float s = 0.f;
    for (int i = threadIdx.x; i < 240; i += 256) s += partial[i];
    red[threadIdx.x] = s;
    __syncthreads();
#pragma unroll
    for (int st = 128; st > 0; st >>= 1) {
        if (threadIdx.x < st) red[threadIdx.x] += red[threadIdx.x + st];
        __syncthreads();
    }
    if (threadIdx.x == 0) inv[0] = 1.0f / sqrtf(red[0]);
}

__global__ void scale_out(float* __restrict__ out, const float* __restrict__ inv)
{
    int i = blockIdx.x * 256 + threadIdx.x;
    out[i] *= inv[0];
}

// ---------------- launch ----------------
extern "C" void kernel_launch(void* const* d_in, const int* in_sizes, int n_in,
                              void* d_out, int out_size)
{
    const float* x1      = (const float*)d_in[0];
    const float* x2      = (const float*)d_in[1];
    const float* W_ih_l0 = (const float*)d_in[2];
    const float* W_hh_l0 = (const float*)d_in[3];
    const float* b_ih_l0 = (const float*)d_in[4];
    const float* b_hh_l0 = (const float*)d_in[5];
    const float* W_ih_l1 = (const float*)d_in[6];
    const float* W_hh_l1 = (const float*)d_in[7];
    const float* b_ih_l1 = (const float*)d_in[8];
    const float* b_hh_l1 = (const float*)d_in[9];
    const float* fc1_w   = (const float*)d_in[10];
    const float* fc1_b   = (const float*)d_in[11];
    const float* fc2_w   = (const float*)d_in[12];
    const float* fc2_b   = (const float*)d_in[13];
    float* out = (float*)d_out;

    float *FC1P, *FC1R, *PART, *INV, *B0, *B1;
    __half *XG, *FEAT, *W0, *WR0, *WI1, *WH1, *FW;
    cudaGetSymbolAddress((void**)&XG,   g_XG);
    cudaGetSymbolAddress((void**)&FEAT, g_FEAT);
    cudaGetSymbolAddress((void**)&FC1P, g_FC1P);
    cudaGetSymbolAddress((void**)&FC1R, g_FC1R);
    cudaGetSymbolAddress((void**)&PART, g_PART);
    cudaGetSymbolAddress((void**)&INV,  g_INV);
    cudaGetSymbolAddress((void**)&B0,   g_B0);
    cudaGetSymbolAddress((void**)&B1,   g_B1);
    cudaGetSymbolAddress((void**)&W0,   g_W0);
    cudaGetSymbolAddress((void**)&WR0,  g_WR0);
    cudaGetSymbolAddress((void**)&WI1,  g_WI1);
    cudaGetSymbolAddress((void**)&WH1,  g_WH1);
    cudaGetSymbolAddress((void**)&FW,   g_FW);

    cudaFuncSetAttribute(lstm_fused_tc, cudaFuncAttributeMaxDynamicSharedMemorySize,
                         FUSED_SMEM);

    // all weight/bias conversions in ONE launch
    convert_all<<<(SEG6 + 255) / 256, 256>>>(
        W_ih_l0, W_hh_l0, W_ih_l1, W_hh_l1, fc1_w,
        b_ih_l0, b_hh_l0, b_ih_l1, b_hh_l1,
        W0, WR0, WI1, WH1, FW, B0, B1);

    // layer-0 input projection; grid (cols=2, rows) so paired col-CTAs are
    // adjacent in schedule -> A tile read once from DRAM (L2 reuse)
    gemm_f16<0, 1, __half><<<dim3(2, M2 / 128, 1), 256>>>(
        x1, x2, BT, Dsz, K0P / 16, W0, K0P, B0, XG, 256, 0);

    // fused 2-layer recurrence (1 barrier/step, phase-interleaved)
    lstm_fused_tc<<<128, 512, FUSED_SMEM>>>(XG, WR0, WI1, WH1, B1, FEAT);

    // FC1: fp16 split-K x16, then reduce(+bias,+relu)
    gemm_f16<1, 0, float><<<dim3(Bsz / 128, 1, FSPLIT), 256>>>(
        FEAT, FEAT, 1 << 30, FCK, FSTEPS, FW, FCK, nullptr,
        FC1P, 128, (size_t)Bsz * 128);
    fc1_reduce<<<(Bsz * 128) / 256, 256>>>(FC1P, fc1_b, FC1R);

    // FC2 + deterministic norm + scale
    fc2_norm<<<240, 256>>>(FC1R, fc2_w, fc2_b, out, PART);
    reduce_norm<<<1, 256>>>(PART, INV);
    scale_out<<<240, 256>>>(out, INV);
}

// round 17
// speedup vs baseline: 7.8734x; 1.0074x over previous
#include <cuda_runtime.h>
#include <cuda_fp16.h>
#include <cstdint>
#include <cstddef>

#define Bsz 4096
#define Tsz 60
#define Dsz 200
#define K0P 208             // Dsz padded to multiple of 16
#define Hsz 64
#define G4  256
#define BT  (Bsz*Tsz)       // 245760
#define M2  (2*BT)          // 491520
#define FCK (2*Tsz*Hsz)     // 7680
#define FSPLIT 16
#define FSTEPS (FCK/FSPLIT/16)  // 30 k-steps per split

// fused-lstm smem layout (bytes)
#define OW0   0
#define OWI   36864
#define OWH   73728
#define OH0A  110592
#define OH1A  129024
#define OXG0  147456
#define OXG1  180224
#define OB1   212992
#define FUSED_SMEM 214016

// ---------------- scratch (device globals: allocation-free) ----------------
__device__ __half g_XG[(size_t)M2 * G4];
__device__ __half g_FEAT[(size_t)Bsz * FCK];
__device__ float g_FC1P[(size_t)FSPLIT * Bsz * 128];
__device__ float g_FC1R[(size_t)Bsz * 128];
__device__ float g_PART[240];
__device__ float g_INV[1];
__device__ __half g_W0[256 * K0P];
__device__ __half g_WR0[256 * 64];
__device__ __half g_WI1[256 * 64];
__device__ __half g_WH1[256 * 64];
__device__ __half g_FW[(size_t)128 * FCK];
__device__ float g_B0[256];
__device__ float g_B1[256];

// ---------------- activations ----------------
__device__ __forceinline__ float tanh_fast(float x) {
    float y;
    asm("tanh.approx.f32 %0, %1;" : "=f"(y) : "f"(x));
    return y;
}
__device__ __forceinline__ float sig_fast(float x) {
    return fmaf(tanh_fast(0.5f * x), 0.5f, 0.5f);
}

// ---------------- mma/ldmatrix helpers (baseline PTX) ----------------
__device__ __forceinline__ uint32_t smem_u32(const void* p) {
    uint32_t a;
    asm("{ .reg .u64 t; cvta.to.shared.u64 t, %1; cvt.u32.u64 %0, t; }" : "=r"(a) : "l"(p));
    return a;
}
#define LDSM_X4(r, addr) \
    asm volatile("ldmatrix.sync.aligned.m8n8.x4.shared.b16 {%0,%1,%2,%3}, [%4];" \
        : "=r"((r)[0]), "=r"((r)[1]), "=r"((r)[2]), "=r"((r)[3]) : "r"(addr))
#define LDSM_X2(r, addr) \
    asm volatile("ldmatrix.sync.aligned.m8n8.x2.shared.b16 {%0,%1}, [%2];" \
        : "=r"((r)[0]), "=r"((r)[1]) : "r"(addr))

__device__ __forceinline__ void mma_f16(float* c, const uint32_t* a, const uint32_t* b) {
    asm volatile(
        "mma.sync.aligned.m16n8k16.row.col.f32.f16.f16.f32 "
        "{%0,%1,%2,%3}, {%4,%5,%6,%7}, {%8,%9}, {%0,%1,%2,%3};"
        : "+f"(c[0]), "+f"(c[1]), "+f"(c[2]), "+f"(c[3])
        : "r"(a[0]), "r"(a[1]), "r"(a[2]), "r"(a[3]), "r"(b[0]), "r"(b[1]));
}

__device__ __forceinline__ void cp16(uint32_t dst, const void* src) {
    asm volatile("cp.async.cg.shared.global [%0], [%1], 16;" :: "r"(dst), "l"(src));
}
__device__ __forceinline__ void cp16z(uint32_t dst, const void* src, int nbytes) {
    asm volatile("cp.async.cg.shared.global [%0], [%1], 16, %2;"
                 :: "r"(dst), "l"(src), "r"(nbytes));
}
#define CP_COMMIT() asm volatile("cp.async.commit_group;" ::: "memory")
#define CP_WAIT0()  asm volatile("cp.async.wait_group 0;" ::: "memory")
#define CP_WAIT2()  asm volatile("cp.async.wait_group 2;" ::: "memory")

// ---------------- merged conversion (one launch) ----------------
#define SEG0 (256*K0P)
#define SEG1 (SEG0 + 256*64)
#define SEG2 (SEG1 + 256*64)
#define SEG3 (SEG2 + 256*64)
#define SEG4 (SEG3 + 128*FCK)
#define SEG5 (SEG4 + 256)
#define SEG6 (SEG5 + 256)

__device__ __forceinline__ int gate_perm_row(int n) {
    int gate = 2 * ((n >> 3) & 1) + (n & 1);
    int j = (n >> 4) * 4 + ((n >> 1) & 3);
    return gate * 64 + j;
}

__global__ void convert_all(
    const float* __restrict__ Wih0, const float* __restrict__ Whh0,
    const float* __restrict__ Wih1, const float* __restrict__ Whh1,
    const float* __restrict__ fc1w,
    const float* __restrict__ bih0, const float* __restrict__ bhh0,
    const float* __restrict__ bih1, const float* __restrict__ bhh1,
    __half* __restrict__ W0, __half* __restrict__ WR0,
    __half* __restrict__ WI1, __half* __restrict__ WH1,
    __half* __restrict__ FW, float* __restrict__ B0, float* __restrict__ B1)
{
    int idx = blockIdx.x * 256 + threadIdx.x;
    if (idx < SEG0) {
        int n = idx / K0P, k = idx - n * K0P;
        float v = (k < Dsz) ? Wih0[gate_perm_row(n) * Dsz + k] : 0.f;
        W0[idx] = __float2half_rn(v);
    } else if (idx < SEG3) {
        int r = idx - SEG0;
        const float* src; __half* dst;
        if (r < 16384)      { src = Whh0; dst = WR0; }
        else if (r < 32768) { src = Wih1; dst = WI1; r -= 16384; }
        else                { src = Whh1; dst = WH1; r -= 32768; }
        int n = r >> 6, k = r & 63;
        dst[r] = __float2half_rn(src[gate_perm_row(n) * 64 + k]);
    } else if (idx < SEG4) {
        int r = idx - SEG3;
        FW[r] = __float2half_rn(fc1w[r]);
    } else if (idx < SEG5) {
        int i = idx - SEG4;
        int n_in = gate_perm_row(i);
        B0[i] = bih0[n_in] + bhh0[n_in];
    } else if (idx < SEG6) {
        int i = idx - SEG5;
        int n_in = gate_perm_row(i);
        B1[i] = bih1[n_in] + bhh1[n_in];
    }
}

// ---------------- fp16 tensor-core GEMM, 4-stage cp.async ring --------------
// C[M,N] = A[M,K] * W[N,K]^T (+bias). CTA 128x128, 8 warps, fp32 accum.
// AHALF=1: A fp16 in gmem (48B-padded stage rows, ldmatrix).
// AHALF=0: A fp32 in gmem (80B-padded stage rows, manual LDS.64 + cvt),
//          zero-filled beyond lda (K tail). W always fp16, 48B rows.
// SWAPXY=1: row block from blockIdx.y, col from blockIdx.x (L2 A reuse).
template<int AHALF, int SWAPXY, typename OutT>
__global__ void __launch_bounds__(256, 2) gemm_f16(
    const void* __restrict__ A0v, const void* __restrict__ A1v, int rowsplit,
    int lda, int nch,
    const __half* __restrict__ W, int ldw, const float* __restrict__ bias,
    OutT* __restrict__ C, int ldc, size_t csplit)
{
    constexpr int A_PITCH = AHALF ? 48 : 80;
    constexpr int A_STAGE = 128 * A_PITCH;
    constexpr int W_STAGE = 128 * 48;
    constexpr int STAGE   = A_STAGE + W_STAGE;
    extern __shared__ char dsm[];
    const uint32_t sb = smem_u32(dsm);

    const int tid  = threadIdx.x;
    const int lane = tid & 31;
    const int wid  = tid >> 5;
    const int warpM = wid >> 2;
    const int warpN = wid & 3;
    const int row0 = (SWAPXY ? blockIdx.y : blockIdx.x) * 128;
    const int col0 = (SWAPXY ? blockIdx.x : blockIdx.y) * 128;
    const int kbase = blockIdx.z * nch * 16;

    const size_t elt = AHALF ? 2 : 4;
    const char* Ab = (const char*)((row0 < rowsplit) ? A0v : A1v)
        + (size_t)((row0 < rowsplit) ? row0 : row0 - rowsplit) * lda * elt;

    const int gid = lane >> 2;
    const int tig = lane & 3;

    // fragment addressing
    const uint32_t laneA = (uint32_t)((((lane >> 3) & 1) * 8 + (lane & 7)) * 48
                                      + (lane >> 4) * 16);
    const uint32_t laneB = (uint32_t)((lane & 7) * 48 + ((lane >> 3) & 1) * 16);

    float acc[4][4][4];
#pragma unroll
    for (int mt = 0; mt < 4; mt++)
#pragma unroll
        for (int nt = 0; nt < 4; nt++)
#pragma unroll
            for (int e = 0; e < 4; e++) acc[mt][nt][e] = 0.f;

    // ---- stage issue ----
    auto issue_stage = [&](int slot, int s) {
        const int k0 = kbase + s * 16;
        uint32_t stA = sb + (uint32_t)slot * STAGE;
        uint32_t stW = stA + A_STAGE;
        if (AHALF) {
            // A: 256 chunks, 1/thread
            {
                int r = tid >> 1, ci = tid & 1;
                cp16(stA + r * 48 + ci * 16,
                     Ab + ((size_t)r * lda + k0 + ci * 8) * 2);
            }
        } else {
            // A fp32: 512 chunks, 2/thread, zero-fill beyond lda floats
#pragma unroll
            for (int i = 0; i < 2; i++) {
                int c = tid + 256 * i;
                int r = c >> 2, ci = c & 3;
                int kb = (k0 + ci * 4) * 4;           // byte offset in row
                int valid = lda * 4 - kb;
                valid = valid < 0 ? 0 : (valid > 16 ? 16 : valid);
                int kbs = kb < (lda - 4) * 4 ? kb : (lda - 4) * 4;
                cp16z(stA + r * 80 + ci * 16,
                      Ab + (size_t)r * lda * 4 + kbs, valid);
            }
        }
        // W: 256 chunks, 1/thread (always in-bounds: padded/exact)
        {
            int r = tid >> 1, ci = tid & 1;
            cp16(stW + r * 48 + ci * 16,
                 W + (size_t)(col0 + r) * ldw + k0 + ci * 8);
        }
    };

    // prologue: stages 0..2
    issue_stage(0, 0); CP_COMMIT();
    issue_stage(1, 1); CP_COMMIT();
    issue_stage(2, 2); CP_COMMIT();

    for (int s = 0; s < nch; s++) {
        CP_WAIT2();          // stage s complete
        __syncthreads();     // visible to all; prior compute done (slot reuse safe)
        if (s + 3 < nch) issue_stage((s + 3) & 3, s + 3);
        CP_COMMIT();         // always commit (possibly empty) to keep group count

        uint32_t stA = sb + (uint32_t)(s & 3) * STAGE;
        uint32_t stW = stA + A_STAGE;

        uint32_t af[4][4], bf[4][2];
        if (AHALF) {
            uint32_t aOff = stA + (uint32_t)(warpM * 64) * 48 + laneA;
#pragma unroll
            for (int mt = 0; mt < 4; mt++) LDSM_X4(af[mt], aOff + mt * 768u);
        } else {
            const char* ab = dsm + (s & 3) * STAGE;
#pragma unroll
            for (int mt = 0; mt < 4; mt++) {
                int rlo = warpM * 64 + mt * 16 + gid;
                const float2 f0 = *reinterpret_cast<const float2*>(
                    ab + rlo * 80 + tig * 8);
                const float2 f2 = *reinterpret_cast<const float2*>(
                    ab + rlo * 80 + tig * 8 + 32);
                const float2 f1 = *reinterpret_cast<const float2*>(
                    ab + (rlo + 8) * 80 + tig * 8);
                const float2 f3 = *reinterpret_cast<const float2*>(
                    ab + (rlo + 8) * 80 + tig * 8 + 32);
                __half2 h;
                h = __floats2half2_rn(f0.x, f0.y); af[mt][0] = *reinterpret_cast<uint32_t*>(&h);
                h = __floats2half2_rn(f1.x, f1.y); af[mt][1] = *reinterpret_cast<uint32_t*>(&h);
                h = __floats2half2_rn(f2.x, f2.y); af[mt][2] = *reinterpret_cast<uint32_t*>(&h);
                h = __floats2half2_rn(f3.x, f3.y); af[mt][3] = *reinterpret_cast<uint32_t*>(&h);
            }
        }
        uint32_t bOff = stW + (uint32_t)(warpN * 32) * 48 + laneB;
#pragma unroll
        for (int nt = 0; nt < 4; nt++) LDSM_X2(bf[nt], bOff + nt * 384u);

#pragma unroll
        for (int mt = 0; mt < 4; mt++)
#pragma unroll
            for (int nt = 0; nt < 4; nt++)
                mma_f16(acc[mt][nt], af[mt], bf[nt]);
    }

    OutT* Cb = C + (size_t)blockIdx.z * csplit;
#pragma unroll
    for (int mt = 0; mt < 4; mt++) {
        int r = row0 + warpM * 64 + mt * 16 + gid;
#pragma unroll
        for (int nt = 0; nt < 4; nt++) {
            int cc = col0 + warpN * 32 + nt * 8 + 2 * tig;
            float b0 = bias ? bias[cc] : 0.f;
            float b1 = bias ? bias[cc + 1] : 0.f;
            float v00 = acc[mt][nt][0] + b0, v01 = acc[mt][nt][1] + b1;
            float v10 = acc[mt][nt][2] + b0, v11 = acc[mt][nt][3] + b1;
            if (sizeof(OutT) == 2) {
                __half2 h0 = __floats2half2_rn(v00, v01);
                __half2 h1 = __floats2half2_rn(v10, v11);
                *reinterpret_cast<__half2*>((__half*)Cb + (size_t)r * ldc + cc) = h0;
                *reinterpret_cast<__half2*>((__half*)Cb + (size_t)(r + 8) * ldc + cc) = h1;
            } else {
                *reinterpret_cast<float2*>((float*)Cb + (size_t)r * ldc + cc)
                    = make_float2(v00, v01);
                *reinterpret_cast<float2*>((float*)Cb + (size_t)(r + 8) * ldc + cc)
                    = make_float2(v10, v11);
            }
        }
    }
}

// ---------------- fused 2-layer tensor-core LSTM (unchanged from R16) -------
__global__ void __launch_bounds__(512, 1) lstm_fused_tc(
    const __half* __restrict__ XG,
    const __half* __restrict__ W0,
    const __half* __restrict__ Wi1,
    const __half* __restrict__ Wh1,
    const float* __restrict__ B1,
    __half* __restrict__ FEAT)
{
    extern __shared__ char smem[];
    const uint32_t sb = smem_u32(smem);
    const int tid = threadIdx.x;
    const int lane = tid & 31;
    const int wid = tid >> 5;
    const int warpM = wid & 3;
    const int warpN = wid >> 2;
    const int row0 = blockIdx.x * 64;

    {
        const uint32_t* w0 = reinterpret_cast<const uint32_t*>(W0);
        const uint32_t* wi = reinterpret_cast<const uint32_t*>(Wi1);
        const uint32_t* wh = reinterpret_cast<const uint32_t*>(Wh1);
#pragma unroll
        for (int i = 0; i < 16; i++) {
            int idx = tid + 512 * i;
            int r = idx >> 5, c = idx & 31;
            *reinterpret_cast<uint32_t*>(smem + OW0 + r * 144 + c * 4) = w0[idx];
            *reinterpret_cast<uint32_t*>(smem + OWI + r * 144 + c * 4) = wi[idx];
            *reinterpret_cast<uint32_t*>(smem + OWH + r * 144 + c * 4) = wh[idx];
        }
#pragma unroll
        for (int i = 0; i < 18; i++) {
            int idx = tid + 512 * i;
            *reinterpret_cast<uint32_t*>(smem + OH0A + idx * 4) = 0;
        }
        if (tid < 256) reinterpret_cast<float*>(smem + OB1)[tid] = B1[tid];
    }

#pragma unroll
    for (int i = 0; i < 4; i++) {
        int idx = tid + 512 * i;
        int r = idx >> 5, ch = idx & 31;
        cp16(sb + OXG0 + r * 512 + ch * 16,
             XG + ((size_t)(row0 + r) * Tsz + 0) * 256 + ch * 8);
    }
    CP_COMMIT();
    CP_WAIT0();

    const uint32_t aoff = (uint32_t)((warpM * 16 + (lane & 7) + ((lane >> 3) & 1) * 8) * 144
                                     + (lane >> 4) * 16);
    const uint32_t boff = (uint32_t)((warpN * 64 + (lane & 7) + (lane >> 4) * 8) * 144
                                     + ((lane >> 3) & 1) * 16);
    const uint32_t bW0 = sb + OW0 + boff, bWi = sb + OWI + boff, bWh = sb + OWH + boff;

    const int gid = lane >> 2;
    const int tig = lane & 3;
    const int rowA = warpM * 16 + gid;
    const float* b1s = reinterpret_cast<const float*>(smem + OB1);

    const int growA = row0 + rowA;
    const int inp = growA >> 12, bbA = growA & (Bsz - 1);
    __half* featA = FEAT + (size_t)bbA * FCK + (size_t)inp * (Tsz * Hsz);
    __half* featB = FEAT + (size_t)(bbA + 8) * FCK + (size_t)inp * (Tsz * Hsz);

    float c0st[8], c1st[8];
#pragma unroll
    for (int i = 0; i < 8; i++) { c0st[i] = 0.f; c1st[i] = 0.f; }

    __syncthreads();

    for (int m = 0; m <= Tsz; m++) {
        const int pr = (m + 1) & 1;
        const int pw = m & 1;

        if (m + 1 < Tsz) {
            uint32_t xdst = sb + OXG0 + (uint32_t)pr * 32768u;
#pragma unroll
            for (int i = 0; i < 4; i++) {
                int idx = tid + 512 * i;
                int r = idx >> 5, ch = idx & 31;
                cp16(xdst + r * 512 + ch * 16,
                     XG + ((size_t)(row0 + r) * Tsz + m + 1) * 256 + ch * 8);
            }
            CP_COMMIT();
        }

        const uint32_t a0 = sb + OH0A + (uint32_t)pr * 9216u + aoff;
        const uint32_t a1 = sb + OH1A + (uint32_t)pr * 9216u + aoff;
        const uint32_t h0w = sb + OH0A + (uint32_t)pw * 9216u;
        const uint32_t h1w = sb + OH1A + (uint32_t)pw * 9216u;

        if (m < Tsz) {
            float acc0[8][4];
#pragma unroll
            for (int nt = 0; nt < 8; nt++)
#pragma unroll
                for (int e = 0; e < 4; e++) acc0[nt][e] = 0.f;
#pragma unroll
            for (int ks = 0; ks < 4; ks++) {
                uint32_t ah[4];
                LDSM_X4(ah, a0 + ks * 32);
#pragma unroll
                for (int np = 0; np < 4; np++) {
                    uint32_t bv[4];
                    LDSM_X4(bv, bW0 + np * 2304 + ks * 32);
                    mma_f16(acc0[2 * np],     ah, bv);
                    mma_f16(acc0[2 * np + 1], ah, bv + 2);
                }
            }
            const __half* xbuf = reinterpret_cast<const __half*>(
                smem + OXG0 + pw * 32768);
#pragma unroll
            for (int p = 0; p < 4; p++) {
                int colb = warpN * 64 + p * 16 + 2 * tig;
                int j = warpN * 16 + p * 4 + tig;
#pragma unroll
                for (int rh = 0; rh < 2; rh++) {
                    int row = rowA + rh * 8;
                    int e = 2 * rh;
                    float2 xif = __half22float2(*reinterpret_cast<const __half2*>(
                        xbuf + row * 256 + colb));
                    float2 xgo = __half22float2(*reinterpret_cast<const __half2*>(
                        xbuf + row * 256 + colb + 8));
                    float gi = acc0[2 * p][e]     + xif.x;
                    float gf = acc0[2 * p][e + 1] + xif.y;
                    float gg = acc0[2 * p + 1][e]     + xgo.x;
                    float go = acc0[2 * p + 1][e + 1] + xgo.y;
                    float& c = c0st[2 * p + rh];
                    c = sig_fast(gf) * c + sig_fast(gi) * tanh_fast(gg);
                    float h = sig_fast(go) * tanh_fast(c);
                    *reinterpret_cast<unsigned short*>(
                        smem + (h0w - sb) + row * 144 + j * 2)
                        = __half_as_ushort(__float2half_rn(h));
                }
            }
        }

        if (m >= 1) {
            float acc1[8][4];
#pragma unroll
            for (int nt = 0; nt < 8; nt++)
#pragma unroll
                for (int e = 0; e < 4; e++) acc1[nt][e] = 0.f;
#pragma unroll
            for (int ks = 0; ks < 4; ks++) {
                uint32_t ah[4];
                LDSM_X4(ah, a0 + ks * 32);
#pragma unroll
                for (int np = 0; np < 4; np++) {
                    uint32_t bw[4];
                    LDSM_X4(bw, bWi + np * 2304 + ks * 32);
                    mma_f16(acc1[2 * np],     ah, bw);
                    mma_f16(acc1[2 * np + 1], ah, bw + 2);
                }
            }
#pragma unroll
            for (int ks = 0; ks < 4; ks++) {
                uint32_t ah[4];
                LDSM_X4(ah, a1 + ks * 32);
#pragma unroll
                for (int np = 0; np < 4; np++) {
                    uint32_t bv[4];
                    LDSM_X4(bv, bWh + np * 2304 + ks * 32);
                    mma_f16(acc1[2 * np],     ah, bv);
                    mma_f16(acc1[2 * np + 1], ah, bv + 2);
                }
            }
#pragma unroll
            for (int p = 0; p < 4; p++) {
                int colb = warpN * 64 + p * 16 + 2 * tig;
                int j = warpN * 16 + p * 4 + tig;
                float2 bif = *reinterpret_cast<const float2*>(b1s + colb);
                float2 bgo = *reinterpret_cast<const float2*>(b1s + colb + 8);
#pragma unroll
                for (int rh = 0; rh < 2; rh++) {
                    int row = rowA + rh * 8;
                    int e = 2 * rh;
                    float gi = acc1[2 * p][e]     + bif.x;
                    float gf = acc1[2 * p][e + 1] + bif.y;
                    float gg = acc1[2 * p + 1][e]     + bgo.x;
                    float go = acc1[2 * p + 1][e + 1] + bgo.y;
                    float& c = c1st[2 * p + rh];
                    c = sig_fast(gf) * c + sig_fast(gi) * tanh_fast(gg);
                    float h = sig_fast(go) * tanh_fast(c);
                    *reinterpret_cast<unsigned short*>(
                        smem + (h1w - sb) + row * 144 + j * 2)
                        = __half_as_ushort(__float2half_rn(h));
                    __half* fp = rh ? featB : featA;
                    fp[(size_t)(m - 1) * Hsz + j] = __float2half_rn(fmaxf(h, 0.f));
                }
            }
        }

        CP_WAIT0();
        __syncthreads();
    }
}

// ---------------- FC1 split-K reduction (+bias, +relu) ----------------
__global__ void __launch_bounds__(256) fc1_reduce(
    const float* __restrict__ part, const float* __restrict__ bias,
    float* __restrict__ outp)
{
    const size_t S = (size_t)Bsz * 128;
    size_t i = (size_t)blockIdx.x * 256 + threadIdx.x;
    int n = (int)(i & 127);
    float s = bias[n];
#pragma unroll
    for (int z = 0; z < FSPLIT; z++) s += part[i + z * S];
    outp[i] = fmaxf(s, 0.f);
}

// ---------------- FC2 + partial sum-of-squares ----------------
__global__ void __launch_bounds__(256) fc2_norm(
    const float* __restrict__ fc1, const float* __restrict__ w,
    const float* __restrict__ bias, float* __restrict__ out,
    float* __restrict__ partial)
{
    __shared__ float sw[15 * 132];
    __shared__ float red[256];
    const int tid = threadIdx.x;
    for (int i = tid; i < 15 * 128; i += 256) {
        int n = i >> 7, k = i & 127;
        sw[n * 132 + k] = w[i];
    }
    __syncthreads();

    int idx = blockIdx.x * 256 + tid;
    int b = idx / 15, n = idx - b * 15;
    const float4* fr = reinterpret_cast<const float4*>(fc1 + (size_t)b * 128);
    const float4* wn = reinterpret_cast<const float4*>(sw + n * 132);
    float acc = bias[n];
#pragma unroll
    for (int k = 0; k < 32; k++) {
        float4 f4 = fr[k];
        float4 w4 = wn[k];
        acc = fmaf(f4.x, w4.x, acc);
        acc = fmaf(f4.y, w4.y, acc);
        acc = fmaf(f4.z, w4.z, acc);
        acc = fmaf(f4.w, w4.w, acc);
    }
    out[idx] = acc;
    red[tid] = acc * acc;
    __syncthreads();
#pragma unroll
    for (int s = 128; s > 0; s >>= 1) {
        if (tid < s) red[tid] += red[tid + s];
        __syncthreads();
    }
    if (tid == 0) partial[blockIdx.x] = red[0];
}

__global__ void reduce_norm(const float* __restrict__ partial, float* __restrict__ inv)
{
    __shared__ float red[256];
    float s = 0.f;
    for (int i = threadIdx.x; i < 240; i += 256) s += partial[i];
    red[threadIdx.x] = s;
    __syncthreads();
#pragma unroll
    for (int st = 128; st > 0; st >>= 1) {
        if (threadIdx.x < st) red[threadIdx.x] += red[threadIdx.x + st];
        __syncthreads();
    }
    if (threadIdx.x == 0) inv[0] = 1.0f / sqrtf(red[0]);
}

__global__ void scale_out(float* __restrict__ out, const float* __restrict__ inv)
{
    int i = blockIdx.x * 256 + threadIdx.x;
    out[i] *= inv[0];
}

// ---------------- launch ----------------
extern "C" void kernel_launch(void* const* d_in, const int* in_sizes, int n_in,
                              void* d_out, int out_size)
{
    const float* x1      = (const float*)d_in[0];
    const float* x2      = (const float*)d_in[1];
    const float* W_ih_l0 = (const float*)d_in[2];
    const float* W_hh_l0 = (const float*)d_in[3];
    const float* b_ih_l0 = (const float*)d_in[4];
    const float* b_hh_l0 = (const float*)d_in[5];
    const float* W_ih_l1 = (const float*)d_in[6];
    const float* W_hh_l1 = (const float*)d_in[7];
    const float* b_ih_l1 = (const float*)d_in[8];
    const float* b_hh_l1 = (const float*)d_in[9];
    const float* fc1_w   = (const float*)d_in[10];
    const float* fc1_b   = (const float*)d_in[11];
    const float* fc2_w   = (const float*)d_in[12];
    const float* fc2_b   = (const float*)d_in[13];
    float* out = (float*)d_out;

    float *FC1P, *FC1R, *PART, *INV, *B0, *B1;
    __half *XG, *FEAT, *W0, *WR0, *WI1, *WH1, *FW;
    cudaGetSymbolAddress((void**)&XG,   g_XG);
    cudaGetSymbolAddress((void**)&FEAT, g_FEAT);
    cudaGetSymbolAddress((void**)&FC1P, g_FC1P);
    cudaGetSymbolAddress((void**)&FC1R, g_FC1R);
    cudaGetSymbolAddress((void**)&PART, g_PART);
    cudaGetSymbolAddress((void**)&INV,  g_INV);
    cudaGetSymbolAddress((void**)&B0,   g_B0);
    cudaGetSymbolAddress((void**)&B1,   g_B1);
    cudaGetSymbolAddress((void**)&W0,   g_W0);
    cudaGetSymbolAddress((void**)&WR0,  g_WR0);
    cudaGetSymbolAddress((void**)&WI1,  g_WI1);
    cudaGetSymbolAddress((void**)&WH1,  g_WH1);
    cudaGetSymbolAddress((void**)&FW,   g_FW);

    cudaFuncSetAttribute(lstm_fused_tc, cudaFuncAttributeMaxDynamicSharedMemorySize,
                         FUSED_SMEM);
    cudaFuncSetAttribute((const void*)gemm_f16<0, 1, __half>,
                         cudaFuncAttributeMaxDynamicSharedMemorySize, 65536);
    cudaFuncSetAttribute((const void*)gemm_f16<1, 0, float>,
                         cudaFuncAttributeMaxDynamicSharedMemorySize, 49152);

    // all weight/bias conversions in ONE launch
    convert_all<<<(SEG6 + 255) / 256, 256>>>(
        W_ih_l0, W_hh_l0, W_ih_l1, W_hh_l1, fc1_w,
        b_ih_l0, b_hh_l0, b_ih_l1, b_hh_l1,
        W0, WR0, WI1, WH1, FW, B0, B1);

    // layer-0 input projection (fp32 A, cp.async 4-stage)
    gemm_f16<0, 1, __half><<<dim3(2, M2 / 128, 1), 256, 65536>>>(
        x1, x2, BT, Dsz, K0P / 16, W0, K0P, B0, XG, 256, 0);

    // fused 2-layer recurrence
    lstm_fused_tc<<<128, 512, FUSED_SMEM>>>(XG, WR0, WI1, WH1, B1, FEAT);

    // FC1: fp16 split-K x16 (cp.async 4-stage), then reduce(+bias,+relu)
    gemm_f16<1, 0, float><<<dim3(Bsz / 128, 1, FSPLIT), 256, 49152>>>(
        FEAT, FEAT, 1 << 30, FCK, FSTEPS, FW, FCK, nullptr,
        FC1P, 128, (size_t)Bsz * 128);
    fc1_reduce<<<(Bsz * 128) / 256, 256>>>(FC1P, fc1_b, FC1R);

    // FC2 + deterministic norm + scale
    fc2_norm<<<240, 256>>>(FC1R, fc2_w, fc2_b, out, PART);
    reduce_norm<<<1, 256>>>(PART, INV);
    scale_out<<<240, 256>>>(out, INV);
}